// round 4
// baseline (speedup 1.0000x reference)
#include <cuda_runtime.h>
#include <math.h>

#define S_    2048
#define HID_  2048
#define H_    16
#define D_    256
#define R_    64
#define NOPE_ 192
#define QL_   1024
#define OR_   512
#define G_    4
#define EPS_  1e-6f
#define SCALE_ 0.0625f   // 256^-0.5

// ---------------- scratch (static device arrays; no allocs allowed) -------
__device__ float g_qa [S_*QL_];       // 8 MB
__device__ float g_q  [S_*H_*D_];     // 32 MB
__device__ float g_kv [S_*D_];        // 2 MB
__device__ float g_o  [S_*H_*D_];     // 32 MB
__device__ float g_or [S_*G_*OR_];    // 16 MB
__device__ float g_cos[S_*(R_/2)];
__device__ float g_sin[S_*(R_/2)];

// ---------------- cos/sin precompute --------------------------------------
__global__ void k_cossin(const float* __restrict__ f,
                         float* __restrict__ c, float* __restrict__ s) {
    int i = blockIdx.x * 256 + threadIdx.x;
    if (i < S_ * (R_/2)) { c[i] = cosf(f[i]); s[i] = sinf(f[i]); }
}

// ---------------- generic tiled SGEMM: C[M,N] = A[M,K] @ B[N,K]^T ---------
// 128x128 block, 8-deep K tile, 256 threads, 8x8 per thread.
// Requires M,N multiples of 128 and K multiple of 8 (true for all calls).
__global__ void k_sgemm(const float* __restrict__ A, const float* __restrict__ B,
                        float* __restrict__ C, int M, int N, int K,
                        int lda, int ldb, int ldc) {
    __shared__ float As[8][128];
    __shared__ float Bs[8][128];
    int bm = blockIdx.y * 128, bn = blockIdx.x * 128;
    int t = threadIdx.x;
    int tx = t & 15, ty = t >> 4;
    int lrow = t >> 1;
    int lcol = (t & 1) << 2;
    const float* Ag = A + (size_t)(bm + lrow) * lda + lcol;
    const float* Bg = B + (size_t)(bn + lrow) * ldb + lcol;
    float acc[8][8];
#pragma unroll
    for (int i = 0; i < 8; i++)
#pragma unroll
        for (int j = 0; j < 8; j++) acc[i][j] = 0.f;

    for (int k0 = 0; k0 < K; k0 += 8) {
        float4 av = *(const float4*)(Ag + k0);
        float4 bv = *(const float4*)(Bg + k0);
        As[lcol+0][lrow] = av.x; As[lcol+1][lrow] = av.y;
        As[lcol+2][lrow] = av.z; As[lcol+3][lrow] = av.w;
        Bs[lcol+0][lrow] = bv.x; Bs[lcol+1][lrow] = bv.y;
        Bs[lcol+2][lrow] = bv.z; Bs[lcol+3][lrow] = bv.w;
        __syncthreads();
#pragma unroll
        for (int k = 0; k < 8; ++k) {
            float a[8], b[8];
            *(float4*)&a[0] = *(const float4*)&As[k][ty*8];
            *(float4*)&a[4] = *(const float4*)&As[k][ty*8+4];
            *(float4*)&b[0] = *(const float4*)&Bs[k][tx*8];
            *(float4*)&b[4] = *(const float4*)&Bs[k][tx*8+4];
#pragma unroll
            for (int i = 0; i < 8; i++)
#pragma unroll
                for (int j = 0; j < 8; j++)
                    acc[i][j] += a[i] * b[j];
        }
        __syncthreads();
    }
#pragma unroll
    for (int i = 0; i < 8; i++) {
        float* Cp = C + (size_t)(bm + ty*8 + i) * ldc + bn + tx*8;
        *(float4*)Cp     = make_float4(acc[i][0], acc[i][1], acc[i][2], acc[i][3]);
        *(float4*)(Cp+4) = make_float4(acc[i][4], acc[i][5], acc[i][6], acc[i][7]);
    }
}

// ---------------- rmsnorm over rows of length N with weight ----------------
__global__ void k_rmsrow(float* __restrict__ x, const float* __restrict__ w, int N) {
    int row = blockIdx.x, t = threadIdx.x;
    float* xp = x + (size_t)row * N;
    float ss = 0.f;
    for (int i = t; i < N; i += 256) { float v = xp[i]; ss += v * v; }
#pragma unroll
    for (int o = 16; o; o >>= 1) ss += __shfl_xor_sync(0xffffffffu, ss, o);
    __shared__ float wr[8];
    __shared__ float rinv;
    if ((t & 31) == 0) wr[t >> 5] = ss;
    __syncthreads();
    if (t == 0) {
        float tot = 0.f;
        for (int i = 0; i < 8; i++) tot += wr[i];
        rinv = rsqrtf(tot / (float)N + EPS_);
    }
    __syncthreads();
    float r = rinv;
    for (int i = t; i < N; i += 256) xp[i] = xp[i] * r * w[i];
}

// ---------------- q per-head norm (no weight) + RoPE on last 64 -----------
__global__ void k_qproc(float* __restrict__ q,
                        const float* __restrict__ cb, const float* __restrict__ sb) {
    int s = blockIdx.x >> 4;
    int h = blockIdx.x & 15;
    int t = threadIdx.x;   // 256
    float* qp = q + ((size_t)s * H_ + h) * D_;
    float v = qp[t];
    float ss = v * v;
#pragma unroll
    for (int o = 16; o; o >>= 1) ss += __shfl_xor_sync(0xffffffffu, ss, o);
    __shared__ float wr[8];
    __shared__ float rinv;
    __shared__ float buf[D_];
    if ((t & 31) == 0) wr[t >> 5] = ss;
    __syncthreads();
    if (t == 0) {
        float tot = 0.f;
        for (int i = 0; i < 8; i++) tot += wr[i];
        rinv = rsqrtf(tot / 256.f + EPS_);
    }
    __syncthreads();
    buf[t] = v * rinv;
    __syncthreads();
    if (t < 32) {
        float c = cb[s*32 + t], sn = sb[s*32 + t];
        float x1 = buf[NOPE_ + 2*t], x2 = buf[NOPE_ + 2*t + 1];
        buf[NOPE_ + 2*t]     = x1 * c - x2 * sn;
        buf[NOPE_ + 2*t + 1] = x1 * sn + x2 * c;
    }
    __syncthreads();
    qp[t] = buf[t];
}

// ---------------- kv rmsnorm (with weight) + RoPE on last 64 --------------
__global__ void k_kvproc(float* __restrict__ kv, const float* __restrict__ w,
                         const float* __restrict__ cb, const float* __restrict__ sb) {
    int s = blockIdx.x, t = threadIdx.x;   // 256
    float* p = kv + (size_t)s * D_;
    float v = p[t];
    float ss = v * v;
#pragma unroll
    for (int o = 16; o; o >>= 1) ss += __shfl_xor_sync(0xffffffffu, ss, o);
    __shared__ float wr[8];
    __shared__ float rinv;
    __shared__ float buf[D_];
    if ((t & 31) == 0) wr[t >> 5] = ss;
    __syncthreads();
    if (t == 0) {
        float tot = 0.f;
        for (int i = 0; i < 8; i++) tot += wr[i];
        rinv = rsqrtf(tot / 256.f + EPS_);
    }
    __syncthreads();
    buf[t] = v * rinv * w[t];
    __syncthreads();
    if (t < 32) {
        float c = cb[s*32 + t], sn = sb[s*32 + t];
        float x1 = buf[NOPE_ + 2*t], x2 = buf[NOPE_ + 2*t + 1];
        buf[NOPE_ + 2*t]     = x1 * c - x2 * sn;
        buf[NOPE_ + 2*t + 1] = x1 * sn + x2 * c;
    }
    __syncthreads();
    p[t] = buf[t];
}

// ---------------- flash attention (causal, with sink) ----------------------
// grid: (S/64, H), 256 threads. smem: q 64x256, k 64x256, scores 64x64.
__global__ void k_attn(const float* __restrict__ q, const float* __restrict__ kv,
                       const float* __restrict__ sink, float* __restrict__ o) {
    extern __shared__ float sm[];
    float* q_s = sm;
    float* k_s = sm + 64*256;
    float* s_s = sm + 2*64*256;
    int qb = blockIdx.x, h = blockIdx.y;
    int t = threadIdx.x;
    int tx = t & 15, ty = t >> 4;

    // load q tile
    for (int idx = t; idx < 64*64; idx += 256) {
        int r = idx >> 6, c = (idx & 63) << 2;
        *(float4*)&q_s[r*256 + c] =
            *(const float4*)&q[((size_t)(qb*64 + r) * H_ + h) * D_ + c];
    }

    int row  = t >> 2;
    int dblk = (t & 3) << 6;
    float acc[64];
#pragma unroll
    for (int i = 0; i < 64; i++) acc[i] = 0.f;
    float m = -1e30f, l = 0.f;

    for (int kt = 0; kt <= qb; ++kt) {
        __syncthreads();   // prior pv reads of k_s/s_s done
        for (int idx = t; idx < 64*64; idx += 256) {
            int r = idx >> 6, c = (idx & 63) << 2;
            *(float4*)&k_s[r*256 + c] =
                *(const float4*)&kv[(size_t)(kt*64 + r) * D_ + c];
        }
        __syncthreads();

        // scores: each thread 4x4 of 64x64 tile
        float sc[4][4];
#pragma unroll
        for (int i = 0; i < 4; i++)
#pragma unroll
            for (int j = 0; j < 4; j++) sc[i][j] = 0.f;
        for (int k = 0; k < 256; k += 4) {
            float4 qv[4], kp[4];
#pragma unroll
            for (int i = 0; i < 4; i++) qv[i] = *(const float4*)&q_s[(ty*4+i)*256 + k];
#pragma unroll
            for (int j = 0; j < 4; j++) kp[j] = *(const float4*)&k_s[(tx*4+j)*256 + k];
#pragma unroll
            for (int i = 0; i < 4; i++)
#pragma unroll
                for (int j = 0; j < 4; j++)
                    sc[i][j] += qv[i].x*kp[j].x + qv[i].y*kp[j].y
                              + qv[i].z*kp[j].z + qv[i].w*kp[j].w;
        }
        bool diag = (kt == qb);
#pragma unroll
        for (int i = 0; i < 4; i++)
#pragma unroll
            for (int j = 0; j < 4; j++) {
                int gi = ty*4 + i, gj = tx*4 + j;
                float v = sc[i][j] * SCALE_;
                if (diag && gj > gi) v = -1e30f;
                s_s[gi*64 + gj] = v;
            }
        __syncthreads();

        // online softmax per row + PV accumulate (4 threads per row, 64 dims each)
        float tmax = -1e30f;
#pragma unroll
        for (int j = 0; j < 64; j++) tmax = fmaxf(tmax, s_s[row*64 + j]);
        float newm = fmaxf(m, tmax);
        float cscale = __expf(m - newm);
        l *= cscale;
#pragma unroll
        for (int i = 0; i < 64; i++) acc[i] *= cscale;
        float psum = 0.f;
        for (int j = 0; j < 64; j++) {
            float p = __expf(s_s[row*64 + j] - newm);
            psum += p;
            const float4* kp4 = (const float4*)&k_s[j*256 + dblk];
#pragma unroll
            for (int d4 = 0; d4 < 16; ++d4) {
                float4 kx = kp4[d4];
                acc[d4*4+0] += p * kx.x;
                acc[d4*4+1] += p * kx.y;
                acc[d4*4+2] += p * kx.z;
                acc[d4*4+3] += p * kx.w;
            }
        }
        l += psum;
        m = newm;
    }

    // fold attention sink into denominator
    float sk = sink[h];
    float mf = fmaxf(m, sk);
    float cf = __expf(m - mf);
    l = l * cf + __expf(sk - mf);
    float sc_out = cf / l;

    float* op = &o[((size_t)(qb*64 + row) * H_ + h) * D_ + dblk];
#pragma unroll
    for (int d4 = 0; d4 < 16; ++d4) {
        ((float4*)op)[d4] = make_float4(acc[d4*4+0]*sc_out, acc[d4*4+1]*sc_out,
                                        acc[d4*4+2]*sc_out, acc[d4*4+3]*sc_out);
    }
}

// ---------------- conj RoPE on o's last 64 dims ----------------------------
__global__ void k_orope(float* __restrict__ o,
                        const float* __restrict__ cb, const float* __restrict__ sb) {
    int idx = blockIdx.x * 256 + threadIdx.x;   // S*H*32
    if (idx >= S_ * H_ * 32) return;
    int i = idx & 31;
    int h = (idx >> 5) & 15;
    int s = idx >> 9;
    float c = cb[s*32 + i], sn = sb[s*32 + i];
    float* p = &o[((size_t)s * H_ + h) * D_ + NOPE_ + 2*i];
    float x1 = p[0], x2 = p[1];
    p[0] = x1 * c + x2 * sn;    // conj rotation
    p[1] = -x1 * sn + x2 * c;
}

// ---------------- launch ----------------------------------------------------
extern "C" void kernel_launch(void* const* d_in, const int* in_sizes, int n_in,
                              void* d_out, int out_size) {
    const float* x     = (const float*)d_in[0];
    const float* freqs = (const float*)d_in[1];
    const float* wq_a  = (const float*)d_in[2];
    const float* qnw   = (const float*)d_in[3];
    const float* wq_b  = (const float*)d_in[4];
    const float* wkv   = (const float*)d_in[5];
    const float* kvnw  = (const float*)d_in[6];
    const float* wo_a  = (const float*)d_in[7];
    const float* wo_b  = (const float*)d_in[8];
    const float* sink  = (const float*)d_in[9];
    float* out = (float*)d_out;

    float *qa, *q, *kv, *o, *orr, *cb, *sb;
    cudaGetSymbolAddress((void**)&qa,  g_qa);
    cudaGetSymbolAddress((void**)&q,   g_q);
    cudaGetSymbolAddress((void**)&kv,  g_kv);
    cudaGetSymbolAddress((void**)&o,   g_o);
    cudaGetSymbolAddress((void**)&orr, g_or);
    cudaGetSymbolAddress((void**)&cb,  g_cos);
    cudaGetSymbolAddress((void**)&sb,  g_sin);

    size_t attn_smem = (size_t)(64*256 + 64*256 + 64*64) * sizeof(float); // 144 KB
    cudaFuncSetAttribute(k_attn, cudaFuncAttributeMaxDynamicSharedMemorySize,
                         (int)attn_smem);

    // cos/sin
    k_cossin<<<(S_*32 + 255)/256, 256>>>(freqs, cb, sb);
    // q_a = x @ wq_a^T  (2048x1024x2048)
    k_sgemm<<<dim3(QL_/128, S_/128), 256>>>(x, wq_a, qa, S_, QL_, HID_, HID_, HID_, QL_);
    // rmsnorm(q_a) with q_norm_w
    k_rmsrow<<<S_, 256>>>(qa, qnw, QL_);
    // q = q_a @ wq_b^T  (2048x4096x1024)
    k_sgemm<<<dim3(H_*D_/128, S_/128), 256>>>(qa, wq_b, q, S_, H_*D_, QL_, QL_, QL_, H_*D_);
    // kv = x @ wkv^T  (2048x256x2048)
    k_sgemm<<<dim3(D_/128, S_/128), 256>>>(x, wkv, kv, S_, D_, HID_, HID_, HID_, D_);
    // kv rms + rope
    k_kvproc<<<S_, 256>>>(kv, kvnw, cb, sb);
    // q per-head norm + rope
    k_qproc<<<S_*H_, 256>>>(q, cb, sb);
    // attention
    k_attn<<<dim3(S_/64, H_), 256, attn_smem>>>(q, kv, sink, o);
    // conj rope on o
    k_orope<<<(S_*H_*32 + 255)/256, 256>>>(o, cb, sb);
    // grouped o @ wo_a^T  (4 x 2048x512x1024, block-diagonal)
    for (int g = 0; g < G_; ++g)
        k_sgemm<<<dim3(OR_/128, S_/128), 256>>>(o + g*1024,
                                                wo_a + (size_t)g*OR_*1024,
                                                orr + g*OR_,
                                                S_, OR_, 1024, H_*D_, 1024, G_*OR_);
    // out = o_r @ wo_b^T  (2048x2048x2048)
    k_sgemm<<<dim3(HID_/128, S_/128), 256>>>(orr, wo_b, out, S_, HID_, G_*OR_,
                                             G_*OR_, G_*OR_, HID_);
}

// round 5
// speedup vs baseline: 3.3208x; 3.3208x over previous
#include <cuda_runtime.h>
#include <math.h>

#define S_    2048
#define HID_  2048
#define H_    16
#define D_    256
#define R_    64
#define NOPE_ 192
#define QL_   1024
#define OR_   512
#define G_    4
#define EPS_  1e-6f
#define SCALE_ 0.0625f   // 256^-0.5

// ---------------- scratch (static device arrays; no allocs allowed) -------
__device__ float g_qa [S_*QL_];
__device__ float g_q  [S_*H_*D_];
__device__ float g_kv [S_*D_];
__device__ float g_o  [S_*H_*D_];
__device__ float g_or [S_*G_*OR_];
__device__ float g_cos[S_*(R_/2)];
__device__ float g_sin[S_*(R_/2)];

// ---------------- packed fp32x2 FMA (Blackwell FFMA2) ----------------------
__device__ __forceinline__ float2 ffma2(float2 a, float2 b, float2 c) {
    float2 d;
    asm("fma.rn.f32x2 %0, %1, %2, %3;"
        : "=l"(*(unsigned long long*)&d)
        : "l"(*(unsigned long long*)&a),
          "l"(*(unsigned long long*)&b),
          "l"(*(unsigned long long*)&c));
    return d;
}

// ---------------- cos/sin precompute --------------------------------------
__global__ void k_cossin(const float* __restrict__ f,
                         float* __restrict__ c, float* __restrict__ s) {
    int i = blockIdx.x * 256 + threadIdx.x;
    if (i < S_ * (R_/2)) { c[i] = cosf(f[i]); s[i] = sinf(f[i]); }
}

// ---------------- tiled SGEMM with FFMA2: C[M,N] = A[M,K] @ B[N,K]^T ------
// 128x128 block, 8-deep K tile, 256 threads, 8x8 per thread in split strips.
// blockIdx.z batches independent GEMMs via element strides sA/sB/sC.
__global__ void k_sgemm(const float* __restrict__ A, const float* __restrict__ B,
                        float* __restrict__ C, int M, int N, int K,
                        int lda, int ldb, int ldc,
                        size_t sA, size_t sB, size_t sC) {
    __shared__ float As[8][128];
    __shared__ float Bs[8][128];
    A += sA * blockIdx.z; B += sB * blockIdx.z; C += sC * blockIdx.z;
    int bm = blockIdx.y * 128, bn = blockIdx.x * 128;
    int t = threadIdx.x;
    int tx = t & 15, ty = t >> 4;
    int lrow = t >> 1;
    int lcol = (t & 1) << 2;
    const float* Ag = A + (size_t)(bm + lrow) * lda + lcol;
    const float* Bg = B + (size_t)(bn + lrow) * ldb + lcol;
    float2 acc[8][4];
#pragma unroll
    for (int i = 0; i < 8; i++)
#pragma unroll
        for (int j = 0; j < 4; j++) acc[i][j] = make_float2(0.f, 0.f);

    for (int k0 = 0; k0 < K; k0 += 8) {
        float4 av = *(const float4*)(Ag + k0);
        float4 bv = *(const float4*)(Bg + k0);
        As[lcol+0][lrow] = av.x; As[lcol+1][lrow] = av.y;
        As[lcol+2][lrow] = av.z; As[lcol+3][lrow] = av.w;
        Bs[lcol+0][lrow] = bv.x; Bs[lcol+1][lrow] = bv.y;
        Bs[lcol+2][lrow] = bv.z; Bs[lcol+3][lrow] = bv.w;
        __syncthreads();
#pragma unroll
        for (int k = 0; k < 8; ++k) {
            // split-strip operand fetch: rows {4ty..+3, 64+4ty..+3}, cols same
            float4 a0 = *(const float4*)&As[k][4*ty];
            float4 a1 = *(const float4*)&As[k][64 + 4*ty];
            float4 b0 = *(const float4*)&Bs[k][4*tx];
            float4 b1 = *(const float4*)&Bs[k][64 + 4*tx];
            float a[8] = {a0.x, a0.y, a0.z, a0.w, a1.x, a1.y, a1.z, a1.w};
            float2 bb[4] = {make_float2(b0.x, b0.y), make_float2(b0.z, b0.w),
                            make_float2(b1.x, b1.y), make_float2(b1.z, b1.w)};
#pragma unroll
            for (int i = 0; i < 8; i++) {
                float2 ad = make_float2(a[i], a[i]);
#pragma unroll
                for (int j = 0; j < 4; j++)
                    acc[i][j] = ffma2(ad, bb[j], acc[i][j]);
            }
        }
        __syncthreads();
    }
#pragma unroll
    for (int i = 0; i < 8; i++) {
        int row = (i < 4) ? (4*ty + i) : (64 + 4*ty + i - 4);
        float* Cp = C + (size_t)(bm + row) * ldc + bn;
        *(float4*)(Cp + 4*tx)      = make_float4(acc[i][0].x, acc[i][0].y,
                                                 acc[i][1].x, acc[i][1].y);
        *(float4*)(Cp + 64 + 4*tx) = make_float4(acc[i][2].x, acc[i][2].y,
                                                 acc[i][3].x, acc[i][3].y);
    }
}

// ---------------- rmsnorm over rows of length N with weight ----------------
__global__ void k_rmsrow(float* __restrict__ x, const float* __restrict__ w, int N) {
    int row = blockIdx.x, t = threadIdx.x;
    float* xp = x + (size_t)row * N;
    float ss = 0.f;
    for (int i = t; i < N; i += 256) { float v = xp[i]; ss += v * v; }
#pragma unroll
    for (int o = 16; o; o >>= 1) ss += __shfl_xor_sync(0xffffffffu, ss, o);
    __shared__ float wr[8];
    __shared__ float rinv;
    if ((t & 31) == 0) wr[t >> 5] = ss;
    __syncthreads();
    if (t == 0) {
        float tot = 0.f;
        for (int i = 0; i < 8; i++) tot += wr[i];
        rinv = rsqrtf(tot / (float)N + EPS_);
    }
    __syncthreads();
    float r = rinv;
    for (int i = t; i < N; i += 256) xp[i] = xp[i] * r * w[i];
}

// ---------------- q per-head norm (no weight) + RoPE on last 64 -----------
__global__ void k_qproc(float* __restrict__ q,
                        const float* __restrict__ cb, const float* __restrict__ sb) {
    int s = blockIdx.x >> 4;
    int h = blockIdx.x & 15;
    int t = threadIdx.x;   // 256
    float* qp = q + ((size_t)s * H_ + h) * D_;
    float v = qp[t];
    float ss = v * v;
#pragma unroll
    for (int o = 16; o; o >>= 1) ss += __shfl_xor_sync(0xffffffffu, ss, o);
    __shared__ float wr[8];
    __shared__ float rinv;
    __shared__ float buf[D_];
    if ((t & 31) == 0) wr[t >> 5] = ss;
    __syncthreads();
    if (t == 0) {
        float tot = 0.f;
        for (int i = 0; i < 8; i++) tot += wr[i];
        rinv = rsqrtf(tot / 256.f + EPS_);
    }
    __syncthreads();
    buf[t] = v * rinv;
    __syncthreads();
    if (t < 32) {
        float c = cb[s*32 + t], sn = sb[s*32 + t];
        float x1 = buf[NOPE_ + 2*t], x2 = buf[NOPE_ + 2*t + 1];
        buf[NOPE_ + 2*t]     = x1 * c - x2 * sn;
        buf[NOPE_ + 2*t + 1] = x1 * sn + x2 * c;
    }
    __syncthreads();
    qp[t] = buf[t];
}

// ---------------- kv rmsnorm (with weight) + RoPE on last 64 --------------
__global__ void k_kvproc(float* __restrict__ kv, const float* __restrict__ w,
                         const float* __restrict__ cb, const float* __restrict__ sb) {
    int s = blockIdx.x, t = threadIdx.x;   // 256
    float* p = kv + (size_t)s * D_;
    float v = p[t];
    float ss = v * v;
#pragma unroll
    for (int o = 16; o; o >>= 1) ss += __shfl_xor_sync(0xffffffffu, ss, o);
    __shared__ float wr[8];
    __shared__ float rinv;
    __shared__ float buf[D_];
    if ((t & 31) == 0) wr[t >> 5] = ss;
    __syncthreads();
    if (t == 0) {
        float tot = 0.f;
        for (int i = 0; i < 8; i++) tot += wr[i];
        rinv = rsqrtf(tot / 256.f + EPS_);
    }
    __syncthreads();
    buf[t] = v * rinv * w[t];
    __syncthreads();
    if (t < 32) {
        float c = cb[s*32 + t], sn = sb[s*32 + t];
        float x1 = buf[NOPE_ + 2*t], x2 = buf[NOPE_ + 2*t + 1];
        buf[NOPE_ + 2*t]     = x1 * c - x2 * sn;
        buf[NOPE_ + 2*t + 1] = x1 * sn + x2 * c;
    }
    __syncthreads();
    p[t] = buf[t];
}

// ---------------- flash attention v2 (causal, sink) ------------------------
// 32 q-rows x 64 k-rows per tile, 256 threads, 2 CTAs/SM.
// Score GEMM: thread = 2x4 of 32x64 tile, FFMA2 paired along k (no dup).
// PV GEMM:    thread = 2 rows x 16 cols of 32x256 out, cols strided tx+16cc.
// k_s/q_s XOR-swizzled at float4 granularity for conflict-free lanes.
__global__ void k_attn2(const float* __restrict__ q, const float* __restrict__ kv,
                        const float* __restrict__ sink, float* __restrict__ o) {
    extern __shared__ float4 smx[];
    float4* q_s = smx;              // 32 rows x 64 float4 (32 KB)
    float4* k_s = smx + 2048;       // 64 rows x 64 float4 (64 KB)
    float*  p_s = (float*)(smx + 6144);  // 32 x 64 floats (8 KB)
    float*  c_s = p_s + 2048;       // per-row rescale
    float*  o_s = c_s + 32;         // per-row output scale

    int bid = blockIdx.x;
    int qb = 63 - (bid >> 4);       // longest blocks first
    int h  = bid & 15;
    int t  = threadIdx.x;
    int tx = t & 15, ty = t >> 4;
    int srow = t >> 3;              // softmax row (0..31)
    int scg  = t & 7;               // softmax col group

    // load q tile, swizzle c4 ^ (r & 15)
    for (int idx = t; idx < 32*64; idx += 256) {
        int r = idx >> 6, c4 = idx & 63;
        q_s[r*64 + (c4 ^ (r & 15))] =
            *(const float4*)&q[((size_t)(qb*32 + r) * H_ + h) * D_ + c4*4];
    }

    float2 acc[2][8];
#pragma unroll
    for (int i = 0; i < 2; i++)
#pragma unroll
        for (int j = 0; j < 8; j++) acc[i][j] = make_float2(0.f, 0.f);
    float m = -1e30f, l = 0.f;

    int r0 = 2*ty, r1 = 2*ty + 1;
    int qsw0 = r0 & 15, qsw1 = r1 & 15;

    int nkt = (qb >> 1) + 1;
    for (int kt = 0; kt < nkt; ++kt) {
        __syncthreads();   // prior PV done with k_s / p_s / c_s
        for (int idx = t; idx < 64*64; idx += 256) {
            int r = idx >> 6, c4 = idx & 63;
            k_s[r*64 + (c4 ^ ((r >> 2) & 15))] =
                *(const float4*)&kv[(size_t)(kt*64 + r) * D_ + c4*4];
        }
        __syncthreads();

        // ---- scores: 2 rows x 4 cols, pair along k ----
        float2 sa[2][4];
#pragma unroll
        for (int i = 0; i < 2; i++)
#pragma unroll
            for (int j = 0; j < 4; j++) sa[i][j] = make_float2(0.f, 0.f);
#pragma unroll 4
        for (int k4 = 0; k4 < 64; ++k4) {
            float4 qv0 = q_s[r0*64 + (k4 ^ qsw0)];
            float4 qv1 = q_s[r1*64 + (k4 ^ qsw1)];
            float4 kvv[4];
#pragma unroll
            for (int j = 0; j < 4; j++)
                kvv[j] = k_s[(4*tx + j)*64 + (k4 ^ tx)];
#pragma unroll
            for (int j = 0; j < 4; j++) {
                sa[0][j] = ffma2(make_float2(qv0.x, qv0.y), make_float2(kvv[j].x, kvv[j].y), sa[0][j]);
                sa[0][j] = ffma2(make_float2(qv0.z, qv0.w), make_float2(kvv[j].z, kvv[j].w), sa[0][j]);
                sa[1][j] = ffma2(make_float2(qv1.x, qv1.y), make_float2(kvv[j].x, kvv[j].y), sa[1][j]);
                sa[1][j] = ffma2(make_float2(qv1.z, qv1.w), make_float2(kvv[j].z, kvv[j].w), sa[1][j]);
            }
        }
#pragma unroll
        for (int i = 0; i < 2; i++)
#pragma unroll
            for (int j = 0; j < 4; j++) {
                int qg = qb*32 + 2*ty + i;
                int kg = kt*64 + 4*tx + j;
                float v = (sa[i][j].x + sa[i][j].y) * SCALE_;
                p_s[(2*ty + i)*64 + 4*tx + j] = (kg > qg) ? -1e30f : v;
            }
        __syncthreads();

        // ---- online softmax: 8 threads per row, 8 cols each ----
        float sv[8];
        float tmax = -1e30f;
#pragma unroll
        for (int c = 0; c < 8; ++c) {
            sv[c] = p_s[srow*64 + scg*8 + c];
            tmax = fmaxf(tmax, sv[c]);
        }
        tmax = fmaxf(tmax, __shfl_xor_sync(0xffffffffu, tmax, 1));
        tmax = fmaxf(tmax, __shfl_xor_sync(0xffffffffu, tmax, 2));
        tmax = fmaxf(tmax, __shfl_xor_sync(0xffffffffu, tmax, 4));
        float newm = fmaxf(m, tmax);
        float cs = __expf(m - newm);
        float ps = 0.f;
#pragma unroll
        for (int c = 0; c < 8; ++c) {
            float p = __expf(sv[c] - newm);
            p_s[srow*64 + scg*8 + c] = p;
            ps += p;
        }
        ps += __shfl_xor_sync(0xffffffffu, ps, 1);
        ps += __shfl_xor_sync(0xffffffffu, ps, 2);
        ps += __shfl_xor_sync(0xffffffffu, ps, 4);
        l = l * cs + ps;
        m = newm;
        if (scg == 0) c_s[srow] = cs;
        __syncthreads();

        // ---- rescale + PV: cols strided (tx + 16*cc) for conflict-free lanes
        float cs0 = c_s[r0], cs1 = c_s[r1];
#pragma unroll
        for (int j = 0; j < 8; j++) {
            acc[0][j].x *= cs0; acc[0][j].y *= cs0;
            acc[1][j].x *= cs1; acc[1][j].y *= cs1;
        }
#pragma unroll 2
        for (int kk = 0; kk < 64; ++kk) {
            float p0 = p_s[r0*64 + kk];
            float p1 = p_s[r1*64 + kk];
            float2 pd0 = make_float2(p0, p0);
            float2 pd1 = make_float2(p1, p1);
            int ks = (kk >> 2) & 15;
#pragma unroll
            for (int cc = 0; cc < 4; ++cc) {
                float4 kvv = k_s[kk*64 + ((tx + 16*cc) ^ ks)];
                acc[0][2*cc]   = ffma2(pd0, make_float2(kvv.x, kvv.y), acc[0][2*cc]);
                acc[0][2*cc+1] = ffma2(pd0, make_float2(kvv.z, kvv.w), acc[0][2*cc+1]);
                acc[1][2*cc]   = ffma2(pd1, make_float2(kvv.x, kvv.y), acc[1][2*cc]);
                acc[1][2*cc+1] = ffma2(pd1, make_float2(kvv.z, kvv.w), acc[1][2*cc+1]);
            }
        }
    }

    // ---- fold sink, final scale ----
    if (scg == 0) {
        float sk = sink[h];
        float mf = fmaxf(m, sk);
        float cf = __expf(m - mf);
        float denom = l * cf + __expf(sk - mf);
        o_s[srow] = cf / denom;
    }
    __syncthreads();
    float os0 = o_s[r0], os1 = o_s[r1];
#pragma unroll
    for (int cc = 0; cc < 4; ++cc) {
        int col = 4*(tx + 16*cc);
        float* op0 = &o[((size_t)(qb*32 + r0) * H_ + h) * D_ + col];
        float* op1 = &o[((size_t)(qb*32 + r1) * H_ + h) * D_ + col];
        *(float4*)op0 = make_float4(acc[0][2*cc].x*os0, acc[0][2*cc].y*os0,
                                    acc[0][2*cc+1].x*os0, acc[0][2*cc+1].y*os0);
        *(float4*)op1 = make_float4(acc[1][2*cc].x*os1, acc[1][2*cc].y*os1,
                                    acc[1][2*cc+1].x*os1, acc[1][2*cc+1].y*os1);
    }
}

// ---------------- conj RoPE on o's last 64 dims ----------------------------
__global__ void k_orope(float* __restrict__ o,
                        const float* __restrict__ cb, const float* __restrict__ sb) {
    int idx = blockIdx.x * 256 + threadIdx.x;   // S*H*32
    if (idx >= S_ * H_ * 32) return;
    int i = idx & 31;
    int h = (idx >> 5) & 15;
    int s = idx >> 9;
    float c = cb[s*32 + i], sn = sb[s*32 + i];
    float* p = &o[((size_t)s * H_ + h) * D_ + NOPE_ + 2*i];
    float x1 = p[0], x2 = p[1];
    p[0] = x1 * c + x2 * sn;    // conj rotation
    p[1] = -x1 * sn + x2 * c;
}

// ---------------- launch ----------------------------------------------------
extern "C" void kernel_launch(void* const* d_in, const int* in_sizes, int n_in,
                              void* d_out, int out_size) {
    const float* x     = (const float*)d_in[0];
    const float* freqs = (const float*)d_in[1];
    const float* wq_a  = (const float*)d_in[2];
    const float* qnw   = (const float*)d_in[3];
    const float* wq_b  = (const float*)d_in[4];
    const float* wkv   = (const float*)d_in[5];
    const float* kvnw  = (const float*)d_in[6];
    const float* wo_a  = (const float*)d_in[7];
    const float* wo_b  = (const float*)d_in[8];
    const float* sink  = (const float*)d_in[9];
    float* out = (float*)d_out;

    float *qa, *q, *kv, *o, *orr, *cb, *sb;
    cudaGetSymbolAddress((void**)&qa,  g_qa);
    cudaGetSymbolAddress((void**)&q,   g_q);
    cudaGetSymbolAddress((void**)&kv,  g_kv);
    cudaGetSymbolAddress((void**)&o,   g_o);
    cudaGetSymbolAddress((void**)&orr, g_or);
    cudaGetSymbolAddress((void**)&cb,  g_cos);
    cudaGetSymbolAddress((void**)&sb,  g_sin);

    // attn smem: q 32KB + k 64KB + p 8KB + scales
    size_t attn_smem = 6144 * sizeof(float4) + (2048 + 64) * sizeof(float);
    cudaFuncSetAttribute(k_attn2, cudaFuncAttributeMaxDynamicSharedMemorySize,
                         (int)attn_smem);

    k_cossin<<<(S_*32 + 255)/256, 256>>>(freqs, cb, sb);
    // q_a = x @ wq_a^T
    k_sgemm<<<dim3(QL_/128, S_/128), 256>>>(x, wq_a, qa, S_, QL_, HID_,
                                            HID_, HID_, QL_, 0, 0, 0);
    k_rmsrow<<<S_, 256>>>(qa, qnw, QL_);
    // q = q_a @ wq_b^T
    k_sgemm<<<dim3(H_*D_/128, S_/128), 256>>>(qa, wq_b, q, S_, H_*D_, QL_,
                                              QL_, QL_, H_*D_, 0, 0, 0);
    // kv = x @ wkv^T
    k_sgemm<<<dim3(D_/128, S_/128), 256>>>(x, wkv, kv, S_, D_, HID_,
                                           HID_, HID_, D_, 0, 0, 0);
    k_kvproc<<<S_, 256>>>(kv, kvnw, cb, sb);
    k_qproc<<<S_*H_, 256>>>(q, cb, sb);
    // attention: 64 q-tiles x 16 heads
    k_attn2<<<dim3(64*16), 256, attn_smem>>>(q, kv, sink, o);
    k_orope<<<(S_*H_*32 + 255)/256, 256>>>(o, cb, sb);
    // grouped o @ wo_a^T : all 4 groups batched via blockIdx.z
    k_sgemm<<<dim3(OR_/128, S_/128, G_), 256>>>(o, wo_a, orr, S_, OR_, 1024,
                                                H_*D_, 1024, G_*OR_,
                                                1024, (size_t)OR_*1024, OR_);
    // out = o_r @ wo_b^T
    k_sgemm<<<dim3(HID_/128, S_/128), 256>>>(orr, wo_b, out, S_, HID_, G_*OR_,
                                             G_*OR_, G_*OR_, HID_, 0, 0, 0);
}

// round 11
// speedup vs baseline: 4.8807x; 1.4697x over previous
#include <cuda_runtime.h>
#include <cuda_bf16.h>
#include <math.h>
#include <stdint.h>

#define S_    2048
#define HID_  2048
#define H_    16
#define D_    256
#define R_    64
#define NOPE_ 192
#define QL_   1024
#define OR_   512
#define G_    4
#define EPS_  1e-6f
#define SCALE_ 0.0625f   // 256^-0.5

// ---------------- scratch (static device arrays; no allocs allowed) -------
__device__ float g_qa [S_*QL_];
__device__ float g_q  [S_*H_*D_];
__device__ float g_kv [S_*D_];
__device__ float g_o  [S_*H_*D_];
__device__ float g_or [S_*G_*OR_];
__device__ float g_cos[S_*(R_/2)];
__device__ float g_sin[S_*(R_/2)];
// bf16 3-term split operands (K tripled)
__device__ __nv_bfloat16 g_xs   [S_*3*HID_];          // x split (A)
__device__ __nv_bfloat16 g_wqas [QL_*3*HID_];         // wq_a split (B)
__device__ __nv_bfloat16 g_qas  [S_*3*QL_];           // qa split (A)
__device__ __nv_bfloat16 g_wqbs [H_*D_*3*QL_];        // wq_b split (B)
__device__ __nv_bfloat16 g_wkvs [D_*3*HID_];          // wkv split (B)
__device__ __nv_bfloat16 g_os   [G_*S_*3*1024];       // o grouped split (A)
__device__ __nv_bfloat16 g_woas [G_*OR_*3*1024];      // wo_a split (B)
__device__ __nv_bfloat16 g_ors  [S_*3*(G_*OR_)];      // o_r split (A)
__device__ __nv_bfloat16 g_wobs [HID_*3*(G_*OR_)];    // wo_b split (B)

// ---------------- small PTX helpers ----------------------------------------
__device__ __forceinline__ uint32_t smem_u32(const void* p) {
    uint32_t a;
    asm("{ .reg .u64 t; cvta.to.shared.u64 t, %1; cvt.u32.u64 %0, t; }"
        : "=r"(a) : "l"(p));
    return a;
}
__device__ __forceinline__ void cp_async16(uint32_t saddr, const void* gaddr) {
    asm volatile("cp.async.cg.shared.global [%0], [%1], 16;"
                 :: "r"(saddr), "l"(gaddr));
}
#define CP_COMMIT() asm volatile("cp.async.commit_group;" ::: "memory")
#define CP_WAIT1()  asm volatile("cp.async.wait_group 1;" ::: "memory")
#define CP_WAIT0()  asm volatile("cp.async.wait_group 0;" ::: "memory")

__device__ __forceinline__ void ldsm4(uint32_t& r0, uint32_t& r1,
                                      uint32_t& r2, uint32_t& r3, uint32_t a) {
    asm volatile("ldmatrix.sync.aligned.m8n8.x4.shared.b16 {%0,%1,%2,%3}, [%4];"
                 : "=r"(r0), "=r"(r1), "=r"(r2), "=r"(r3) : "r"(a));
}
__device__ __forceinline__ void mma_bf16(float* d, const uint32_t* a,
                                         const uint32_t* b) {
    asm volatile("mma.sync.aligned.m16n8k16.row.col.f32.bf16.bf16.f32 "
                 "{%0,%1,%2,%3}, {%4,%5,%6,%7}, {%8,%9}, {%0,%1,%2,%3};"
                 : "+f"(d[0]), "+f"(d[1]), "+f"(d[2]), "+f"(d[3])
                 : "r"(a[0]), "r"(a[1]), "r"(a[2]), "r"(a[3]),
                   "r"(b[0]), "r"(b[1]));
}

// ---------------- packed fp32x2 FMA (Blackwell FFMA2) ----------------------
__device__ __forceinline__ float2 ffma2(float2 a, float2 b, float2 c) {
    float2 d;
    asm("fma.rn.f32x2 %0, %1, %2, %3;"
        : "=l"(*(unsigned long long*)&d)
        : "l"(*(unsigned long long*)&a),
          "l"(*(unsigned long long*)&b),
          "l"(*(unsigned long long*)&c));
    return d;
}

// ---------------- cos/sin precompute --------------------------------------
__global__ void k_cossin(const float* __restrict__ f,
                         float* __restrict__ c, float* __restrict__ s) {
    int i = blockIdx.x * 256 + threadIdx.x;
    if (i < S_ * (R_/2)) { c[i] = cosf(f[i]); s[i] = sinf(f[i]); }
}

// ---------------- bf16 3-term split ----------------------------------------
// mode 0 (A operand): out row = [hi(K), lo(K), hi(K)]
// mode 1 (B operand): out row = [hi(K), hi(K), lo(K)]
__global__ void k_split(const float* __restrict__ in, __nv_bfloat16* __restrict__ out,
                        int K, int in_ld, size_t in_goff, size_t out_gstride, int mode) {
    const float* ip = in + in_goff * blockIdx.z;
    __nv_bfloat16* op = out + out_gstride * blockIdx.z;
    int k = blockIdx.x * 256 + threadIdx.x;
    int row = blockIdx.y;
    float v = ip[(size_t)row * in_ld + k];
    __nv_bfloat16 hi = __float2bfloat16(v);
    __nv_bfloat16 lo = __float2bfloat16(v - __bfloat162float(hi));
    size_t ob = (size_t)row * 3 * K;
    if (mode == 0) {
        op[ob + k] = hi; op[ob + K + k] = lo; op[ob + 2*K + k] = hi;
    } else {
        op[ob + k] = hi; op[ob + K + k] = hi; op[ob + 2*K + k] = lo;
    }
}

// ---------------- HMMA bf16 GEMM: C[M,N] = A[M,K3] @ B[N,K3]^T -------------
// 128x128 tile, Kc=64 double-buffered cp.async, 256 threads (8 warps, 4m x 2n).
// Warp tile 32x64 via mma.m16n8k16. SW128-swizzled smem, ldmatrix fragments.
// grid (N/128, M/128, batch)
__global__ void __launch_bounds__(256)
k_hgemm(const __nv_bfloat16* __restrict__ A, const __nv_bfloat16* __restrict__ B,
        float* __restrict__ C, int K3, int ldc,
        size_t sA, size_t sB, size_t sC) {
    extern __shared__ char smem_raw[];
    uint32_t sb_raw = smem_u32(smem_raw);
    uint32_t sb = (sb_raw + 127) & ~127u;

    A += sA * blockIdx.z; B += sB * blockIdx.z; C += sC * blockIdx.z;
    const int bn = blockIdx.x * 128, bm = blockIdx.y * 128;
    int t = threadIdx.x, lane = t & 31, wid = t >> 5;
    int wm = wid & 3, wn = wid >> 2;

    // loader mapping: thread t covers row r = t>>1, 64B half hh = t&1, 4x16B
    int r = t >> 1, hh = t & 1;
    const char* Ag = (const char*)(A + (size_t)(bm + r) * K3) + hh * 64;
    const char* Bg = (const char*)(B + (size_t)(bn + r) * K3) + hh * 64;
    uint32_t soff[4];
#pragma unroll
    for (int i = 0; i < 4; i++) {
        uint32_t off = (uint32_t)(r * 128 + hh * 64 + i * 16);
        soff[i] = off ^ ((off >> 3) & 0x70);
    }

    // buf layout: buf b: A @ sb + b*32768, B @ +16384
#define LOADC(c, buf) do {                                                    \
        const char* ag = Ag + (size_t)(c) * 128;                              \
        const char* bg = Bg + (size_t)(c) * 128;                              \
        uint32_t ab = sb + (buf) * 32768;                                     \
        uint32_t bb = ab + 16384;                                             \
        cp_async16(ab + soff[0], ag);       cp_async16(ab + soff[1], ag + 16);\
        cp_async16(ab + soff[2], ag + 32);  cp_async16(ab + soff[3], ag + 48);\
        cp_async16(bb + soff[0], bg);       cp_async16(bb + soff[1], bg + 16);\
        cp_async16(bb + soff[2], bg + 32);  cp_async16(bb + soff[3], bg + 48);\
    } while (0)

    float d[2][8][4];
#pragma unroll
    for (int i = 0; i < 2; i++)
#pragma unroll
        for (int j = 0; j < 8; j++)
#pragma unroll
            for (int k = 0; k < 4; k++) d[i][j][k] = 0.f;

    const int nch = K3 >> 6;
    LOADC(0, 0);
    CP_COMMIT();

    // precompute fragment smem addresses (per-buffer bases added in loop)
    // A: lane -> row wm*32 + i*16 + (lane&15), kbyte (lane>>4)*16
    uint32_t a_off[2];
#pragma unroll
    for (int i = 0; i < 2; i++) {
        uint32_t off = (uint32_t)((wm*32 + i*16 + (lane & 15)) * 128 + (lane >> 4) * 16);
        a_off[i] = off ^ ((off >> 3) & 0x70);
    }
    // B: lane -> row wn*64 + jp*16 + ((lane>>4)<<3) + (lane&7), kbyte ((lane>>3)&1)*16
    uint32_t b_off[4];
#pragma unroll
    for (int jp = 0; jp < 4; jp++) {
        uint32_t off = (uint32_t)((wn*64 + jp*16 + ((lane >> 4) << 3) + (lane & 7)) * 128
                                  + ((lane >> 3) & 1) * 16);
        b_off[jp] = off ^ ((off >> 3) & 0x70);
    }

    for (int c = 0; c < nch; ++c) {
        int buf = c & 1;
        if (c + 1 < nch) { LOADC(c + 1, buf ^ 1); CP_COMMIT(); CP_WAIT1(); }
        else             { CP_WAIT0(); }
        __syncthreads();

        uint32_t abase = sb + buf * 32768;
        uint32_t bbase = abase + 16384;
#pragma unroll
        for (int ks = 0; ks < 4; ++ks) {
            uint32_t kb = ks * 32;       // swizzle preserves bits 5+; kb multiple of 32
            uint32_t a_f[2][4];
#pragma unroll
            for (int i = 0; i < 2; i++)
                ldsm4(a_f[i][0], a_f[i][1], a_f[i][2], a_f[i][3],
                      abase + (a_off[i] ^ kb));
            uint32_t b_f[8][2];
#pragma unroll
            for (int jp = 0; jp < 4; jp++) {
                uint32_t r0, r1, r2, r3;
                ldsm4(r0, r1, r2, r3, bbase + (b_off[jp] ^ kb));
                b_f[jp*2][0] = r0;   b_f[jp*2][1] = r1;
                b_f[jp*2+1][0] = r2; b_f[jp*2+1][1] = r3;
            }
#pragma unroll
            for (int i = 0; i < 2; i++)
#pragma unroll
                for (int j = 0; j < 8; j++)
                    mma_bf16(d[i][j], a_f[i], b_f[j]);
        }
        __syncthreads();
    }

    // epilogue: direct stores, float2 per fragment row
#pragma unroll
    for (int i = 0; i < 2; i++) {
        int row0 = bm + wm*32 + i*16 + (lane >> 2);
#pragma unroll
        for (int j = 0; j < 8; j++) {
            int col = bn + wn*64 + j*8 + (lane & 3)*2;
            *(float2*)&C[(size_t)row0 * ldc + col] = make_float2(d[i][j][0], d[i][j][1]);
            *(float2*)&C[(size_t)(row0 + 8) * ldc + col] = make_float2(d[i][j][2], d[i][j][3]);
        }
    }
#undef LOADC
}

// ---------------- rmsnorm over rows of length N with weight ----------------
__global__ void k_rmsrow(float* __restrict__ x, const float* __restrict__ w, int N) {
    int row = blockIdx.x, t = threadIdx.x;
    float* xp = x + (size_t)row * N;
    float ss = 0.f;
    for (int i = t; i < N; i += 256) { float v = xp[i]; ss += v * v; }
#pragma unroll
    for (int o = 16; o; o >>= 1) ss += __shfl_xor_sync(0xffffffffu, ss, o);
    __shared__ float wr[8];
    __shared__ float rinv;
    if ((t & 31) == 0) wr[t >> 5] = ss;
    __syncthreads();
    if (t == 0) {
        float tot = 0.f;
        for (int i = 0; i < 8; i++) tot += wr[i];
        rinv = rsqrtf(tot / (float)N + EPS_);
    }
    __syncthreads();
    float r = rinv;
    for (int i = t; i < N; i += 256) xp[i] = xp[i] * r * w[i];
}

// ---------------- q per-head norm (no weight) + RoPE on last 64 -----------
__global__ void k_qproc(float* __restrict__ q,
                        const float* __restrict__ cb, const float* __restrict__ sb) {
    int s = blockIdx.x >> 4;
    int h = blockIdx.x & 15;
    int t = threadIdx.x;   // 256
    float* qp = q + ((size_t)s * H_ + h) * D_;
    float v = qp[t];
    float ss = v * v;
#pragma unroll
    for (int o = 16; o; o >>= 1) ss += __shfl_xor_sync(0xffffffffu, ss, o);
    __shared__ float wr[8];
    __shared__ float rinv;
    __shared__ float buf[D_];
    if ((t & 31) == 0) wr[t >> 5] = ss;
    __syncthreads();
    if (t == 0) {
        float tot = 0.f;
        for (int i = 0; i < 8; i++) tot += wr[i];
        rinv = rsqrtf(tot / 256.f + EPS_);
    }
    __syncthreads();
    buf[t] = v * rinv;
    __syncthreads();
    if (t < 32) {
        float c = cb[s*32 + t], sn = sb[s*32 + t];
        float x1 = buf[NOPE_ + 2*t], x2 = buf[NOPE_ + 2*t + 1];
        buf[NOPE_ + 2*t]     = x1 * c - x2 * sn;
        buf[NOPE_ + 2*t + 1] = x1 * sn + x2 * c;
    }
    __syncthreads();
    qp[t] = buf[t];
}

// ---------------- kv rmsnorm (with weight) + RoPE on last 64 --------------
__global__ void k_kvproc(float* __restrict__ kv, const float* __restrict__ w,
                         const float* __restrict__ cb, const float* __restrict__ sb) {
    int s = blockIdx.x, t = threadIdx.x;   // 256
    float* p = kv + (size_t)s * D_;
    float v = p[t];
    float ss = v * v;
#pragma unroll
    for (int o = 16; o; o >>= 1) ss += __shfl_xor_sync(0xffffffffu, ss, o);
    __shared__ float wr[8];
    __shared__ float rinv;
    __shared__ float buf[D_];
    if ((t & 31) == 0) wr[t >> 5] = ss;
    __syncthreads();
    if (t == 0) {
        float tot = 0.f;
        for (int i = 0; i < 8; i++) tot += wr[i];
        rinv = rsqrtf(tot / 256.f + EPS_);
    }
    __syncthreads();
    buf[t] = v * rinv * w[t];
    __syncthreads();
    if (t < 32) {
        float c = cb[s*32 + t], sn = sb[s*32 + t];
        float x1 = buf[NOPE_ + 2*t], x2 = buf[NOPE_ + 2*t + 1];
        buf[NOPE_ + 2*t]     = x1 * c - x2 * sn;
        buf[NOPE_ + 2*t + 1] = x1 * sn + x2 * c;
    }
    __syncthreads();
    p[t] = buf[t];
}

// ---------------- flash attention v2 (causal, sink) ------------------------
__global__ void k_attn2(const float* __restrict__ q, const float* __restrict__ kv,
                        const float* __restrict__ sink, float* __restrict__ o) {
    extern __shared__ float4 smx[];
    float4* q_s = smx;              // 32 rows x 64 float4 (32 KB)
    float4* k_s = smx + 2048;       // 64 rows x 64 float4 (64 KB)
    float*  p_s = (float*)(smx + 6144);  // 32 x 64 floats (8 KB)
    float*  c_s = p_s + 2048;       // per-row rescale
    float*  o_s = c_s + 32;         // per-row output scale

    int bid = blockIdx.x;
    int qb = 63 - (bid >> 4);       // longest blocks first
    int h  = bid & 15;
    int t  = threadIdx.x;
    int tx = t & 15, ty = t >> 4;
    int srow = t >> 3;              // softmax row (0..31)
    int scg  = t & 7;               // softmax col group

    for (int idx = t; idx < 32*64; idx += 256) {
        int r = idx >> 6, c4 = idx & 63;
        q_s[r*64 + (c4 ^ (r & 15))] =
            *(const float4*)&q[((size_t)(qb*32 + r) * H_ + h) * D_ + c4*4];
    }

    float2 acc[2][8];
#pragma unroll
    for (int i = 0; i < 2; i++)
#pragma unroll
        for (int j = 0; j < 8; j++) acc[i][j] = make_float2(0.f, 0.f);
    float m = -1e30f, l = 0.f;

    int r0 = 2*ty, r1 = 2*ty + 1;
    int qsw0 = r0 & 15, qsw1 = r1 & 15;

    int nkt = (qb >> 1) + 1;
    for (int kt = 0; kt < nkt; ++kt) {
        __syncthreads();
        for (int idx = t; idx < 64*64; idx += 256) {
            int r = idx >> 6, c4 = idx & 63;
            k_s[r*64 + (c4 ^ ((r >> 2) & 15))] =
                *(const float4*)&kv[(size_t)(kt*64 + r) * D_ + c4*4];
        }
        __syncthreads();

        float2 sa[2][4];
#pragma unroll
        for (int i = 0; i < 2; i++)
#pragma unroll
            for (int j = 0; j < 4; j++) sa[i][j] = make_float2(0.f, 0.f);
#pragma unroll 4
        for (int k4 = 0; k4 < 64; ++k4) {
            float4 qv0 = q_s[r0*64 + (k4 ^ qsw0)];
            float4 qv1 = q_s[r1*64 + (k4 ^ qsw1)];
            float4 kvv[4];
#pragma unroll
            for (int j = 0; j < 4; j++)
                kvv[j] = k_s[(4*tx + j)*64 + (k4 ^ tx)];
#pragma unroll
            for (int j = 0; j < 4; j++) {
                sa[0][j] = ffma2(make_float2(qv0.x, qv0.y), make_float2(kvv[j].x, kvv[j].y), sa[0][j]);
                sa[0][j] = ffma2(make_float2(qv0.z, qv0.w), make_float2(kvv[j].z, kvv[j].w), sa[0][j]);
                sa[1][j] = ffma2(make_float2(qv1.x, qv1.y), make_float2(kvv[j].x, kvv[j].y), sa[1][j]);
                sa[1][j] = ffma2(make_float2(qv1.z, qv1.w), make_float2(kvv[j].z, kvv[j].w), sa[1][j]);
            }
        }
#pragma unroll
        for (int i = 0; i < 2; i++)
#pragma unroll
            for (int j = 0; j < 4; j++) {
                int qg = qb*32 + 2*ty + i;
                int kg = kt*64 + 4*tx + j;
                float v = (sa[i][j].x + sa[i][j].y) * SCALE_;
                p_s[(2*ty + i)*64 + 4*tx + j] = (kg > qg) ? -1e30f : v;
            }
        __syncthreads();

        float sv[8];
        float tmax = -1e30f;
#pragma unroll
        for (int c = 0; c < 8; ++c) {
            sv[c] = p_s[srow*64 + scg*8 + c];
            tmax = fmaxf(tmax, sv[c]);
        }
        tmax = fmaxf(tmax, __shfl_xor_sync(0xffffffffu, tmax, 1));
        tmax = fmaxf(tmax, __shfl_xor_sync(0xffffffffu, tmax, 2));
        tmax = fmaxf(tmax, __shfl_xor_sync(0xffffffffu, tmax, 4));
        float newm = fmaxf(m, tmax);
        float cs = __expf(m - newm);
        float ps = 0.f;
#pragma unroll
        for (int c = 0; c < 8; ++c) {
            float p = __expf(sv[c] - newm);
            p_s[srow*64 + scg*8 + c] = p;
            ps += p;
        }
        ps += __shfl_xor_sync(0xffffffffu, ps, 1);
        ps += __shfl_xor_sync(0xffffffffu, ps, 2);
        ps += __shfl_xor_sync(0xffffffffu, ps, 4);
        l = l * cs + ps;
        m = newm;
        if (scg == 0) c_s[srow] = cs;
        __syncthreads();

        float cs0 = c_s[r0], cs1 = c_s[r1];
#pragma unroll
        for (int j = 0; j < 8; j++) {
            acc[0][j].x *= cs0; acc[0][j].y *= cs0;
            acc[1][j].x *= cs1; acc[1][j].y *= cs1;
        }
#pragma unroll 2
        for (int kk = 0; kk < 64; ++kk) {
            float p0 = p_s[r0*64 + kk];
            float p1 = p_s[r1*64 + kk];
            float2 pd0 = make_float2(p0, p0);
            float2 pd1 = make_float2(p1, p1);
            int ks = (kk >> 2) & 15;
#pragma unroll
            for (int cc = 0; cc < 4; ++cc) {
                float4 kvv = k_s[kk*64 + ((tx + 16*cc) ^ ks)];
                acc[0][2*cc]   = ffma2(pd0, make_float2(kvv.x, kvv.y), acc[0][2*cc]);
                acc[0][2*cc+1] = ffma2(pd0, make_float2(kvv.z, kvv.w), acc[0][2*cc+1]);
                acc[1][2*cc]   = ffma2(pd1, make_float2(kvv.x, kvv.y), acc[1][2*cc]);
                acc[1][2*cc+1] = ffma2(pd1, make_float2(kvv.z, kvv.w), acc[1][2*cc+1]);
            }
        }
    }

    if (scg == 0) {
        float sk = sink[h];
        float mf = fmaxf(m, sk);
        float cf = __expf(m - mf);
        float denom = l * cf + __expf(sk - mf);
        o_s[srow] = cf / denom;
    }
    __syncthreads();
    float os0 = o_s[r0], os1 = o_s[r1];
#pragma unroll
    for (int cc = 0; cc < 4; ++cc) {
        int col = 4*(tx + 16*cc);
        float* op0 = &o[((size_t)(qb*32 + r0) * H_ + h) * D_ + col];
        float* op1 = &o[((size_t)(qb*32 + r1) * H_ + h) * D_ + col];
        *(float4*)op0 = make_float4(acc[0][2*cc].x*os0, acc[0][2*cc].y*os0,
                                    acc[0][2*cc+1].x*os0, acc[0][2*cc+1].y*os0);
        *(float4*)op1 = make_float4(acc[1][2*cc].x*os1, acc[1][2*cc].y*os1,
                                    acc[1][2*cc+1].x*os1, acc[1][2*cc+1].y*os1);
    }
}

// ---------------- conj RoPE on o's last 64 dims ----------------------------
__global__ void k_orope(float* __restrict__ o,
                        const float* __restrict__ cb, const float* __restrict__ sb) {
    int idx = blockIdx.x * 256 + threadIdx.x;   // S*H*32
    if (idx >= S_ * H_ * 32) return;
    int i = idx & 31;
    int h = (idx >> 5) & 15;
    int s = idx >> 9;
    float c = cb[s*32 + i], sn = sb[s*32 + i];
    float* p = &o[((size_t)s * H_ + h) * D_ + NOPE_ + 2*i];
    float x1 = p[0], x2 = p[1];
    p[0] = x1 * c + x2 * sn;    // conj rotation
    p[1] = -x1 * sn + x2 * c;
}

// ---------------- launch ----------------------------------------------------
extern "C" void kernel_launch(void* const* d_in, const int* in_sizes, int n_in,
                              void* d_out, int out_size) {
    const float* x     = (const float*)d_in[0];
    const float* freqs = (const float*)d_in[1];
    const float* wq_a  = (const float*)d_in[2];
    const float* qnw   = (const float*)d_in[3];
    const float* wq_b  = (const float*)d_in[4];
    const float* wkv   = (const float*)d_in[5];
    const float* kvnw  = (const float*)d_in[6];
    const float* wo_a  = (const float*)d_in[7];
    const float* wo_b  = (const float*)d_in[8];
    const float* sink  = (const float*)d_in[9];
    float* out = (float*)d_out;

    float *qa, *q, *kv, *o, *orr, *cb, *sb;
    __nv_bfloat16 *xs, *wqas, *qas, *wqbs, *wkvs, *os, *woas, *ors, *wobs;
    cudaGetSymbolAddress((void**)&qa,  g_qa);
    cudaGetSymbolAddress((void**)&q,   g_q);
    cudaGetSymbolAddress((void**)&kv,  g_kv);
    cudaGetSymbolAddress((void**)&o,   g_o);
    cudaGetSymbolAddress((void**)&orr, g_or);
    cudaGetSymbolAddress((void**)&cb,  g_cos);
    cudaGetSymbolAddress((void**)&sb,  g_sin);
    cudaGetSymbolAddress((void**)&xs,   g_xs);
    cudaGetSymbolAddress((void**)&wqas, g_wqas);
    cudaGetSymbolAddress((void**)&qas,  g_qas);
    cudaGetSymbolAddress((void**)&wqbs, g_wqbs);
    cudaGetSymbolAddress((void**)&wkvs, g_wkvs);
    cudaGetSymbolAddress((void**)&os,   g_os);
    cudaGetSymbolAddress((void**)&woas, g_woas);
    cudaGetSymbolAddress((void**)&ors,  g_ors);
    cudaGetSymbolAddress((void**)&wobs, g_wobs);

    size_t attn_smem = 6144 * sizeof(float4) + (2048 + 64) * sizeof(float);
    cudaFuncSetAttribute(k_attn2, cudaFuncAttributeMaxDynamicSharedMemorySize,
                         (int)attn_smem);
    size_t hg_smem = 128 + 2 * 32768;   // align slop + 2 double-buffers
    cudaFuncSetAttribute(k_hgemm, cudaFuncAttributeMaxDynamicSharedMemorySize,
                         (int)hg_smem);

    k_cossin<<<(S_*32 + 255)/256, 256>>>(freqs, cb, sb);

    // ---- splits for stage-1 GEMMs ----
    k_split<<<dim3(HID_/256, S_),   256>>>(x,    xs,   HID_, HID_, 0, 0, 0);
    k_split<<<dim3(HID_/256, QL_),  256>>>(wq_a, wqas, HID_, HID_, 0, 0, 1);
    k_split<<<dim3(HID_/256, D_),   256>>>(wkv,  wkvs, HID_, HID_, 0, 0, 1);

    // qa = x @ wq_a^T   [2048,1024], K3=6144
    k_hgemm<<<dim3(QL_/128, S_/128), 256, hg_smem>>>(xs, wqas, qa,
                                                     3*HID_, QL_, 0, 0, 0);
    k_rmsrow<<<S_, 256>>>(qa, qnw, QL_);
    k_split<<<dim3(QL_/256, S_),    256>>>(qa,   qas,  QL_, QL_, 0, 0, 0);
    k_split<<<dim3(QL_/256, H_*D_), 256>>>(wq_b, wqbs, QL_, QL_, 0, 0, 1);
    // q = qa @ wq_b^T   [2048,4096], K3=3072
    k_hgemm<<<dim3(H_*D_/128, S_/128), 256, hg_smem>>>(qas, wqbs, q,
                                                       3*QL_, H_*D_, 0, 0, 0);
    // kv = x @ wkv^T    [2048,256], K3=6144
    k_hgemm<<<dim3(D_/128, S_/128), 256, hg_smem>>>(xs, wkvs, kv,
                                                    3*HID_, D_, 0, 0, 0);
    k_kvproc<<<S_, 256>>>(kv, kvnw, cb, sb);
    k_qproc<<<S_*H_, 256>>>(q, cb, sb);

    // attention
    k_attn2<<<dim3(64*16), 256, attn_smem>>>(q, kv, sink, o);
    k_orope<<<(S_*H_*32 + 255)/256, 256>>>(o, cb, sb);

    // ---- output projections ----
    k_split<<<dim3(1024/256, S_, G_), 256>>>(o, os, 1024, H_*D_,
                                             1024, (size_t)S_*3*1024, 0);
    k_split<<<dim3(1024/256, G_*OR_), 256>>>(wo_a, woas, 1024, 1024, 0, 0, 1);
    // o_r[g] = o_g @ wo_a[g]^T : batched, [2048,512] per group, K3=3072
    k_hgemm<<<dim3(OR_/128, S_/128, G_), 256, hg_smem>>>(
        os, woas, orr, 3*1024, G_*OR_,
        (size_t)S_*3*1024, (size_t)OR_*3*1024, OR_);

    k_split<<<dim3((G_*OR_)/256, S_),  256>>>(orr,  ors,  G_*OR_, G_*OR_, 0, 0, 0);
    k_split<<<dim3((G_*OR_)/256, HID_), 256>>>(wo_b, wobs, G_*OR_, G_*OR_, 0, 0, 1);
    // out = o_r @ wo_b^T  [2048,2048], K3=6144
    k_hgemm<<<dim3(HID_/128, S_/128), 256, hg_smem>>>(ors, wobs, out,
                                                      3*(G_*OR_), HID_, 0, 0, 0);
}

// round 12
// speedup vs baseline: 7.9207x; 1.6228x over previous
#include <cuda_runtime.h>
#include <cuda_bf16.h>
#include <math.h>
#include <stdint.h>

#define S_    2048
#define HID_  2048
#define H_    16
#define D_    256
#define R_    64
#define NOPE_ 192
#define QL_   1024
#define OR_   512
#define G_    4
#define EPS_  1e-6f
#define SCALE_ 0.0625f   // 256^-0.5

// ---------------- scratch (static device arrays; no allocs allowed) -------
__device__ float g_qa [S_*QL_];
__device__ float g_q  [S_*H_*D_];
__device__ float g_kv [S_*D_];
__device__ float g_o  [S_*H_*D_];
__device__ float g_or [S_*G_*OR_];
__device__ float g_cos[S_*(R_/2)];
__device__ float g_sin[S_*(R_/2)];
// bf16 3-term split operands (K tripled)
__device__ __nv_bfloat16 g_xs   [S_*3*HID_];
__device__ __nv_bfloat16 g_wqas [QL_*3*HID_];
__device__ __nv_bfloat16 g_qas  [S_*3*QL_];
__device__ __nv_bfloat16 g_wqbs [H_*D_*3*QL_];
__device__ __nv_bfloat16 g_wkvs [D_*3*HID_];
__device__ __nv_bfloat16 g_os   [G_*S_*3*1024];
__device__ __nv_bfloat16 g_woas [G_*OR_*3*1024];
__device__ __nv_bfloat16 g_ors  [S_*3*(G_*OR_)];
__device__ __nv_bfloat16 g_wobs [HID_*3*(G_*OR_)];

// ---------------- small PTX helpers ----------------------------------------
__device__ __forceinline__ uint32_t smem_u32(const void* p) {
    uint32_t a;
    asm("{ .reg .u64 t; cvta.to.shared.u64 t, %1; cvt.u32.u64 %0, t; }"
        : "=r"(a) : "l"(p));
    return a;
}
__device__ __forceinline__ void cp_async16(uint32_t saddr, const void* gaddr) {
    asm volatile("cp.async.cg.shared.global [%0], [%1], 16;"
                 :: "r"(saddr), "l"(gaddr));
}
#define CP_COMMIT() asm volatile("cp.async.commit_group;" ::: "memory")
#define CP_WAIT1()  asm volatile("cp.async.wait_group 1;" ::: "memory")
#define CP_WAIT0()  asm volatile("cp.async.wait_group 0;" ::: "memory")

__device__ __forceinline__ void ldsm4(uint32_t& r0, uint32_t& r1,
                                      uint32_t& r2, uint32_t& r3, uint32_t a) {
    asm volatile("ldmatrix.sync.aligned.m8n8.x4.shared.b16 {%0,%1,%2,%3}, [%4];"
                 : "=r"(r0), "=r"(r1), "=r"(r2), "=r"(r3) : "r"(a));
}
__device__ __forceinline__ void ldsm4t(uint32_t& r0, uint32_t& r1,
                                       uint32_t& r2, uint32_t& r3, uint32_t a) {
    asm volatile("ldmatrix.sync.aligned.m8n8.x4.trans.shared.b16 {%0,%1,%2,%3}, [%4];"
                 : "=r"(r0), "=r"(r1), "=r"(r2), "=r"(r3) : "r"(a));
}
__device__ __forceinline__ void mma_bf16(float* d, const uint32_t* a,
                                         const uint32_t* b) {
    asm volatile("mma.sync.aligned.m16n8k16.row.col.f32.bf16.bf16.f32 "
                 "{%0,%1,%2,%3}, {%4,%5,%6,%7}, {%8,%9}, {%0,%1,%2,%3};"
                 : "+f"(d[0]), "+f"(d[1]), "+f"(d[2]), "+f"(d[3])
                 : "r"(a[0]), "r"(a[1]), "r"(a[2]), "r"(a[3]),
                   "r"(b[0]), "r"(b[1]));
}

// ---------------- cos/sin precompute --------------------------------------
__global__ void k_cossin(const float* __restrict__ f,
                         float* __restrict__ c, float* __restrict__ s) {
    int i = blockIdx.x * 256 + threadIdx.x;
    if (i < S_ * (R_/2)) { c[i] = cosf(f[i]); s[i] = sinf(f[i]); }
}

// ---------------- bf16 3-term split ----------------------------------------
__global__ void k_split(const float* __restrict__ in, __nv_bfloat16* __restrict__ out,
                        int K, int in_ld, size_t in_goff, size_t out_gstride, int mode) {
    const float* ip = in + in_goff * blockIdx.z;
    __nv_bfloat16* op = out + out_gstride * blockIdx.z;
    int k = blockIdx.x * 256 + threadIdx.x;
    int row = blockIdx.y;
    float v = ip[(size_t)row * in_ld + k];
    __nv_bfloat16 hi = __float2bfloat16(v);
    __nv_bfloat16 lo = __float2bfloat16(v - __bfloat162float(hi));
    size_t ob = (size_t)row * 3 * K;
    if (mode == 0) {
        op[ob + k] = hi; op[ob + K + k] = lo; op[ob + 2*K + k] = hi;
    } else {
        op[ob + k] = hi; op[ob + K + k] = hi; op[ob + 2*K + k] = lo;
    }
}

// ---------------- HMMA bf16 GEMM: C[M,N] = A[M,K3] @ B[N,K3]^T -------------
__global__ void __launch_bounds__(256)
k_hgemm(const __nv_bfloat16* __restrict__ A, const __nv_bfloat16* __restrict__ B,
        float* __restrict__ C, int K3, int ldc,
        size_t sA, size_t sB, size_t sC) {
    extern __shared__ char smem_raw[];
    uint32_t sb_raw = smem_u32(smem_raw);
    uint32_t sb = (sb_raw + 127) & ~127u;

    A += sA * blockIdx.z; B += sB * blockIdx.z; C += sC * blockIdx.z;
    const int bn = blockIdx.x * 128, bm = blockIdx.y * 128;
    int t = threadIdx.x, lane = t & 31, wid = t >> 5;
    int wm = wid & 3, wn = wid >> 2;

    int r = t >> 1, hh = t & 1;
    const char* Ag = (const char*)(A + (size_t)(bm + r) * K3) + hh * 64;
    const char* Bg = (const char*)(B + (size_t)(bn + r) * K3) + hh * 64;
    uint32_t soff[4];
#pragma unroll
    for (int i = 0; i < 4; i++) {
        uint32_t off = (uint32_t)(r * 128 + hh * 64 + i * 16);
        soff[i] = off ^ ((off >> 3) & 0x70);
    }

#define LOADC(c, buf) do {                                                    \
        const char* ag = Ag + (size_t)(c) * 128;                              \
        const char* bg = Bg + (size_t)(c) * 128;                              \
        uint32_t ab = sb + (buf) * 32768;                                     \
        uint32_t bb = ab + 16384;                                             \
        cp_async16(ab + soff[0], ag);       cp_async16(ab + soff[1], ag + 16);\
        cp_async16(ab + soff[2], ag + 32);  cp_async16(ab + soff[3], ag + 48);\
        cp_async16(bb + soff[0], bg);       cp_async16(bb + soff[1], bg + 16);\
        cp_async16(bb + soff[2], bg + 32);  cp_async16(bb + soff[3], bg + 48);\
    } while (0)

    float d[2][8][4];
#pragma unroll
    for (int i = 0; i < 2; i++)
#pragma unroll
        for (int j = 0; j < 8; j++)
#pragma unroll
            for (int k = 0; k < 4; k++) d[i][j][k] = 0.f;

    const int nch = K3 >> 6;
    LOADC(0, 0);
    CP_COMMIT();

    uint32_t a_off[2];
#pragma unroll
    for (int i = 0; i < 2; i++) {
        uint32_t off = (uint32_t)((wm*32 + i*16 + (lane & 15)) * 128 + (lane >> 4) * 16);
        a_off[i] = off ^ ((off >> 3) & 0x70);
    }
    uint32_t b_off[4];
#pragma unroll
    for (int jp = 0; jp < 4; jp++) {
        uint32_t off = (uint32_t)((wn*64 + jp*16 + ((lane >> 4) << 3) + (lane & 7)) * 128
                                  + ((lane >> 3) & 1) * 16);
        b_off[jp] = off ^ ((off >> 3) & 0x70);
    }

    for (int c = 0; c < nch; ++c) {
        int buf = c & 1;
        if (c + 1 < nch) { LOADC(c + 1, buf ^ 1); CP_COMMIT(); CP_WAIT1(); }
        else             { CP_WAIT0(); }
        __syncthreads();

        uint32_t abase = sb + buf * 32768;
        uint32_t bbase = abase + 16384;
#pragma unroll
        for (int ks = 0; ks < 4; ++ks) {
            uint32_t kb = ks * 32;
            uint32_t a_f[2][4];
#pragma unroll
            for (int i = 0; i < 2; i++)
                ldsm4(a_f[i][0], a_f[i][1], a_f[i][2], a_f[i][3],
                      abase + (a_off[i] ^ kb));
            uint32_t b_f[8][2];
#pragma unroll
            for (int jp = 0; jp < 4; jp++) {
                uint32_t r0, r1, r2, r3;
                ldsm4(r0, r1, r2, r3, bbase + (b_off[jp] ^ kb));
                b_f[jp*2][0] = r0;   b_f[jp*2][1] = r1;
                b_f[jp*2+1][0] = r2; b_f[jp*2+1][1] = r3;
            }
#pragma unroll
            for (int i = 0; i < 2; i++)
#pragma unroll
                for (int j = 0; j < 8; j++)
                    mma_bf16(d[i][j], a_f[i], b_f[j]);
        }
        __syncthreads();
    }

#pragma unroll
    for (int i = 0; i < 2; i++) {
        int row0 = bm + wm*32 + i*16 + (lane >> 2);
#pragma unroll
        for (int j = 0; j < 8; j++) {
            int col = bn + wn*64 + j*8 + (lane & 3)*2;
            *(float2*)&C[(size_t)row0 * ldc + col] = make_float2(d[i][j][0], d[i][j][1]);
            *(float2*)&C[(size_t)(row0 + 8) * ldc + col] = make_float2(d[i][j][2], d[i][j][3]);
        }
    }
#undef LOADC
}

// ---------------- rmsnorm over rows of length N with weight ----------------
__global__ void k_rmsrow(float* __restrict__ x, const float* __restrict__ w, int N) {
    int row = blockIdx.x, t = threadIdx.x;
    float* xp = x + (size_t)row * N;
    float ss = 0.f;
    for (int i = t; i < N; i += 256) { float v = xp[i]; ss += v * v; }
#pragma unroll
    for (int o = 16; o; o >>= 1) ss += __shfl_xor_sync(0xffffffffu, ss, o);
    __shared__ float wr[8];
    __shared__ float rinv;
    if ((t & 31) == 0) wr[t >> 5] = ss;
    __syncthreads();
    if (t == 0) {
        float tot = 0.f;
        for (int i = 0; i < 8; i++) tot += wr[i];
        rinv = rsqrtf(tot / (float)N + EPS_);
    }
    __syncthreads();
    float r = rinv;
    for (int i = t; i < N; i += 256) xp[i] = xp[i] * r * w[i];
}

// ---------------- q per-head norm (no weight) + RoPE on last 64 -----------
__global__ void k_qproc(float* __restrict__ q,
                        const float* __restrict__ cb, const float* __restrict__ sb) {
    int s = blockIdx.x >> 4;
    int h = blockIdx.x & 15;
    int t = threadIdx.x;   // 256
    float* qp = q + ((size_t)s * H_ + h) * D_;
    float v = qp[t];
    float ss = v * v;
#pragma unroll
    for (int o = 16; o; o >>= 1) ss += __shfl_xor_sync(0xffffffffu, ss, o);
    __shared__ float wr[8];
    __shared__ float rinv;
    __shared__ float buf[D_];
    if ((t & 31) == 0) wr[t >> 5] = ss;
    __syncthreads();
    if (t == 0) {
        float tot = 0.f;
        for (int i = 0; i < 8; i++) tot += wr[i];
        rinv = rsqrtf(tot / 256.f + EPS_);
    }
    __syncthreads();
    buf[t] = v * rinv;
    __syncthreads();
    if (t < 32) {
        float c = cb[s*32 + t], sn = sb[s*32 + t];
        float x1 = buf[NOPE_ + 2*t], x2 = buf[NOPE_ + 2*t + 1];
        buf[NOPE_ + 2*t]     = x1 * c - x2 * sn;
        buf[NOPE_ + 2*t + 1] = x1 * sn + x2 * c;
    }
    __syncthreads();
    qp[t] = buf[t];
}

// ---------------- kv rmsnorm (with weight) + RoPE on last 64 --------------
__global__ void k_kvproc(float* __restrict__ kv, const float* __restrict__ w,
                         const float* __restrict__ cb, const float* __restrict__ sb) {
    int s = blockIdx.x, t = threadIdx.x;   // 256
    float* p = kv + (size_t)s * D_;
    float v = p[t];
    float ss = v * v;
#pragma unroll
    for (int o = 16; o; o >>= 1) ss += __shfl_xor_sync(0xffffffffu, ss, o);
    __shared__ float wr[8];
    __shared__ float rinv;
    __shared__ float buf[D_];
    if ((t & 31) == 0) wr[t >> 5] = ss;
    __syncthreads();
    if (t == 0) {
        float tot = 0.f;
        for (int i = 0; i < 8; i++) tot += wr[i];
        rinv = rsqrtf(tot / 256.f + EPS_);
    }
    __syncthreads();
    buf[t] = v * rinv * w[t];
    __syncthreads();
    if (t < 32) {
        float c = cb[s*32 + t], sn = sb[s*32 + t];
        float x1 = buf[NOPE_ + 2*t], x2 = buf[NOPE_ + 2*t + 1];
        buf[NOPE_ + 2*t]     = x1 * c - x2 * sn;
        buf[NOPE_ + 2*t + 1] = x1 * sn + x2 * c;
    }
    __syncthreads();
    p[t] = buf[t];
}

// ================ HMMA flash attention (causal, sink) ======================
// 64 q-rows x 64 k-rows per CTA, 256 threads (8 warps: 4m x 2n).
// bf16 hi/lo 3-pass for QK^T and PV (err ~2^-18). V^T via ldmatrix.trans.
// smem offsets (bytes, 512-aligned base):
#define AQHI 0u
#define AQLO 32768u
#define AKHI 65536u
#define AKLO 98304u
#define APS  131072u
#define APHI 147456u
#define APLO 155648u
#define ACS  163840u
#define AOS  164096u
#define ATTN_SMEM (164352u + 512u)

__global__ void __launch_bounds__(256)
k_attn3(const float* __restrict__ q, const float* __restrict__ kv,
        const float* __restrict__ sink, float* __restrict__ o) {
    extern __shared__ char smraw[];
    uint32_t sb_raw = smem_u32(smraw);
    uint32_t sb = (sb_raw + 511) & ~511u;
    char* sm = smraw + (sb - sb_raw);

    int bid = blockIdx.x;
    int qb = 31 - (bid >> 4);     // longest first
    int h  = bid & 15;
    int t = threadIdx.x, lane = t & 31, wid = t >> 5;
    int wm = wid & 3, wn = wid >> 2;

    // ---- Q tile load + hi/lo split (rows 512B, swizzle ^((r&7)<<4)) ----
#pragma unroll
    for (int i = 0; i < 8; i++) {
        int idx = t + i * 256;
        int r = idx >> 5, u = idx & 31;
        const float4* gp = (const float4*)&q[(((size_t)(qb*64 + r)) * H_ + h) * D_ + u*8];
        float4 v0 = gp[0], v1 = gp[1];
        float f[8] = {v0.x, v0.y, v0.z, v0.w, v1.x, v1.y, v1.z, v1.w};
        uint32_t hw[4], lw[4];
#pragma unroll
        for (int j = 0; j < 4; j++) {
            __nv_bfloat16 h0 = __float2bfloat16(f[2*j]);
            __nv_bfloat16 h1 = __float2bfloat16(f[2*j+1]);
            float l0 = f[2*j]   - __bfloat162float(h0);
            float l1 = f[2*j+1] - __bfloat162float(h1);
            __nv_bfloat162 hh; hh.x = h0; hh.y = h1;
            __nv_bfloat162 ll; ll.x = __float2bfloat16(l0); ll.y = __float2bfloat16(l1);
            hw[j] = *(uint32_t*)&hh; lw[j] = *(uint32_t*)&ll;
        }
        uint32_t off = (uint32_t)(r*512 + u*16) ^ ((uint32_t)(r & 7) << 4);
        *(uint4*)(sm + AQHI + off) = make_uint4(hw[0], hw[1], hw[2], hw[3]);
        *(uint4*)(sm + AQLO + off) = make_uint4(lw[0], lw[1], lw[2], lw[3]);
    }

    // ---- fragment address precomputes (XOR-decomposable swizzles) ----
    uint32_t a_pre;   // score A from Q tiles (512B rows)
    { int row = wm*16 + (lane & 15);
      a_pre = (uint32_t)(row*512) ^ ((uint32_t)(lane >> 4) << 4)
            ^ ((uint32_t)(lane & 7) << 4); }
    uint32_t b_pre[2];   // score B from K tiles
#pragma unroll
    for (int jp = 0; jp < 2; jp++) {
        int row = wn*32 + jp*16 + ((lane >> 4) << 3) + (lane & 7);
        b_pre[jp] = (uint32_t)(row*512) ^ (((uint32_t)(lane >> 3) & 1u) << 4)
                  ^ ((uint32_t)(lane & 7) << 4);
    }
    uint32_t pa_pre;  // PV A from P tiles (128B rows)
    { int row = wm*16 + (lane & 15);
      pa_pre = (uint32_t)(row*128) ^ ((uint32_t)(lane >> 4) << 4)
             ^ ((uint32_t)(lane & 7) << 4); }
    uint32_t pv_pre;  // PV B: trans loads from K tiles
    { int mi = lane >> 3;
      pv_pre = (uint32_t)((((mi & 1)*8 + (lane & 7)) * 512) + wn*256)
             ^ ((uint32_t)(mi >> 1) << 4) ^ ((uint32_t)(lane & 7) << 4); }

    float cpv[16][4];
#pragma unroll
    for (int j = 0; j < 16; j++)
#pragma unroll
        for (int k = 0; k < 4; k++) cpv[j][k] = 0.f;

    float m_ = -1e30f, l_ = 0.f;
    int srow = t >> 2, sc = t & 3;
    int rm_lo = wm*16 + (lane >> 2);    // PV-layout row (low), +8 for high

#define SCORE_PASS(QB, KB) do {                                               \
    _Pragma("unroll")                                                         \
    for (int ks = 0; ks < 16; ++ks) {                                         \
        uint32_t a4[4];                                                       \
        ldsm4(a4[0], a4[1], a4[2], a4[3],                                     \
              sb + (QB) + (a_pre ^ ((uint32_t)ks << 5)));                     \
        _Pragma("unroll")                                                     \
        for (int jp = 0; jp < 2; jp++) {                                      \
            uint32_t r0, r1, r2, r3;                                          \
            ldsm4(r0, r1, r2, r3,                                             \
                  sb + (KB) + (b_pre[jp] ^ ((uint32_t)ks << 5)));             \
            uint32_t bA[2] = {r0, r1}, bB[2] = {r2, r3};                      \
            mma_bf16(c[jp*2],   a4, bA);                                      \
            mma_bf16(c[jp*2+1], a4, bB);                                      \
        }                                                                     \
    }                                                                         \
} while (0)

#define PV_PASS(PB, KB) do {                                                  \
    _Pragma("unroll")                                                         \
    for (int ks = 0; ks < 4; ++ks) {                                          \
        uint32_t a4[4];                                                       \
        ldsm4(a4[0], a4[1], a4[2], a4[3],                                     \
              sb + (PB) + (pa_pre ^ ((uint32_t)ks << 5)));                    \
        _Pragma("unroll")                                                     \
        for (int jn = 0; jn < 16; jn += 2) {                                  \
            uint32_t r0, r1, r2, r3;                                          \
            ldsm4t(r0, r1, r2, r3,                                            \
                   sb + (KB) + (uint32_t)(ks*8192) + (pv_pre ^ ((uint32_t)jn << 4))); \
            uint32_t bA[2] = {r0, r1}, bB[2] = {r2, r3};                      \
            mma_bf16(cpv[jn],   a4, bA);                                      \
            mma_bf16(cpv[jn+1], a4, bB);                                      \
        }                                                                     \
    }                                                                         \
} while (0)

    for (int kt = 0; kt <= qb; ++kt) {
        if (kt) __syncthreads();    // prior PV done reading K/P tiles
        // ---- KV tile load + split ----
#pragma unroll
        for (int i = 0; i < 8; i++) {
            int idx = t + i * 256;
            int r = idx >> 5, u = idx & 31;
            const float4* gp = (const float4*)&kv[((size_t)(kt*64 + r)) * D_ + u*8];
            float4 v0 = gp[0], v1 = gp[1];
            float f[8] = {v0.x, v0.y, v0.z, v0.w, v1.x, v1.y, v1.z, v1.w};
            uint32_t hw[4], lw[4];
#pragma unroll
            for (int j = 0; j < 4; j++) {
                __nv_bfloat16 h0 = __float2bfloat16(f[2*j]);
                __nv_bfloat16 h1 = __float2bfloat16(f[2*j+1]);
                float l0 = f[2*j]   - __bfloat162float(h0);
                float l1 = f[2*j+1] - __bfloat162float(h1);
                __nv_bfloat162 hh; hh.x = h0; hh.y = h1;
                __nv_bfloat162 ll; ll.x = __float2bfloat16(l0); ll.y = __float2bfloat16(l1);
                hw[j] = *(uint32_t*)&hh; lw[j] = *(uint32_t*)&ll;
            }
            uint32_t off = (uint32_t)(r*512 + u*16) ^ ((uint32_t)(r & 7) << 4);
            *(uint4*)(sm + AKHI + off) = make_uint4(hw[0], hw[1], hw[2], hw[3]);
            *(uint4*)(sm + AKLO + off) = make_uint4(lw[0], lw[1], lw[2], lw[3]);
        }
        __syncthreads();

        // ---- scores: 3-pass hi/lo HMMA ----
        float c[4][4];
#pragma unroll
        for (int j = 0; j < 4; j++)
#pragma unroll
            for (int k = 0; k < 4; k++) c[j][k] = 0.f;
        SCORE_PASS(AQHI, AKHI);
        SCORE_PASS(AQLO, AKHI);
        SCORE_PASS(AQHI, AKLO);

        // ---- score epilogue: scale + causal mask -> PS (fp32, 32B-unit swz)
#pragma unroll
        for (int n8 = 0; n8 < 4; n8++) {
            int col  = wn*32 + n8*8 + (lane & 3)*2;
            int gcol = kt*64 + col;
#pragma unroll
            for (int hf = 0; hf < 2; hf++) {
                int row  = wm*16 + (lane >> 2) + hf*8;
                int grow = qb*64 + row;
                float v0 = c[n8][hf*2]   * SCALE_;
                float v1 = c[n8][hf*2+1] * SCALE_;
                if (gcol     > grow) v0 = -1e30f;
                if (gcol + 1 > grow) v1 = -1e30f;
                uint32_t off = (uint32_t)(row*256 + col*4)
                             ^ ((uint32_t)(row & 7) << 5);
                *(float2*)(sm + APS + off) = make_float2(v0, v1);
            }
        }
        __syncthreads();

        // ---- online softmax: 4 threads per row, 16 cols each ----
        float sv[16];
#pragma unroll
        for (int jj = 0; jj < 4; jj++) {
            uint32_t off = (uint32_t)(srow*256 + sc*64 + jj*16)
                         ^ ((uint32_t)(srow & 7) << 5);
            *(float4*)&sv[jj*4] = *(const float4*)(sm + APS + off);
        }
        float tmax = sv[0];
#pragma unroll
        for (int j = 1; j < 16; j++) tmax = fmaxf(tmax, sv[j]);
        tmax = fmaxf(tmax, __shfl_xor_sync(0xffffffffu, tmax, 1));
        tmax = fmaxf(tmax, __shfl_xor_sync(0xffffffffu, tmax, 2));
        float nm = fmaxf(m_, tmax);
        float cs = __expf(m_ - nm);
        float ps = 0.f;
        uint32_t hw[8], lw[8];
#pragma unroll
        for (int j = 0; j < 8; j++) {
            float p0 = __expf(sv[2*j]   - nm);
            float p1 = __expf(sv[2*j+1] - nm);
            ps += p0 + p1;
            __nv_bfloat16 h0 = __float2bfloat16(p0), h1 = __float2bfloat16(p1);
            float l0 = p0 - __bfloat162float(h0), l1 = p1 - __bfloat162float(h1);
            __nv_bfloat162 hh; hh.x = h0; hh.y = h1;
            __nv_bfloat162 ll; ll.x = __float2bfloat16(l0); ll.y = __float2bfloat16(l1);
            hw[j] = *(uint32_t*)&hh; lw[j] = *(uint32_t*)&ll;
        }
        ps += __shfl_xor_sync(0xffffffffu, ps, 1);
        ps += __shfl_xor_sync(0xffffffffu, ps, 2);
        l_ = l_ * cs + ps;
        m_ = nm;
        uint32_t po0 = (uint32_t)(srow*128) ^ ((uint32_t)sc << 5)
                     ^ ((uint32_t)(srow & 7) << 4);
        uint32_t po1 = po0 ^ 16u;
        *(uint4*)(sm + APHI + po0) = make_uint4(hw[0], hw[1], hw[2], hw[3]);
        *(uint4*)(sm + APHI + po1) = make_uint4(hw[4], hw[5], hw[6], hw[7]);
        *(uint4*)(sm + APLO + po0) = make_uint4(lw[0], lw[1], lw[2], lw[3]);
        *(uint4*)(sm + APLO + po1) = make_uint4(lw[4], lw[5], lw[6], lw[7]);
        if (sc == 0) *(float*)(sm + ACS + srow*4) = cs;
        __syncthreads();

        // ---- rescale accumulators + PV (3-pass) ----
        float cs_lo = *(const float*)(sm + ACS + rm_lo*4);
        float cs_hi = *(const float*)(sm + ACS + (rm_lo + 8)*4);
#pragma unroll
        for (int jn = 0; jn < 16; jn++) {
            cpv[jn][0] *= cs_lo; cpv[jn][1] *= cs_lo;
            cpv[jn][2] *= cs_hi; cpv[jn][3] *= cs_hi;
        }
        PV_PASS(APHI, AKHI);
        PV_PASS(APLO, AKHI);
        PV_PASS(APHI, AKLO);
    }

    // ---- fold sink, output scale ----
    if (sc == 0) {
        float sk = sink[h];
        float mf = fmaxf(m_, sk);
        float cf = __expf(m_ - mf);
        float den = l_ * cf + __expf(sk - mf);
        *(float*)(sm + AOS + srow*4) = cf / den;
    }
    __syncthreads();
    float os_lo = *(const float*)(sm + AOS + rm_lo*4);
    float os_hi = *(const float*)(sm + AOS + (rm_lo + 8)*4);
    int s_lo = qb*64 + rm_lo;
#pragma unroll
    for (int jn = 0; jn < 16; jn++) {
        int col = wn*128 + jn*8 + (lane & 3)*2;
        *(float2*)&o[(((size_t)s_lo) * H_ + h) * D_ + col] =
            make_float2(cpv[jn][0]*os_lo, cpv[jn][1]*os_lo);
        *(float2*)&o[(((size_t)(s_lo + 8)) * H_ + h) * D_ + col] =
            make_float2(cpv[jn][2]*os_hi, cpv[jn][3]*os_hi);
    }
#undef SCORE_PASS
#undef PV_PASS
}

// ---------------- conj RoPE on o's last 64 dims ----------------------------
__global__ void k_orope(float* __restrict__ o,
                        const float* __restrict__ cb, const float* __restrict__ sb) {
    int idx = blockIdx.x * 256 + threadIdx.x;   // S*H*32
    if (idx >= S_ * H_ * 32) return;
    int i = idx & 31;
    int h = (idx >> 5) & 15;
    int s = idx >> 9;
    float c = cb[s*32 + i], sn = sb[s*32 + i];
    float* p = &o[((size_t)s * H_ + h) * D_ + NOPE_ + 2*i];
    float x1 = p[0], x2 = p[1];
    p[0] = x1 * c + x2 * sn;    // conj rotation
    p[1] = -x1 * sn + x2 * c;
}

// ---------------- launch ----------------------------------------------------
extern "C" void kernel_launch(void* const* d_in, const int* in_sizes, int n_in,
                              void* d_out, int out_size) {
    const float* x     = (const float*)d_in[0];
    const float* freqs = (const float*)d_in[1];
    const float* wq_a  = (const float*)d_in[2];
    const float* qnw   = (const float*)d_in[3];
    const float* wq_b  = (const float*)d_in[4];
    const float* wkv   = (const float*)d_in[5];
    const float* kvnw  = (const float*)d_in[6];
    const float* wo_a  = (const float*)d_in[7];
    const float* wo_b  = (const float*)d_in[8];
    const float* sink  = (const float*)d_in[9];
    float* out = (float*)d_out;

    float *qa, *q, *kv, *o, *orr, *cb, *sb;
    __nv_bfloat16 *xs, *wqas, *qas, *wqbs, *wkvs, *os, *woas, *ors, *wobs;
    cudaGetSymbolAddress((void**)&qa,  g_qa);
    cudaGetSymbolAddress((void**)&q,   g_q);
    cudaGetSymbolAddress((void**)&kv,  g_kv);
    cudaGetSymbolAddress((void**)&o,   g_o);
    cudaGetSymbolAddress((void**)&orr, g_or);
    cudaGetSymbolAddress((void**)&cb,  g_cos);
    cudaGetSymbolAddress((void**)&sb,  g_sin);
    cudaGetSymbolAddress((void**)&xs,   g_xs);
    cudaGetSymbolAddress((void**)&wqas, g_wqas);
    cudaGetSymbolAddress((void**)&qas,  g_qas);
    cudaGetSymbolAddress((void**)&wqbs, g_wqbs);
    cudaGetSymbolAddress((void**)&wkvs, g_wkvs);
    cudaGetSymbolAddress((void**)&os,   g_os);
    cudaGetSymbolAddress((void**)&woas, g_woas);
    cudaGetSymbolAddress((void**)&ors,  g_ors);
    cudaGetSymbolAddress((void**)&wobs, g_wobs);

    size_t hg_smem = 128 + 2 * 32768;
    cudaFuncSetAttribute(k_hgemm, cudaFuncAttributeMaxDynamicSharedMemorySize,
                         (int)hg_smem);
    cudaFuncSetAttribute(k_attn3, cudaFuncAttributeMaxDynamicSharedMemorySize,
                         (int)ATTN_SMEM);

    k_cossin<<<(S_*32 + 255)/256, 256>>>(freqs, cb, sb);

    // ---- splits for stage-1 GEMMs ----
    k_split<<<dim3(HID_/256, S_),   256>>>(x,    xs,   HID_, HID_, 0, 0, 0);
    k_split<<<dim3(HID_/256, QL_),  256>>>(wq_a, wqas, HID_, HID_, 0, 0, 1);
    k_split<<<dim3(HID_/256, D_),   256>>>(wkv,  wkvs, HID_, HID_, 0, 0, 1);

    // qa = x @ wq_a^T   [2048,1024], K3=6144
    k_hgemm<<<dim3(QL_/128, S_/128), 256, hg_smem>>>(xs, wqas, qa,
                                                     3*HID_, QL_, 0, 0, 0);
    k_rmsrow<<<S_, 256>>>(qa, qnw, QL_);
    k_split<<<dim3(QL_/256, S_),    256>>>(qa,   qas,  QL_, QL_, 0, 0, 0);
    k_split<<<dim3(QL_/256, H_*D_), 256>>>(wq_b, wqbs, QL_, QL_, 0, 0, 1);
    // q = qa @ wq_b^T   [2048,4096], K3=3072
    k_hgemm<<<dim3(H_*D_/128, S_/128), 256, hg_smem>>>(qas, wqbs, q,
                                                       3*QL_, H_*D_, 0, 0, 0);
    // kv = x @ wkv^T    [2048,256], K3=6144
    k_hgemm<<<dim3(D_/128, S_/128), 256, hg_smem>>>(xs, wkvs, kv,
                                                    3*HID_, D_, 0, 0, 0);
    k_kvproc<<<S_, 256>>>(kv, kvnw, cb, sb);
    k_qproc<<<S_*H_, 256>>>(q, cb, sb);

    // attention: 32 q-tiles of 64 rows x 16 heads, HMMA 3-pass
    k_attn3<<<dim3(32*16), 256, ATTN_SMEM>>>(q, kv, sink, o);
    k_orope<<<(S_*H_*32 + 255)/256, 256>>>(o, cb, sb);

    // ---- output projections ----
    k_split<<<dim3(1024/256, S_, G_), 256>>>(o, os, 1024, H_*D_,
                                             1024, (size_t)S_*3*1024, 0);
    k_split<<<dim3(1024/256, G_*OR_), 256>>>(wo_a, woas, 1024, 1024, 0, 0, 1);
    // o_r[g] = o_g @ wo_a[g]^T : batched, [2048,512] per group, K3=3072
    k_hgemm<<<dim3(OR_/128, S_/128, G_), 256, hg_smem>>>(
        os, woas, orr, 3*1024, G_*OR_,
        (size_t)S_*3*1024, (size_t)OR_*3*1024, OR_);

    k_split<<<dim3((G_*OR_)/256, S_),  256>>>(orr,  ors,  G_*OR_, G_*OR_, 0, 0, 0);
    k_split<<<dim3((G_*OR_)/256, HID_), 256>>>(wo_b, wobs, G_*OR_, G_*OR_, 0, 0, 1);
    // out = o_r @ wo_b^T  [2048,2048], K3=6144
    k_hgemm<<<dim3(HID_/128, S_/128), 256, hg_smem>>>(ors, wobs, out,
                                                      3*(G_*OR_), HID_, 0, 0, 0);
}

// round 13
// speedup vs baseline: 8.1254x; 1.0259x over previous
#include <cuda_runtime.h>
#include <cuda_bf16.h>
#include <math.h>
#include <stdint.h>

#define S_    2048
#define HID_  2048
#define H_    16
#define D_    256
#define R_    64
#define NOPE_ 192
#define QL_   1024
#define OR_   512
#define G_    4
#define EPS_  1e-6f
#define SCALE_ 0.0625f   // 256^-0.5

// ---------------- scratch (static device arrays; no allocs allowed) -------
__device__ float g_qa [S_*QL_];
__device__ float g_q  [S_*H_*D_];
__device__ float g_kv [S_*D_];
__device__ float g_o  [S_*H_*D_];
__device__ float g_or [S_*G_*OR_];
__device__ float g_cos[S_*(R_/2)];
__device__ float g_sin[S_*(R_/2)];
// bf16 3-term split operands (K tripled) for GEMMs
__device__ __nv_bfloat16 g_xs   [S_*3*HID_];
__device__ __nv_bfloat16 g_wqas [QL_*3*HID_];
__device__ __nv_bfloat16 g_qas  [S_*3*QL_];
__device__ __nv_bfloat16 g_wqbs [H_*D_*3*QL_];
__device__ __nv_bfloat16 g_wkvs [D_*3*HID_];
__device__ __nv_bfloat16 g_os   [G_*S_*3*1024];
__device__ __nv_bfloat16 g_woas [G_*OR_*3*1024];
__device__ __nv_bfloat16 g_ors  [S_*3*(G_*OR_)];
__device__ __nv_bfloat16 g_wobs [HID_*3*(G_*OR_)];
// attention hi/lo operands (pre-split once)
__device__ __nv_bfloat16 g_qhi [S_*H_*D_];
__device__ __nv_bfloat16 g_qlo [S_*H_*D_];
__device__ __nv_bfloat16 g_kvhi[S_*D_];
__device__ __nv_bfloat16 g_kvlo[S_*D_];

// ---------------- small PTX helpers ----------------------------------------
__device__ __forceinline__ uint32_t smem_u32(const void* p) {
    uint32_t a;
    asm("{ .reg .u64 t; cvta.to.shared.u64 t, %1; cvt.u32.u64 %0, t; }"
        : "=r"(a) : "l"(p));
    return a;
}
__device__ __forceinline__ void cp_async16(uint32_t saddr, const void* gaddr) {
    asm volatile("cp.async.cg.shared.global [%0], [%1], 16;"
                 :: "r"(saddr), "l"(gaddr));
}
#define CP_COMMIT() asm volatile("cp.async.commit_group;" ::: "memory")
#define CP_WAIT1()  asm volatile("cp.async.wait_group 1;" ::: "memory")
#define CP_WAIT0()  asm volatile("cp.async.wait_group 0;" ::: "memory")

__device__ __forceinline__ void ldsm4(uint32_t& r0, uint32_t& r1,
                                      uint32_t& r2, uint32_t& r3, uint32_t a) {
    asm volatile("ldmatrix.sync.aligned.m8n8.x4.shared.b16 {%0,%1,%2,%3}, [%4];"
                 : "=r"(r0), "=r"(r1), "=r"(r2), "=r"(r3) : "r"(a));
}
__device__ __forceinline__ void ldsm4t(uint32_t& r0, uint32_t& r1,
                                       uint32_t& r2, uint32_t& r3, uint32_t a) {
    asm volatile("ldmatrix.sync.aligned.m8n8.x4.trans.shared.b16 {%0,%1,%2,%3}, [%4];"
                 : "=r"(r0), "=r"(r1), "=r"(r2), "=r"(r3) : "r"(a));
}
__device__ __forceinline__ void mma_bf16(float* d, const uint32_t* a,
                                         const uint32_t* b) {
    asm volatile("mma.sync.aligned.m16n8k16.row.col.f32.bf16.bf16.f32 "
                 "{%0,%1,%2,%3}, {%4,%5,%6,%7}, {%8,%9}, {%0,%1,%2,%3};"
                 : "+f"(d[0]), "+f"(d[1]), "+f"(d[2]), "+f"(d[3])
                 : "r"(a[0]), "r"(a[1]), "r"(a[2]), "r"(a[3]),
                   "r"(b[0]), "r"(b[1]));
}

// ---------------- cos/sin precompute --------------------------------------
__global__ void k_cossin(const float* __restrict__ f,
                         float* __restrict__ c, float* __restrict__ s) {
    int i = blockIdx.x * 256 + threadIdx.x;
    if (i < S_ * (R_/2)) { c[i] = cosf(f[i]); s[i] = sinf(f[i]); }
}

// ---------------- bf16 3-term split ----------------------------------------
__global__ void k_split(const float* __restrict__ in, __nv_bfloat16* __restrict__ out,
                        int K, int in_ld, size_t in_goff, size_t out_gstride, int mode) {
    const float* ip = in + in_goff * blockIdx.z;
    __nv_bfloat16* op = out + out_gstride * blockIdx.z;
    int k = blockIdx.x * 256 + threadIdx.x;
    int row = blockIdx.y;
    float v = ip[(size_t)row * in_ld + k];
    __nv_bfloat16 hi = __float2bfloat16(v);
    __nv_bfloat16 lo = __float2bfloat16(v - __bfloat162float(hi));
    size_t ob = (size_t)row * 3 * K;
    if (mode == 0) {
        op[ob + k] = hi; op[ob + K + k] = lo; op[ob + 2*K + k] = hi;
    } else {
        op[ob + k] = hi; op[ob + K + k] = hi; op[ob + 2*K + k] = lo;
    }
}

// ---------------- HMMA bf16 GEMM: C[M,N] = A[M,K3] @ B[N,K3]^T -------------
__global__ void __launch_bounds__(256)
k_hgemm(const __nv_bfloat16* __restrict__ A, const __nv_bfloat16* __restrict__ B,
        float* __restrict__ C, int K3, int ldc,
        size_t sA, size_t sB, size_t sC) {
    extern __shared__ char smem_raw[];
    uint32_t sb_raw = smem_u32(smem_raw);
    uint32_t sb = (sb_raw + 127) & ~127u;

    A += sA * blockIdx.z; B += sB * blockIdx.z; C += sC * blockIdx.z;
    const int bn = blockIdx.x * 128, bm = blockIdx.y * 128;
    int t = threadIdx.x, lane = t & 31, wid = t >> 5;
    int wm = wid & 3, wn = wid >> 2;

    int r = t >> 1, hh = t & 1;
    const char* Ag = (const char*)(A + (size_t)(bm + r) * K3) + hh * 64;
    const char* Bg = (const char*)(B + (size_t)(bn + r) * K3) + hh * 64;
    uint32_t soff[4];
#pragma unroll
    for (int i = 0; i < 4; i++) {
        uint32_t off = (uint32_t)(r * 128 + hh * 64 + i * 16);
        soff[i] = off ^ ((off >> 3) & 0x70);
    }

#define LOADC(c, buf) do {                                                    \
        const char* ag = Ag + (size_t)(c) * 128;                              \
        const char* bg = Bg + (size_t)(c) * 128;                              \
        uint32_t ab = sb + (buf) * 32768;                                     \
        uint32_t bb = ab + 16384;                                             \
        cp_async16(ab + soff[0], ag);       cp_async16(ab + soff[1], ag + 16);\
        cp_async16(ab + soff[2], ag + 32);  cp_async16(ab + soff[3], ag + 48);\
        cp_async16(bb + soff[0], bg);       cp_async16(bb + soff[1], bg + 16);\
        cp_async16(bb + soff[2], bg + 32);  cp_async16(bb + soff[3], bg + 48);\
    } while (0)

    float d[2][8][4];
#pragma unroll
    for (int i = 0; i < 2; i++)
#pragma unroll
        for (int j = 0; j < 8; j++)
#pragma unroll
            for (int k = 0; k < 4; k++) d[i][j][k] = 0.f;

    const int nch = K3 >> 6;
    LOADC(0, 0);
    CP_COMMIT();

    uint32_t a_off[2];
#pragma unroll
    for (int i = 0; i < 2; i++) {
        uint32_t off = (uint32_t)((wm*32 + i*16 + (lane & 15)) * 128 + (lane >> 4) * 16);
        a_off[i] = off ^ ((off >> 3) & 0x70);
    }
    uint32_t b_off[4];
#pragma unroll
    for (int jp = 0; jp < 4; jp++) {
        uint32_t off = (uint32_t)((wn*64 + jp*16 + ((lane >> 4) << 3) + (lane & 7)) * 128
                                  + ((lane >> 3) & 1) * 16);
        b_off[jp] = off ^ ((off >> 3) & 0x70);
    }

    for (int c = 0; c < nch; ++c) {
        int buf = c & 1;
        if (c + 1 < nch) { LOADC(c + 1, buf ^ 1); CP_COMMIT(); CP_WAIT1(); }
        else             { CP_WAIT0(); }
        __syncthreads();

        uint32_t abase = sb + buf * 32768;
        uint32_t bbase = abase + 16384;
#pragma unroll
        for (int ks = 0; ks < 4; ++ks) {
            uint32_t kb = ks * 32;
            uint32_t a_f[2][4];
#pragma unroll
            for (int i = 0; i < 2; i++)
                ldsm4(a_f[i][0], a_f[i][1], a_f[i][2], a_f[i][3],
                      abase + (a_off[i] ^ kb));
            uint32_t b_f[8][2];
#pragma unroll
            for (int jp = 0; jp < 4; jp++) {
                uint32_t r0, r1, r2, r3;
                ldsm4(r0, r1, r2, r3, bbase + (b_off[jp] ^ kb));
                b_f[jp*2][0] = r0;   b_f[jp*2][1] = r1;
                b_f[jp*2+1][0] = r2; b_f[jp*2+1][1] = r3;
            }
#pragma unroll
            for (int i = 0; i < 2; i++)
#pragma unroll
                for (int j = 0; j < 8; j++)
                    mma_bf16(d[i][j], a_f[i], b_f[j]);
        }
        __syncthreads();
    }

#pragma unroll
    for (int i = 0; i < 2; i++) {
        int row0 = bm + wm*32 + i*16 + (lane >> 2);
#pragma unroll
        for (int j = 0; j < 8; j++) {
            int col = bn + wn*64 + j*8 + (lane & 3)*2;
            *(float2*)&C[(size_t)row0 * ldc + col] = make_float2(d[i][j][0], d[i][j][1]);
            *(float2*)&C[(size_t)(row0 + 8) * ldc + col] = make_float2(d[i][j][2], d[i][j][3]);
        }
    }
#undef LOADC
}

// ---------------- rmsnorm over rows of length N with weight ----------------
__global__ void k_rmsrow(float* __restrict__ x, const float* __restrict__ w, int N) {
    int row = blockIdx.x, t = threadIdx.x;
    float* xp = x + (size_t)row * N;
    float ss = 0.f;
    for (int i = t; i < N; i += 256) { float v = xp[i]; ss += v * v; }
#pragma unroll
    for (int o = 16; o; o >>= 1) ss += __shfl_xor_sync(0xffffffffu, ss, o);
    __shared__ float wr[8];
    __shared__ float rinv;
    if ((t & 31) == 0) wr[t >> 5] = ss;
    __syncthreads();
    if (t == 0) {
        float tot = 0.f;
        for (int i = 0; i < 8; i++) tot += wr[i];
        rinv = rsqrtf(tot / (float)N + EPS_);
    }
    __syncthreads();
    float r = rinv;
    for (int i = t; i < N; i += 256) xp[i] = xp[i] * r * w[i];
}

// ---------------- q per-head norm + RoPE + hi/lo split ---------------------
__global__ void k_qproc2(const float* __restrict__ q,
                         const float* __restrict__ cb, const float* __restrict__ sbn,
                         __nv_bfloat16* __restrict__ qhi, __nv_bfloat16* __restrict__ qlo) {
    int s = blockIdx.x >> 4;
    int h = blockIdx.x & 15;
    int t = threadIdx.x;   // 256
    const float* qp = q + ((size_t)s * H_ + h) * D_;
    float v = qp[t];
    float ss = v * v;
#pragma unroll
    for (int o = 16; o; o >>= 1) ss += __shfl_xor_sync(0xffffffffu, ss, o);
    __shared__ float wr[8];
    __shared__ float rinv;
    __shared__ float buf[D_];
    if ((t & 31) == 0) wr[t >> 5] = ss;
    __syncthreads();
    if (t == 0) {
        float tot = 0.f;
        for (int i = 0; i < 8; i++) tot += wr[i];
        rinv = rsqrtf(tot / 256.f + EPS_);
    }
    __syncthreads();
    buf[t] = v * rinv;
    __syncthreads();
    if (t < 32) {
        float c = cb[s*32 + t], sn = sbn[s*32 + t];
        float x1 = buf[NOPE_ + 2*t], x2 = buf[NOPE_ + 2*t + 1];
        buf[NOPE_ + 2*t]     = x1 * c - x2 * sn;
        buf[NOPE_ + 2*t + 1] = x1 * sn + x2 * c;
    }
    __syncthreads();
    float f = buf[t];
    __nv_bfloat16 hi = __float2bfloat16(f);
    size_t idx = ((size_t)s * H_ + h) * D_ + t;
    qhi[idx] = hi;
    qlo[idx] = __float2bfloat16(f - __bfloat162float(hi));
}

// ---------------- kv rmsnorm + RoPE + hi/lo split --------------------------
__global__ void k_kvproc2(const float* __restrict__ kv, const float* __restrict__ w,
                          const float* __restrict__ cb, const float* __restrict__ sbn,
                          __nv_bfloat16* __restrict__ kvhi, __nv_bfloat16* __restrict__ kvlo) {
    int s = blockIdx.x, t = threadIdx.x;   // 256
    const float* p = kv + (size_t)s * D_;
    float v = p[t];
    float ss = v * v;
#pragma unroll
    for (int o = 16; o; o >>= 1) ss += __shfl_xor_sync(0xffffffffu, ss, o);
    __shared__ float wr[8];
    __shared__ float rinv;
    __shared__ float buf[D_];
    if ((t & 31) == 0) wr[t >> 5] = ss;
    __syncthreads();
    if (t == 0) {
        float tot = 0.f;
        for (int i = 0; i < 8; i++) tot += wr[i];
        rinv = rsqrtf(tot / 256.f + EPS_);
    }
    __syncthreads();
    buf[t] = v * rinv * w[t];
    __syncthreads();
    if (t < 32) {
        float c = cb[s*32 + t], sn = sbn[s*32 + t];
        float x1 = buf[NOPE_ + 2*t], x2 = buf[NOPE_ + 2*t + 1];
        buf[NOPE_ + 2*t]     = x1 * c - x2 * sn;
        buf[NOPE_ + 2*t + 1] = x1 * sn + x2 * c;
    }
    __syncthreads();
    float f = buf[t];
    __nv_bfloat16 hi = __float2bfloat16(f);
    size_t idx = (size_t)s * D_ + t;
    kvhi[idx] = hi;
    kvlo[idx] = __float2bfloat16(f - __bfloat162float(hi));
}

// ================ HMMA flash attention v4 (causal, sink) ===================
// Pre-split bf16 Q/KV inputs, cp.async double-buffered KV tiles.
// 64 q-rows x 64 k-rows per CTA, 256 threads (8 warps: 4m x 2n).
#define AQHI 0u
#define AQLO 32768u
#define AKV0 65536u          // buf b at AKV0 + b*65536; hi +0, lo +32768
#define APS  196608u
#define APHI 212992u
#define APLO 221184u
#define ACS  229376u
#define AOS  229504u
#define ATTN4_SMEM (229632u + 512u)

__global__ void __launch_bounds__(256)
k_attn4(const __nv_bfloat16* __restrict__ qhi, const __nv_bfloat16* __restrict__ qlo,
        const __nv_bfloat16* __restrict__ kvhi, const __nv_bfloat16* __restrict__ kvlo,
        const float* __restrict__ sink, float* __restrict__ o) {
    extern __shared__ char smraw[];
    uint32_t sb_raw = smem_u32(smraw);
    uint32_t sb = (sb_raw + 511) & ~511u;
    char* sm = smraw + (sb - sb_raw);

    int bid = blockIdx.x;
    int qb = 31 - (bid >> 4);     // longest first
    int h  = bid & 15;
    int t = threadIdx.x, lane = t & 31, wid = t >> 5;
    int wm = wid & 3, wn = wid >> 2;

    // per-thread load pattern: 8 chunks of 16B over a 64x256 bf16 tile
    uint32_t dsw[8];
    int      ksrc[8];
#pragma unroll
    for (int i = 0; i < 8; i++) {
        int idx = t + i * 256;
        int rr = idx >> 5, uu = idx & 31;
        uint32_t off = (uint32_t)(rr*512 + uu*16);
        dsw[i]  = off ^ ((uint32_t)(rr & 7) << 4);
        ksrc[i] = rr*256 + uu*8;
    }

#define LOADKV(kt, buf) do {                                                  \
        const __nv_bfloat16* ph = kvhi + (size_t)(kt)*64*256;                 \
        const __nv_bfloat16* pl = kvlo + (size_t)(kt)*64*256;                 \
        uint32_t base = sb + AKV0 + (uint32_t)(buf)*65536u;                   \
        _Pragma("unroll")                                                     \
        for (int i = 0; i < 8; i++) {                                         \
            cp_async16(base + dsw[i],          ph + ksrc[i]);                 \
            cp_async16(base + 32768u + dsw[i], pl + ksrc[i]);                 \
        }                                                                     \
    } while (0)

    // issue Q tile + KV tile 0
#pragma unroll
    for (int i = 0; i < 8; i++) {
        int idx = t + i * 256;
        int rr = idx >> 5, uu = idx & 31;
        size_t qsrc = ((size_t)(qb*64 + rr) * H_ + h) * D_ + uu*8;
        cp_async16(sb + AQHI + dsw[i], qhi + qsrc);
        cp_async16(sb + AQLO + dsw[i], qlo + qsrc);
    }
    LOADKV(0, 0);
    CP_COMMIT();

    // ---- fragment address precomputes ----
    uint32_t a_pre;
    { int row = wm*16 + (lane & 15);
      a_pre = (uint32_t)(row*512) ^ ((uint32_t)(lane >> 4) << 4)
            ^ ((uint32_t)(lane & 7) << 4); }
    uint32_t b_pre[2];
#pragma unroll
    for (int jp = 0; jp < 2; jp++) {
        int row = wn*32 + jp*16 + ((lane >> 4) << 3) + (lane & 7);
        b_pre[jp] = (uint32_t)(row*512) ^ (((uint32_t)(lane >> 3) & 1u) << 4)
                  ^ ((uint32_t)(lane & 7) << 4);
    }
    uint32_t pa_pre;
    { int row = wm*16 + (lane & 15);
      pa_pre = (uint32_t)(row*128) ^ ((uint32_t)(lane >> 4) << 4)
             ^ ((uint32_t)(lane & 7) << 4); }
    uint32_t pv_pre;
    { int mi = lane >> 3;
      pv_pre = (uint32_t)((((mi & 1)*8 + (lane & 7)) * 512) + wn*256)
             ^ ((uint32_t)(mi >> 1) << 4) ^ ((uint32_t)(lane & 7) << 4); }

    float cpv[16][4];
#pragma unroll
    for (int j = 0; j < 16; j++)
#pragma unroll
        for (int k = 0; k < 4; k++) cpv[j][k] = 0.f;

    float m_ = -1e30f, l_ = 0.f;
    int srow = t >> 2, sc = t & 3;
    int rm_lo = wm*16 + (lane >> 2);

#define SCORE_PASS(QB, KB) do {                                               \
    _Pragma("unroll")                                                         \
    for (int ks = 0; ks < 16; ++ks) {                                         \
        uint32_t a4[4];                                                       \
        ldsm4(a4[0], a4[1], a4[2], a4[3],                                     \
              sb + (QB) + (a_pre ^ ((uint32_t)ks << 5)));                     \
        _Pragma("unroll")                                                     \
        for (int jp = 0; jp < 2; jp++) {                                      \
            uint32_t r0, r1, r2, r3;                                          \
            ldsm4(r0, r1, r2, r3,                                             \
                  sb + (KB) + (b_pre[jp] ^ ((uint32_t)ks << 5)));             \
            uint32_t bA[2] = {r0, r1}, bB[2] = {r2, r3};                      \
            mma_bf16(c[jp*2],   a4, bA);                                      \
            mma_bf16(c[jp*2+1], a4, bB);                                      \
        }                                                                     \
    }                                                                         \
} while (0)

#define PV_PASS(PB, KB) do {                                                  \
    _Pragma("unroll")                                                         \
    for (int ks = 0; ks < 4; ++ks) {                                          \
        uint32_t a4[4];                                                       \
        ldsm4(a4[0], a4[1], a4[2], a4[3],                                     \
              sb + (PB) + (pa_pre ^ ((uint32_t)ks << 5)));                    \
        _Pragma("unroll")                                                     \
        for (int jn = 0; jn < 16; jn += 2) {                                  \
            uint32_t r0, r1, r2, r3;                                          \
            ldsm4t(r0, r1, r2, r3,                                            \
                   sb + (KB) + (uint32_t)(ks*8192) + (pv_pre ^ ((uint32_t)jn << 4))); \
            uint32_t bA[2] = {r0, r1}, bB[2] = {r2, r3};                      \
            mma_bf16(cpv[jn],   a4, bA);                                      \
            mma_bf16(cpv[jn+1], a4, bB);                                      \
        }                                                                     \
    }                                                                         \
} while (0)

    CP_WAIT0();
    __syncthreads();

    for (int kt = 0; kt <= qb; ++kt) {
        int buf = kt & 1;
        if (kt < qb) { LOADKV(kt + 1, buf ^ 1); CP_COMMIT(); }
        uint32_t KHI = AKV0 + (uint32_t)buf * 65536u;
        uint32_t KLO = KHI + 32768u;

        // ---- scores: 3-pass hi/lo HMMA ----
        float c[4][4];
#pragma unroll
        for (int j = 0; j < 4; j++)
#pragma unroll
            for (int k = 0; k < 4; k++) c[j][k] = 0.f;
        SCORE_PASS(AQHI, KHI);
        SCORE_PASS(AQLO, KHI);
        SCORE_PASS(AQHI, KLO);

        // ---- score epilogue: scale + causal mask -> PS ----
#pragma unroll
        for (int n8 = 0; n8 < 4; n8++) {
            int col  = wn*32 + n8*8 + (lane & 3)*2;
            int gcol = kt*64 + col;
#pragma unroll
            for (int hf = 0; hf < 2; hf++) {
                int row  = wm*16 + (lane >> 2) + hf*8;
                int grow = qb*64 + row;
                float v0 = c[n8][hf*2]   * SCALE_;
                float v1 = c[n8][hf*2+1] * SCALE_;
                if (gcol     > grow) v0 = -1e30f;
                if (gcol + 1 > grow) v1 = -1e30f;
                uint32_t off = (uint32_t)(row*256 + col*4)
                             ^ ((uint32_t)(row & 7) << 5);
                *(float2*)(sm + APS + off) = make_float2(v0, v1);
            }
        }
        __syncthreads();

        // ---- online softmax: 4 threads per row, 16 cols each ----
        float sv[16];
#pragma unroll
        for (int jj = 0; jj < 4; jj++) {
            uint32_t off = (uint32_t)(srow*256 + sc*64 + jj*16)
                         ^ ((uint32_t)(srow & 7) << 5);
            *(float4*)&sv[jj*4] = *(const float4*)(sm + APS + off);
        }
        float tmax = sv[0];
#pragma unroll
        for (int j = 1; j < 16; j++) tmax = fmaxf(tmax, sv[j]);
        tmax = fmaxf(tmax, __shfl_xor_sync(0xffffffffu, tmax, 1));
        tmax = fmaxf(tmax, __shfl_xor_sync(0xffffffffu, tmax, 2));
        float nm = fmaxf(m_, tmax);
        float cs = __expf(m_ - nm);
        float ps = 0.f;
        uint32_t hw[8], lw[8];
#pragma unroll
        for (int j = 0; j < 8; j++) {
            float p0 = __expf(sv[2*j]   - nm);
            float p1 = __expf(sv[2*j+1] - nm);
            ps += p0 + p1;
            __nv_bfloat16 h0 = __float2bfloat16(p0), h1 = __float2bfloat16(p1);
            float l0 = p0 - __bfloat162float(h0), l1 = p1 - __bfloat162float(h1);
            __nv_bfloat162 hh; hh.x = h0; hh.y = h1;
            __nv_bfloat162 ll; ll.x = __float2bfloat16(l0); ll.y = __float2bfloat16(l1);
            hw[j] = *(uint32_t*)&hh; lw[j] = *(uint32_t*)&ll;
        }
        ps += __shfl_xor_sync(0xffffffffu, ps, 1);
        ps += __shfl_xor_sync(0xffffffffu, ps, 2);
        l_ = l_ * cs + ps;
        m_ = nm;
        uint32_t po0 = (uint32_t)(srow*128) ^ ((uint32_t)sc << 5)
                     ^ ((uint32_t)(srow & 7) << 4);
        uint32_t po1 = po0 ^ 16u;
        *(uint4*)(sm + APHI + po0) = make_uint4(hw[0], hw[1], hw[2], hw[3]);
        *(uint4*)(sm + APHI + po1) = make_uint4(hw[4], hw[5], hw[6], hw[7]);
        *(uint4*)(sm + APLO + po0) = make_uint4(lw[0], lw[1], lw[2], lw[3]);
        *(uint4*)(sm + APLO + po1) = make_uint4(lw[4], lw[5], lw[6], lw[7]);
        if (sc == 0) *(float*)(sm + ACS + srow*4) = cs;
        __syncthreads();

        // ---- rescale accumulators + PV (3-pass) ----
        float cs_lo = *(const float*)(sm + ACS + rm_lo*4);
        float cs_hi = *(const float*)(sm + ACS + (rm_lo + 8)*4);
#pragma unroll
        for (int jn = 0; jn < 16; jn++) {
            cpv[jn][0] *= cs_lo; cpv[jn][1] *= cs_lo;
            cpv[jn][2] *= cs_hi; cpv[jn][3] *= cs_hi;
        }
        PV_PASS(APHI, KHI);
        PV_PASS(APLO, KHI);
        PV_PASS(APHI, KLO);

        if (kt < qb) CP_WAIT0();
        __syncthreads();
    }

    // ---- fold sink, output scale ----
    if (sc == 0) {
        float sk = sink[h];
        float mf = fmaxf(m_, sk);
        float cf = __expf(m_ - mf);
        float den = l_ * cf + __expf(sk - mf);
        *(float*)(sm + AOS + srow*4) = cf / den;
    }
    __syncthreads();
    float os_lo = *(const float*)(sm + AOS + rm_lo*4);
    float os_hi = *(const float*)(sm + AOS + (rm_lo + 8)*4);
    int s_lo = qb*64 + rm_lo;
#pragma unroll
    for (int jn = 0; jn < 16; jn++) {
        int col = wn*128 + jn*8 + (lane & 3)*2;
        *(float2*)&o[(((size_t)s_lo) * H_ + h) * D_ + col] =
            make_float2(cpv[jn][0]*os_lo, cpv[jn][1]*os_lo);
        *(float2*)&o[(((size_t)(s_lo + 8)) * H_ + h) * D_ + col] =
            make_float2(cpv[jn][2]*os_hi, cpv[jn][3]*os_hi);
    }
#undef SCORE_PASS
#undef PV_PASS
#undef LOADKV
}

// ---------------- fused conj-RoPE + grouped hi/lo split of o ---------------
// grid (2, S, G), 256 threads. Each thread handles 1 col-pair of the group row.
__global__ void k_osplit(const float* __restrict__ o,
                         const float* __restrict__ cb, const float* __restrict__ sbn,
                         __nv_bfloat16* __restrict__ os) {
    int t = threadIdx.x;
    int s = blockIdx.y;
    int g = blockIdx.z;
    int p = blockIdx.x * 256 + t;        // pair index 0..511
    int c0 = p * 2;                      // group col (even)
    int hpg = c0 >> 8;
    int d0  = c0 & 255;
    int hh  = g * (H_/G_) + hpg;
    const float* src = &o[((size_t)s * H_ + hh) * D_ + d0];
    float v0 = src[0], v1 = src[1];
    if (d0 >= NOPE_) {
        int i = (d0 - NOPE_) >> 1;
        float c = cb[s*32 + i], sn = sbn[s*32 + i];
        float n0 =  v0 * c + v1 * sn;    // conj rotation
        float n1 = -v0 * sn + v1 * c;
        v0 = n0; v1 = n1;
    }
    __nv_bfloat16 h0 = __float2bfloat16(v0);
    __nv_bfloat16 h1 = __float2bfloat16(v1);
    __nv_bfloat162 hip; hip.x = h0; hip.y = h1;
    __nv_bfloat162 lop;
    lop.x = __float2bfloat16(v0 - __bfloat162float(h0));
    lop.y = __float2bfloat16(v1 - __bfloat162float(h1));
    __nv_bfloat16* ob = os + (size_t)g * (S_*3*1024) + (size_t)s * 3*1024;
    *(__nv_bfloat162*)(ob + c0)          = hip;   // hi
    *(__nv_bfloat162*)(ob + 1024 + c0)   = lop;   // lo
    *(__nv_bfloat162*)(ob + 2048 + c0)   = hip;   // hi
}

// ---------------- launch ----------------------------------------------------
extern "C" void kernel_launch(void* const* d_in, const int* in_sizes, int n_in,
                              void* d_out, int out_size) {
    const float* x     = (const float*)d_in[0];
    const float* freqs = (const float*)d_in[1];
    const float* wq_a  = (const float*)d_in[2];
    const float* qnw   = (const float*)d_in[3];
    const float* wq_b  = (const float*)d_in[4];
    const float* wkv   = (const float*)d_in[5];
    const float* kvnw  = (const float*)d_in[6];
    const float* wo_a  = (const float*)d_in[7];
    const float* wo_b  = (const float*)d_in[8];
    const float* sink  = (const float*)d_in[9];
    float* out = (float*)d_out;

    float *qa, *q, *kv, *o, *orr, *cb, *sb;
    __nv_bfloat16 *xs, *wqas, *qas, *wqbs, *wkvs, *os, *woas, *ors, *wobs;
    __nv_bfloat16 *qhi, *qlo, *kvhi, *kvlo;
    cudaGetSymbolAddress((void**)&qa,  g_qa);
    cudaGetSymbolAddress((void**)&q,   g_q);
    cudaGetSymbolAddress((void**)&kv,  g_kv);
    cudaGetSymbolAddress((void**)&o,   g_o);
    cudaGetSymbolAddress((void**)&orr, g_or);
    cudaGetSymbolAddress((void**)&cb,  g_cos);
    cudaGetSymbolAddress((void**)&sb,  g_sin);
    cudaGetSymbolAddress((void**)&xs,   g_xs);
    cudaGetSymbolAddress((void**)&wqas, g_wqas);
    cudaGetSymbolAddress((void**)&qas,  g_qas);
    cudaGetSymbolAddress((void**)&wqbs, g_wqbs);
    cudaGetSymbolAddress((void**)&wkvs, g_wkvs);
    cudaGetSymbolAddress((void**)&os,   g_os);
    cudaGetSymbolAddress((void**)&woas, g_woas);
    cudaGetSymbolAddress((void**)&ors,  g_ors);
    cudaGetSymbolAddress((void**)&wobs, g_wobs);
    cudaGetSymbolAddress((void**)&qhi,  g_qhi);
    cudaGetSymbolAddress((void**)&qlo,  g_qlo);
    cudaGetSymbolAddress((void**)&kvhi, g_kvhi);
    cudaGetSymbolAddress((void**)&kvlo, g_kvlo);

    size_t hg_smem = 128 + 2 * 32768;
    cudaFuncSetAttribute(k_hgemm, cudaFuncAttributeMaxDynamicSharedMemorySize,
                         (int)hg_smem);
    cudaFuncSetAttribute(k_attn4, cudaFuncAttributeMaxDynamicSharedMemorySize,
                         (int)ATTN4_SMEM);

    k_cossin<<<(S_*32 + 255)/256, 256>>>(freqs, cb, sb);

    // ---- splits for stage-1 GEMMs ----
    k_split<<<dim3(HID_/256, S_),   256>>>(x,    xs,   HID_, HID_, 0, 0, 0);
    k_split<<<dim3(HID_/256, QL_),  256>>>(wq_a, wqas, HID_, HID_, 0, 0, 1);
    k_split<<<dim3(HID_/256, D_),   256>>>(wkv,  wkvs, HID_, HID_, 0, 0, 1);

    // qa = x @ wq_a^T   [2048,1024], K3=6144
    k_hgemm<<<dim3(QL_/128, S_/128), 256, hg_smem>>>(xs, wqas, qa,
                                                     3*HID_, QL_, 0, 0, 0);
    k_rmsrow<<<S_, 256>>>(qa, qnw, QL_);
    k_split<<<dim3(QL_/256, S_),    256>>>(qa,   qas,  QL_, QL_, 0, 0, 0);
    k_split<<<dim3(QL_/256, H_*D_), 256>>>(wq_b, wqbs, QL_, QL_, 0, 0, 1);
    // q = qa @ wq_b^T   [2048,4096], K3=3072
    k_hgemm<<<dim3(H_*D_/128, S_/128), 256, hg_smem>>>(qas, wqbs, q,
                                                       3*QL_, H_*D_, 0, 0, 0);
    // kv = x @ wkv^T    [2048,256], K3=6144
    k_hgemm<<<dim3(D_/128, S_/128), 256, hg_smem>>>(xs, wkvs, kv,
                                                    3*HID_, D_, 0, 0, 0);
    // norm + rope + hi/lo pre-split for attention
    k_kvproc2<<<S_, 256>>>(kv, kvnw, cb, sb, kvhi, kvlo);
    k_qproc2<<<S_*H_, 256>>>(q, cb, sb, qhi, qlo);

    // attention: 32 q-tiles of 64 rows x 16 heads
    k_attn4<<<dim3(32*16), 256, ATTN4_SMEM>>>(qhi, qlo, kvhi, kvlo, sink, o);

    // fused conj-rope + grouped split of o
    k_osplit<<<dim3(2, S_, G_), 256>>>(o, cb, sb, os);
    k_split<<<dim3(1024/256, G_*OR_), 256>>>(wo_a, woas, 1024, 1024, 0, 0, 1);
    // o_r[g] = o_g @ wo_a[g]^T : batched, [2048,512] per group, K3=3072
    k_hgemm<<<dim3(OR_/128, S_/128, G_), 256, hg_smem>>>(
        os, woas, orr, 3*1024, G_*OR_,
        (size_t)S_*3*1024, (size_t)OR_*3*1024, OR_);

    k_split<<<dim3((G_*OR_)/256, S_),  256>>>(orr,  ors,  G_*OR_, G_*OR_, 0, 0, 0);
    k_split<<<dim3((G_*OR_)/256, HID_), 256>>>(wo_b, wobs, G_*OR_, G_*OR_, 0, 0, 1);
    // out = o_r @ wo_b^T  [2048,2048], K3=6144
    k_hgemm<<<dim3(HID_/128, S_/128), 256, hg_smem>>>(ors, wobs, out,
                                                      3*(G_*OR_), HID_, 0, 0, 0);
}

// round 15
// speedup vs baseline: 9.1896x; 1.1310x over previous
#include <cuda_runtime.h>
#include <cuda_bf16.h>
#include <cuda_fp16.h>
#include <math.h>
#include <stdint.h>

#define S_    2048
#define HID_  2048
#define H_    16
#define D_    256
#define R_    64
#define NOPE_ 192
#define QL_   1024
#define OR_   512
#define G_    4
#define EPS_  1e-6f
#define SCALE_ 0.0625f   // 256^-0.5

// ---------------- scratch (static device arrays; no allocs allowed) -------
__device__ float g_qa [S_*QL_];
__device__ float g_q  [S_*H_*D_];
__device__ float g_kv [S_*D_];
__device__ float g_o  [S_*H_*D_];
__device__ float g_cos[S_*(R_/2)];
__device__ float g_sin[S_*(R_/2)];
// bf16 3-term split operands (K tripled) for GEMMs
__device__ __nv_bfloat16 g_xs   [S_*3*HID_];
__device__ __nv_bfloat16 g_wqas [QL_*3*HID_];
__device__ __nv_bfloat16 g_qas  [S_*3*QL_];
__device__ __nv_bfloat16 g_wqbs [H_*D_*3*QL_];
__device__ __nv_bfloat16 g_wkvs [D_*3*HID_];
__device__ __nv_bfloat16 g_os   [G_*S_*3*1024];
__device__ __nv_bfloat16 g_woas [G_*OR_*3*1024];
__device__ __nv_bfloat16 g_ors  [S_*3*(G_*OR_)];
__device__ __nv_bfloat16 g_wobs [HID_*3*(G_*OR_)];
// attention fp16 hi/lo operands (pre-split once)
__device__ __half g_qhi [S_*H_*D_];
__device__ __half g_qlo [S_*H_*D_];
__device__ __half g_kvhi[S_*D_];
__device__ __half g_kvlo[S_*D_];

// ---------------- small PTX helpers ----------------------------------------
__device__ __forceinline__ uint32_t smem_u32(const void* p) {
    uint32_t a;
    asm("{ .reg .u64 t; cvta.to.shared.u64 t, %1; cvt.u32.u64 %0, t; }"
        : "=r"(a) : "l"(p));
    return a;
}
__device__ __forceinline__ void cp_async16(uint32_t saddr, const void* gaddr) {
    asm volatile("cp.async.cg.shared.global [%0], [%1], 16;"
                 :: "r"(saddr), "l"(gaddr));
}
#define CP_COMMIT() asm volatile("cp.async.commit_group;" ::: "memory")
#define CP_WAIT1()  asm volatile("cp.async.wait_group 1;" ::: "memory")
#define CP_WAIT0()  asm volatile("cp.async.wait_group 0;" ::: "memory")

__device__ __forceinline__ void ldsm4(uint32_t& r0, uint32_t& r1,
                                      uint32_t& r2, uint32_t& r3, uint32_t a) {
    asm volatile("ldmatrix.sync.aligned.m8n8.x4.shared.b16 {%0,%1,%2,%3}, [%4];"
                 : "=r"(r0), "=r"(r1), "=r"(r2), "=r"(r3) : "r"(a));
}
__device__ __forceinline__ void ldsm4t(uint32_t& r0, uint32_t& r1,
                                       uint32_t& r2, uint32_t& r3, uint32_t a) {
    asm volatile("ldmatrix.sync.aligned.m8n8.x4.trans.shared.b16 {%0,%1,%2,%3}, [%4];"
                 : "=r"(r0), "=r"(r1), "=r"(r2), "=r"(r3) : "r"(a));
}
__device__ __forceinline__ void mma_bf16(float* d, const uint32_t* a,
                                         const uint32_t* b) {
    asm volatile("mma.sync.aligned.m16n8k16.row.col.f32.bf16.bf16.f32 "
                 "{%0,%1,%2,%3}, {%4,%5,%6,%7}, {%8,%9}, {%0,%1,%2,%3};"
                 : "+f"(d[0]), "+f"(d[1]), "+f"(d[2]), "+f"(d[3])
                 : "r"(a[0]), "r"(a[1]), "r"(a[2]), "r"(a[3]),
                   "r"(b[0]), "r"(b[1]));
}
__device__ __forceinline__ void mma_f16(float* d, const uint32_t* a,
                                        const uint32_t* b) {
    asm volatile("mma.sync.aligned.m16n8k16.row.col.f32.f16.f16.f32 "
                 "{%0,%1,%2,%3}, {%4,%5,%6,%7}, {%8,%9}, {%0,%1,%2,%3};"
                 : "+f"(d[0]), "+f"(d[1]), "+f"(d[2]), "+f"(d[3])
                 : "r"(a[0]), "r"(a[1]), "r"(a[2]), "r"(a[3]),
                   "r"(b[0]), "r"(b[1]));
}

// ---------------- cos/sin precompute --------------------------------------
__global__ void k_cossin(const float* __restrict__ f,
                         float* __restrict__ c, float* __restrict__ s) {
    int i = blockIdx.x * 256 + threadIdx.x;
    if (i < S_ * (R_/2)) { c[i] = cosf(f[i]); s[i] = sinf(f[i]); }
}

// ---------------- bf16 3-term split ----------------------------------------
__global__ void k_split(const float* __restrict__ in, __nv_bfloat16* __restrict__ out,
                        int K, int in_ld, size_t in_goff, size_t out_gstride, int mode) {
    const float* ip = in + in_goff * blockIdx.z;
    __nv_bfloat16* op = out + out_gstride * blockIdx.z;
    int k = blockIdx.x * 256 + threadIdx.x;
    int row = blockIdx.y;
    float v = ip[(size_t)row * in_ld + k];
    __nv_bfloat16 hi = __float2bfloat16(v);
    __nv_bfloat16 lo = __float2bfloat16(v - __bfloat162float(hi));
    size_t ob = (size_t)row * 3 * K;
    if (mode == 0) {
        op[ob + k] = hi; op[ob + K + k] = lo; op[ob + 2*K + k] = hi;
    } else {
        op[ob + k] = hi; op[ob + K + k] = hi; op[ob + 2*K + k] = lo;
    }
}

// ---------------- fused rmsnorm + A-split (row len 1024) -------------------
__global__ void k_rmsplit(const float* __restrict__ x, const float* __restrict__ w,
                          __nv_bfloat16* __restrict__ out) {
    int row = blockIdx.x, t = threadIdx.x;
    const float* xp = x + (size_t)row * QL_;
    float ss = 0.f;
    float v4[4];
    *(float4*)v4 = *(const float4*)(xp + t*4);
#pragma unroll
    for (int i = 0; i < 4; i++) ss += v4[i]*v4[i];
#pragma unroll
    for (int o = 16; o; o >>= 1) ss += __shfl_xor_sync(0xffffffffu, ss, o);
    __shared__ float wr[8];
    __shared__ float rinv;
    if ((t & 31) == 0) wr[t >> 5] = ss;
    __syncthreads();
    if (t == 0) {
        float tot = 0.f;
        for (int i = 0; i < 8; i++) tot += wr[i];
        rinv = rsqrtf(tot / (float)QL_ + EPS_);
    }
    __syncthreads();
    float r = rinv;
    __nv_bfloat16* op = out + (size_t)row * 3 * QL_;
#pragma unroll
    for (int i = 0; i < 4; i++) {
        int k = t*4 + i;
        float f = v4[i] * r * w[k];
        __nv_bfloat16 hi = __float2bfloat16(f);
        __nv_bfloat16 lo = __float2bfloat16(f - __bfloat162float(hi));
        op[k] = hi; op[QL_ + k] = lo; op[2*QL_ + k] = hi;
    }
}

// ---------------- HMMA bf16 GEMM: C[M,N] = A[M,K3] @ B[N,K3]^T -------------
// If Cs != nullptr: epilogue writes bf16 hi/lo/hi 3-term layout instead of C:
//   Cs[row][3*splitK] with column base blockIdx.z*csoff + bn.
__global__ void __launch_bounds__(256)
k_hgemm(const __nv_bfloat16* __restrict__ A, const __nv_bfloat16* __restrict__ B,
        float* __restrict__ C, int K3, int ldc,
        size_t sA, size_t sB, size_t sC,
        __nv_bfloat16* __restrict__ Cs, int splitK, int csoff) {
    extern __shared__ char smem_raw[];
    uint32_t sb_raw = smem_u32(smem_raw);
    uint32_t sb = (sb_raw + 127) & ~127u;

    A += sA * blockIdx.z; B += sB * blockIdx.z; C += sC * blockIdx.z;
    const int bn = blockIdx.x * 128, bm = blockIdx.y * 128;
    int t = threadIdx.x, lane = t & 31, wid = t >> 5;
    int wm = wid & 3, wn = wid >> 2;

    int r = t >> 1, hh = t & 1;
    const char* Ag = (const char*)(A + (size_t)(bm + r) * K3) + hh * 64;
    const char* Bg = (const char*)(B + (size_t)(bn + r) * K3) + hh * 64;
    uint32_t soff[4];
#pragma unroll
    for (int i = 0; i < 4; i++) {
        uint32_t off = (uint32_t)(r * 128 + hh * 64 + i * 16);
        soff[i] = off ^ ((off >> 3) & 0x70);
    }

#define LOADC(c, buf) do {                                                    \
        const char* ag = Ag + (size_t)(c) * 128;                              \
        const char* bg = Bg + (size_t)(c) * 128;                              \
        uint32_t ab = sb + (buf) * 32768;                                     \
        uint32_t bb = ab + 16384;                                             \
        cp_async16(ab + soff[0], ag);       cp_async16(ab + soff[1], ag + 16);\
        cp_async16(ab + soff[2], ag + 32);  cp_async16(ab + soff[3], ag + 48);\
        cp_async16(bb + soff[0], bg);       cp_async16(bb + soff[1], bg + 16);\
        cp_async16(bb + soff[2], bg + 32);  cp_async16(bb + soff[3], bg + 48);\
    } while (0)

    float d[2][8][4];
#pragma unroll
    for (int i = 0; i < 2; i++)
#pragma unroll
        for (int j = 0; j < 8; j++)
#pragma unroll
            for (int k = 0; k < 4; k++) d[i][j][k] = 0.f;

    const int nch = K3 >> 6;
    LOADC(0, 0);
    CP_COMMIT();

    uint32_t a_off[2];
#pragma unroll
    for (int i = 0; i < 2; i++) {
        uint32_t off = (uint32_t)((wm*32 + i*16 + (lane & 15)) * 128 + (lane >> 4) * 16);
        a_off[i] = off ^ ((off >> 3) & 0x70);
    }
    uint32_t b_off[4];
#pragma unroll
    for (int jp = 0; jp < 4; jp++) {
        uint32_t off = (uint32_t)((wn*64 + jp*16 + ((lane >> 4) << 3) + (lane & 7)) * 128
                                  + ((lane >> 3) & 1) * 16);
        b_off[jp] = off ^ ((off >> 3) & 0x70);
    }

    for (int c = 0; c < nch; ++c) {
        int buf = c & 1;
        if (c + 1 < nch) { LOADC(c + 1, buf ^ 1); CP_COMMIT(); CP_WAIT1(); }
        else             { CP_WAIT0(); }
        __syncthreads();

        uint32_t abase = sb + buf * 32768;
        uint32_t bbase = abase + 16384;
#pragma unroll
        for (int ks = 0; ks < 4; ++ks) {
            uint32_t kb = ks * 32;
            uint32_t a_f[2][4];
#pragma unroll
            for (int i = 0; i < 2; i++)
                ldsm4(a_f[i][0], a_f[i][1], a_f[i][2], a_f[i][3],
                      abase + (a_off[i] ^ kb));
            uint32_t b_f[8][2];
#pragma unroll
            for (int jp = 0; jp < 4; jp++) {
                uint32_t r0, r1, r2, r3;
                ldsm4(r0, r1, r2, r3, bbase + (b_off[jp] ^ kb));
                b_f[jp*2][0] = r0;   b_f[jp*2][1] = r1;
                b_f[jp*2+1][0] = r2; b_f[jp*2+1][1] = r3;
            }
#pragma unroll
            for (int i = 0; i < 2; i++)
#pragma unroll
                for (int j = 0; j < 8; j++)
                    mma_bf16(d[i][j], a_f[i], b_f[j]);
        }
        __syncthreads();
    }

    if (Cs == nullptr) {
#pragma unroll
        for (int i = 0; i < 2; i++) {
            int row0 = bm + wm*32 + i*16 + (lane >> 2);
#pragma unroll
            for (int j = 0; j < 8; j++) {
                int col = bn + wn*64 + j*8 + (lane & 3)*2;
                *(float2*)&C[(size_t)row0 * ldc + col] = make_float2(d[i][j][0], d[i][j][1]);
                *(float2*)&C[(size_t)(row0 + 8) * ldc + col] = make_float2(d[i][j][2], d[i][j][3]);
            }
        }
    } else {
        const size_t ld3 = 3 * (size_t)splitK;
        int csbase = blockIdx.z * csoff;
#pragma unroll
        for (int i = 0; i < 2; i++) {
            int row0 = bm + wm*32 + i*16 + (lane >> 2);
#pragma unroll
            for (int j = 0; j < 8; j++) {
                int colg = csbase + bn + wn*64 + j*8 + (lane & 3)*2;
#pragma unroll
                for (int hf = 0; hf < 2; hf++) {
                    float v0 = d[i][j][hf*2], v1 = d[i][j][hf*2+1];
                    __nv_bfloat16 h0 = __float2bfloat16(v0);
                    __nv_bfloat16 h1 = __float2bfloat16(v1);
                    __nv_bfloat162 hp; hp.x = h0; hp.y = h1;
                    __nv_bfloat162 lp;
                    lp.x = __float2bfloat16(v0 - __bfloat162float(h0));
                    lp.y = __float2bfloat16(v1 - __bfloat162float(h1));
                    __nv_bfloat16* p = Cs + (size_t)(row0 + hf*8) * ld3 + colg;
                    *(__nv_bfloat162*)p             = hp;
                    *(__nv_bfloat162*)(p + splitK)  = lp;
                    *(__nv_bfloat162*)(p + 2*splitK)= hp;
                }
            }
        }
    }
#undef LOADC
}

// ---------------- q per-head norm + RoPE + fp16 hi/lo split ----------------
__global__ void k_qproc2(const float* __restrict__ q,
                         const float* __restrict__ cb, const float* __restrict__ sbn,
                         __half* __restrict__ qhi, __half* __restrict__ qlo) {
    int s = blockIdx.x >> 4;
    int h = blockIdx.x & 15;
    int t = threadIdx.x;   // 256
    const float* qp = q + ((size_t)s * H_ + h) * D_;
    float v = qp[t];
    float ss = v * v;
#pragma unroll
    for (int o = 16; o; o >>= 1) ss += __shfl_xor_sync(0xffffffffu, ss, o);
    __shared__ float wr[8];
    __shared__ float rinv;
    __shared__ float buf[D_];
    if ((t & 31) == 0) wr[t >> 5] = ss;
    __syncthreads();
    if (t == 0) {
        float tot = 0.f;
        for (int i = 0; i < 8; i++) tot += wr[i];
        rinv = rsqrtf(tot / 256.f + EPS_);
    }
    __syncthreads();
    buf[t] = v * rinv;
    __syncthreads();
    if (t < 32) {
        float c = cb[s*32 + t], sn = sbn[s*32 + t];
        float x1 = buf[NOPE_ + 2*t], x2 = buf[NOPE_ + 2*t + 1];
        buf[NOPE_ + 2*t]     = x1 * c - x2 * sn;
        buf[NOPE_ + 2*t + 1] = x1 * sn + x2 * c;
    }
    __syncthreads();
    float f = buf[t];
    __half hi = __float2half(f);
    size_t idx = ((size_t)s * H_ + h) * D_ + t;
    qhi[idx] = hi;
    qlo[idx] = __float2half(f - __half2float(hi));
}

// ---------------- kv rmsnorm + RoPE + fp16 hi/lo split ---------------------
__global__ void k_kvproc2(const float* __restrict__ kv, const float* __restrict__ w,
                          const float* __restrict__ cb, const float* __restrict__ sbn,
                          __half* __restrict__ kvhi, __half* __restrict__ kvlo) {
    int s = blockIdx.x, t = threadIdx.x;   // 256
    const float* p = kv + (size_t)s * D_;
    float v = p[t];
    float ss = v * v;
#pragma unroll
    for (int o = 16; o; o >>= 1) ss += __shfl_xor_sync(0xffffffffu, ss, o);
    __shared__ float wr[8];
    __shared__ float rinv;
    __shared__ float buf[D_];
    if ((t & 31) == 0) wr[t >> 5] = ss;
    __syncthreads();
    if (t == 0) {
        float tot = 0.f;
        for (int i = 0; i < 8; i++) tot += wr[i];
        rinv = rsqrtf(tot / 256.f + EPS_);
    }
    __syncthreads();
    buf[t] = v * rinv * w[t];
    __syncthreads();
    if (t < 32) {
        float c = cb[s*32 + t], sn = sbn[s*32 + t];
        float x1 = buf[NOPE_ + 2*t], x2 = buf[NOPE_ + 2*t + 1];
        buf[NOPE_ + 2*t]     = x1 * c - x2 * sn;
        buf[NOPE_ + 2*t + 1] = x1 * sn + x2 * c;
    }
    __syncthreads();
    float f = buf[t];
    __half hi = __float2half(f);
    size_t idx = (size_t)s * D_ + t;
    kvhi[idx] = hi;
    kvlo[idx] = __float2half(f - __half2float(hi));
}

// ================ HMMA fp16 flash attention v5 (causal, sink) ==============
// 4 MMA passes total: scores = (Qhi+Qlo)*Khi (2), PV = P*(Vhi+Vlo) (2).
// 64 q x 64 k per CTA, 256 threads (4m x 2n warps), cp.async dbl-buffered KV.
#define AQHI 0u
#define AQLO 32768u
#define AKV0 65536u          // buf b at AKV0 + b*65536; hi +0, lo +32768
#define APS  196608u
#define APHI 212992u
#define ACS  221184u
#define AOS  221440u
#define ATTN5_SMEM (221696u + 512u)

__global__ void __launch_bounds__(256)
k_attn5(const __half* __restrict__ qhi, const __half* __restrict__ qlo,
        const __half* __restrict__ kvhi, const __half* __restrict__ kvlo,
        const float* __restrict__ sink, float* __restrict__ o) {
    extern __shared__ char smraw[];
    uint32_t sb_raw = smem_u32(smraw);
    uint32_t sb = (sb_raw + 511) & ~511u;
    char* sm = smraw + (sb - sb_raw);

    int bid = blockIdx.x;
    int qb = 31 - (bid >> 4);     // longest first
    int h  = bid & 15;
    int t = threadIdx.x, lane = t & 31, wid = t >> 5;
    int wm = wid & 3, wn = wid >> 2;

    uint32_t dsw[8];
    int      ksrc[8];
#pragma unroll
    for (int i = 0; i < 8; i++) {
        int idx = t + i * 256;
        int rr = idx >> 5, uu = idx & 31;
        uint32_t off = (uint32_t)(rr*512 + uu*16);
        dsw[i]  = off ^ ((uint32_t)(rr & 7) << 4);
        ksrc[i] = rr*256 + uu*8;
    }

#define LOADKV(kt, buf) do {                                                  \
        const __half* ph = kvhi + (size_t)(kt)*64*256;                        \
        const __half* pl = kvlo + (size_t)(kt)*64*256;                        \
        uint32_t base = sb + AKV0 + (uint32_t)(buf)*65536u;                   \
        _Pragma("unroll")                                                     \
        for (int i = 0; i < 8; i++) {                                         \
            cp_async16(base + dsw[i],          ph + ksrc[i]);                 \
            cp_async16(base + 32768u + dsw[i], pl + ksrc[i]);                 \
        }                                                                     \
    } while (0)

#pragma unroll
    for (int i = 0; i < 8; i++) {
        int idx = t + i * 256;
        int rr = idx >> 5, uu = idx & 31;
        size_t qsrc = ((size_t)(qb*64 + rr) * H_ + h) * D_ + uu*8;
        cp_async16(sb + AQHI + dsw[i], qhi + qsrc);
        cp_async16(sb + AQLO + dsw[i], qlo + qsrc);
    }
    LOADKV(0, 0);
    CP_COMMIT();

    uint32_t a_pre;
    { int row = wm*16 + (lane & 15);
      a_pre = (uint32_t)(row*512) ^ ((uint32_t)(lane >> 4) << 4)
            ^ ((uint32_t)(lane & 7) << 4); }
    uint32_t b_pre[2];
#pragma unroll
    for (int jp = 0; jp < 2; jp++) {
        int row = wn*32 + jp*16 + ((lane >> 4) << 3) + (lane & 7);
        b_pre[jp] = (uint32_t)(row*512) ^ (((uint32_t)(lane >> 3) & 1u) << 4)
                  ^ ((uint32_t)(lane & 7) << 4);
    }
    uint32_t pa_pre;
    { int row = wm*16 + (lane & 15);
      pa_pre = (uint32_t)(row*128) ^ ((uint32_t)(lane >> 4) << 4)
             ^ ((uint32_t)(lane & 7) << 4); }
    uint32_t pv_pre;
    { int mi = lane >> 3;
      pv_pre = (uint32_t)((((mi & 1)*8 + (lane & 7)) * 512) + wn*256)
             ^ ((uint32_t)(mi >> 1) << 4) ^ ((uint32_t)(lane & 7) << 4); }

    float cpv[16][4];
#pragma unroll
    for (int j = 0; j < 16; j++)
#pragma unroll
        for (int k = 0; k < 4; k++) cpv[j][k] = 0.f;

    float m_ = -1e30f, l_ = 0.f;
    int srow = t >> 2, sc = t & 3;
    int rm_lo = wm*16 + (lane >> 2);

    CP_WAIT0();
    __syncthreads();

    for (int kt = 0; kt <= qb; ++kt) {
        int buf = kt & 1;
        if (kt < qb) { LOADKV(kt + 1, buf ^ 1); CP_COMMIT(); }
        uint32_t KHI = AKV0 + (uint32_t)buf * 65536u;
        uint32_t KLO = KHI + 32768u;

        // ---- scores: (Qhi + Qlo) * Khi, shared B fragments ----
        float c[4][4];
#pragma unroll
        for (int j = 0; j < 4; j++)
#pragma unroll
            for (int k = 0; k < 4; k++) c[j][k] = 0.f;
#pragma unroll
        for (int ks = 0; ks < 16; ++ks) {
            uint32_t ahi[4], alo[4];
            ldsm4(ahi[0], ahi[1], ahi[2], ahi[3],
                  sb + AQHI + (a_pre ^ ((uint32_t)ks << 5)));
            ldsm4(alo[0], alo[1], alo[2], alo[3],
                  sb + AQLO + (a_pre ^ ((uint32_t)ks << 5)));
#pragma unroll
            for (int jp = 0; jp < 2; jp++) {
                uint32_t r0, r1, r2, r3;
                ldsm4(r0, r1, r2, r3,
                      sb + KHI + (b_pre[jp] ^ ((uint32_t)ks << 5)));
                uint32_t bA[2] = {r0, r1}, bB[2] = {r2, r3};
                mma_f16(c[jp*2],   ahi, bA);
                mma_f16(c[jp*2+1], ahi, bB);
                mma_f16(c[jp*2],   alo, bA);
                mma_f16(c[jp*2+1], alo, bB);
            }
        }

        // ---- score epilogue: scale + causal mask -> PS ----
#pragma unroll
        for (int n8 = 0; n8 < 4; n8++) {
            int col  = wn*32 + n8*8 + (lane & 3)*2;
            int gcol = kt*64 + col;
#pragma unroll
            for (int hf = 0; hf < 2; hf++) {
                int row  = wm*16 + (lane >> 2) + hf*8;
                int grow = qb*64 + row;
                float v0 = c[n8][hf*2]   * SCALE_;
                float v1 = c[n8][hf*2+1] * SCALE_;
                if (gcol     > grow) v0 = -1e30f;
                if (gcol + 1 > grow) v1 = -1e30f;
                uint32_t off = (uint32_t)(row*256 + col*4)
                             ^ ((uint32_t)(row & 7) << 5);
                *(float2*)(sm + APS + off) = make_float2(v0, v1);
            }
        }
        __syncthreads();

        // ---- online softmax: 4 threads per row, 16 cols each ----
        float sv[16];
#pragma unroll
        for (int jj = 0; jj < 4; jj++) {
            uint32_t off = (uint32_t)(srow*256 + sc*64 + jj*16)
                         ^ ((uint32_t)(srow & 7) << 5);
            *(float4*)&sv[jj*4] = *(const float4*)(sm + APS + off);
        }
        float tmax = sv[0];
#pragma unroll
        for (int j = 1; j < 16; j++) tmax = fmaxf(tmax, sv[j]);
        tmax = fmaxf(tmax, __shfl_xor_sync(0xffffffffu, tmax, 1));
        tmax = fmaxf(tmax, __shfl_xor_sync(0xffffffffu, tmax, 2));
        float nm = fmaxf(m_, tmax);
        float cs = __expf(m_ - nm);
        float ps = 0.f;
        uint32_t hw[8];
#pragma unroll
        for (int j = 0; j < 8; j++) {
            float p0 = __expf(sv[2*j]   - nm);
            float p1 = __expf(sv[2*j+1] - nm);
            ps += p0 + p1;
            __half2 hh = __floats2half2_rn(p0, p1);
            hw[j] = *(uint32_t*)&hh;
        }
        ps += __shfl_xor_sync(0xffffffffu, ps, 1);
        ps += __shfl_xor_sync(0xffffffffu, ps, 2);
        l_ = l_ * cs + ps;
        m_ = nm;
        uint32_t po0 = (uint32_t)(srow*128) ^ ((uint32_t)sc << 5)
                     ^ ((uint32_t)(srow & 7) << 4);
        uint32_t po1 = po0 ^ 16u;
        *(uint4*)(sm + APHI + po0) = make_uint4(hw[0], hw[1], hw[2], hw[3]);
        *(uint4*)(sm + APHI + po1) = make_uint4(hw[4], hw[5], hw[6], hw[7]);
        if (sc == 0) *(float*)(sm + ACS + srow*4) = cs;
        __syncthreads();

        // ---- rescale accumulators + PV: P * (Vhi + Vlo), shared A frags ----
        float cs_lo = *(const float*)(sm + ACS + rm_lo*4);
        float cs_hi = *(const float*)(sm + ACS + (rm_lo + 8)*4);
#pragma unroll
        for (int jn = 0; jn < 16; jn++) {
            cpv[jn][0] *= cs_lo; cpv[jn][1] *= cs_lo;
            cpv[jn][2] *= cs_hi; cpv[jn][3] *= cs_hi;
        }
#pragma unroll
        for (int ks = 0; ks < 4; ++ks) {
            uint32_t a4[4];
            ldsm4(a4[0], a4[1], a4[2], a4[3],
                  sb + APHI + (pa_pre ^ ((uint32_t)ks << 5)));
#pragma unroll
            for (int jn = 0; jn < 16; jn += 2) {
                uint32_t r0, r1, r2, r3;
                ldsm4t(r0, r1, r2, r3,
                       sb + KHI + (uint32_t)(ks*8192) + (pv_pre ^ ((uint32_t)jn << 4)));
                uint32_t bA[2] = {r0, r1}, bB[2] = {r2, r3};
                mma_f16(cpv[jn],   a4, bA);
                mma_f16(cpv[jn+1], a4, bB);
                ldsm4t(r0, r1, r2, r3,
                       sb + KLO + (uint32_t)(ks*8192) + (pv_pre ^ ((uint32_t)jn << 4)));
                uint32_t cA[2] = {r0, r1}, cB[2] = {r2, r3};
                mma_f16(cpv[jn],   a4, cA);
                mma_f16(cpv[jn+1], a4, cB);
            }
        }

        if (kt < qb) CP_WAIT0();
        __syncthreads();
    }

    // ---- fold sink, output scale ----
    if (sc == 0) {
        float sk = sink[h];
        float mf = fmaxf(m_, sk);
        float cf = __expf(m_ - mf);
        float den = l_ * cf + __expf(sk - mf);
        *(float*)(sm + AOS + srow*4) = cf / den;
    }
    __syncthreads();
    float os_lo = *(const float*)(sm + AOS + rm_lo*4);
    float os_hi = *(const float*)(sm + AOS + (rm_lo + 8)*4);
    int s_lo = qb*64 + rm_lo;
#pragma unroll
    for (int jn = 0; jn < 16; jn++) {
        int col = wn*128 + jn*8 + (lane & 3)*2;
        *(float2*)&o[(((size_t)s_lo) * H_ + h) * D_ + col] =
            make_float2(cpv[jn][0]*os_lo, cpv[jn][1]*os_lo);
        *(float2*)&o[(((size_t)(s_lo + 8)) * H_ + h) * D_ + col] =
            make_float2(cpv[jn][2]*os_hi, cpv[jn][3]*os_hi);
    }
#undef LOADKV
}

// ---------------- fused conj-RoPE + grouped hi/lo split of o ---------------
__global__ void k_osplit(const float* __restrict__ o,
                         const float* __restrict__ cb, const float* __restrict__ sbn,
                         __nv_bfloat16* __restrict__ os) {
    int t = threadIdx.x;
    int s = blockIdx.y;
    int g = blockIdx.z;
    int p = blockIdx.x * 256 + t;        // pair index 0..511
    int c0 = p * 2;                      // group col (even)
    int hpg = c0 >> 8;
    int d0  = c0 & 255;
    int hh  = g * (H_/G_) + hpg;
    const float* src = &o[((size_t)s * H_ + hh) * D_ + d0];
    float v0 = src[0], v1 = src[1];
    if (d0 >= NOPE_) {
        int i = (d0 - NOPE_) >> 1;
        float c = cb[s*32 + i], sn = sbn[s*32 + i];
        float n0 =  v0 * c + v1 * sn;    // conj rotation
        float n1 = -v0 * sn + v1 * c;
        v0 = n0; v1 = n1;
    }
    __nv_bfloat16 h0 = __float2bfloat16(v0);
    __nv_bfloat16 h1 = __float2bfloat16(v1);
    __nv_bfloat162 hip; hip.x = h0; hip.y = h1;
    __nv_bfloat162 lop;
    lop.x = __float2bfloat16(v0 - __bfloat162float(h0));
    lop.y = __float2bfloat16(v1 - __bfloat162float(h1));
    __nv_bfloat16* ob = os + (size_t)g * (S_*3*1024) + (size_t)s * 3*1024;
    *(__nv_bfloat162*)(ob + c0)          = hip;   // hi
    *(__nv_bfloat162*)(ob + 1024 + c0)   = lop;   // lo
    *(__nv_bfloat162*)(ob + 2048 + c0)   = hip;   // hi
}

// ---------------- launch ----------------------------------------------------
extern "C" void kernel_launch(void* const* d_in, const int* in_sizes, int n_in,
                              void* d_out, int out_size) {
    const float* x     = (const float*)d_in[0];
    const float* freqs = (const float*)d_in[1];
    const float* wq_a  = (const float*)d_in[2];
    const float* qnw   = (const float*)d_in[3];
    const float* wq_b  = (const float*)d_in[4];
    const float* wkv   = (const float*)d_in[5];
    const float* kvnw  = (const float*)d_in[6];
    const float* wo_a  = (const float*)d_in[7];
    const float* wo_b  = (const float*)d_in[8];
    const float* sink  = (const float*)d_in[9];
    float* out = (float*)d_out;

    float *qa, *q, *kv, *o, *cb, *sb;
    __nv_bfloat16 *xs, *wqas, *qas, *wqbs, *wkvs, *os, *woas, *ors, *wobs;
    __half *qhi, *qlo, *kvhi, *kvlo;
    cudaGetSymbolAddress((void**)&qa,  g_qa);
    cudaGetSymbolAddress((void**)&q,   g_q);
    cudaGetSymbolAddress((void**)&kv,  g_kv);
    cudaGetSymbolAddress((void**)&o,   g_o);
    cudaGetSymbolAddress((void**)&cb,  g_cos);
    cudaGetSymbolAddress((void**)&sb,  g_sin);
    cudaGetSymbolAddress((void**)&xs,   g_xs);
    cudaGetSymbolAddress((void**)&wqas, g_wqas);
    cudaGetSymbolAddress((void**)&qas,  g_qas);
    cudaGetSymbolAddress((void**)&wqbs, g_wqbs);
    cudaGetSymbolAddress((void**)&wkvs, g_wkvs);
    cudaGetSymbolAddress((void**)&os,   g_os);
    cudaGetSymbolAddress((void**)&woas, g_woas);
    cudaGetSymbolAddress((void**)&ors,  g_ors);
    cudaGetSymbolAddress((void**)&wobs, g_wobs);
    cudaGetSymbolAddress((void**)&qhi,  g_qhi);
    cudaGetSymbolAddress((void**)&qlo,  g_qlo);
    cudaGetSymbolAddress((void**)&kvhi, g_kvhi);
    cudaGetSymbolAddress((void**)&kvlo, g_kvlo);

    size_t hg_smem = 128 + 2 * 32768;
    cudaFuncSetAttribute(k_hgemm, cudaFuncAttributeMaxDynamicSharedMemorySize,
                         (int)hg_smem);
    cudaFuncSetAttribute(k_attn5, cudaFuncAttributeMaxDynamicSharedMemorySize,
                         (int)ATTN5_SMEM);

    k_cossin<<<(S_*32 + 255)/256, 256>>>(freqs, cb, sb);

    // ---- splits for stage-1 GEMMs ----
    k_split<<<dim3(HID_/256, S_),   256>>>(x,    xs,   HID_, HID_, 0, 0, 0);
    k_split<<<dim3(HID_/256, QL_),  256>>>(wq_a, wqas, HID_, HID_, 0, 0, 1);
    k_split<<<dim3(HID_/256, D_),   256>>>(wkv,  wkvs, HID_, HID_, 0, 0, 1);

    // qa = x @ wq_a^T   [2048,1024], K3=6144
    k_hgemm<<<dim3(QL_/128, S_/128), 256, hg_smem>>>(xs, wqas, qa,
                                                     3*HID_, QL_, 0, 0, 0,
                                                     nullptr, 0, 0);
    // fused rmsnorm + A-split: qa -> qas
    k_rmsplit<<<S_, 256>>>(qa, qnw, qas);
    k_split<<<dim3(QL_/256, H_*D_), 256>>>(wq_b, wqbs, QL_, QL_, 0, 0, 1);
    // q = qa @ wq_b^T   [2048,4096], K3=3072
    k_hgemm<<<dim3(H_*D_/128, S_/128), 256, hg_smem>>>(qas, wqbs, q,
                                                       3*QL_, H_*D_, 0, 0, 0,
                                                       nullptr, 0, 0);
    // kv = x @ wkv^T    [2048,256], K3=6144
    k_hgemm<<<dim3(D_/128, S_/128), 256, hg_smem>>>(xs, wkvs, kv,
                                                    3*HID_, D_, 0, 0, 0,
                                                    nullptr, 0, 0);
    // norm + rope + fp16 hi/lo pre-split for attention
    k_kvproc2<<<S_, 256>>>(kv, kvnw, cb, sb, kvhi, kvlo);
    k_qproc2<<<S_*H_, 256>>>(q, cb, sb, qhi, qlo);

    // attention: 32 q-tiles of 64 rows x 16 heads, fp16 4-pass
    k_attn5<<<dim3(32*16), 256, ATTN5_SMEM>>>(qhi, qlo, kvhi, kvlo, sink, o);

    // fused conj-rope + grouped split of o
    k_osplit<<<dim3(2, S_, G_), 256>>>(o, cb, sb, os);
    k_split<<<dim3(1024/256, G_*OR_), 256>>>(wo_a, woas, 1024, 1024, 0, 0, 1);
    // o_r[g] = o_g @ wo_a[g]^T, epilogue writes ors hi/lo/hi directly
    k_hgemm<<<dim3(OR_/128, S_/128, G_), 256, hg_smem>>>(
        os, woas, (float*)out /*unused*/, 3*1024, 0,
        (size_t)S_*3*1024, (size_t)OR_*3*1024, 0,
        ors, G_*OR_, OR_);

    k_split<<<dim3((G_*OR_)/256, HID_), 256>>>(wo_b, wobs, G_*OR_, G_*OR_, 0, 0, 1);
    // out = o_r @ wo_b^T  [2048,2048], K3=6144
    k_hgemm<<<dim3(HID_/128, S_/128), 256, hg_smem>>>(ors, wobs, out,
                                                      3*(G_*OR_), HID_, 0, 0, 0,
                                                      nullptr, 0, 0);
}

// round 17
// speedup vs baseline: 12.0351x; 1.3096x over previous
#include <cuda_runtime.h>
#include <cuda_bf16.h>
#include <cuda_fp16.h>
#include <math.h>
#include <stdint.h>

#define S_    2048
#define HID_  2048
#define H_    16
#define D_    256
#define R_    64
#define NOPE_ 192
#define QL_   1024
#define OR_   512
#define G_    4
#define EPS_  1e-6f
#define SCALE_ 0.0625f   // 256^-0.5

// ---------------- scratch (static device arrays; no allocs allowed) -------
__device__ float g_qa [S_*QL_];
__device__ float g_q  [S_*H_*D_];
__device__ float g_kv [S_*D_];
__device__ float g_o  [S_*H_*D_];
__device__ float g_cos[S_*(R_/2)];
__device__ float g_sin[S_*(R_/2)];
// fp16 2-term split operands (K doubled) for GEMMs: A=[hi,lo], B=[hi,hi]
__device__ __half g_xs   [S_*2*HID_];
__device__ __half g_wqas [QL_*2*HID_];
__device__ __half g_qas  [S_*2*QL_];
__device__ __half g_wqbs [H_*D_*2*QL_];
__device__ __half g_wkvs [D_*2*HID_];
__device__ __half g_os   [G_*S_*2*1024];
__device__ __half g_woas [G_*OR_*2*1024];
__device__ __half g_ors  [S_*2*(G_*OR_)];
__device__ __half g_wobs [HID_*2*(G_*OR_)];
// attention fp16 hi/lo operands (pre-split once)
__device__ __half g_qhi [S_*H_*D_];
__device__ __half g_qlo [S_*H_*D_];
__device__ __half g_kvhi[S_*D_];
__device__ __half g_kvlo[S_*D_];

// ---------------- small PTX helpers ----------------------------------------
__device__ __forceinline__ uint32_t smem_u32(const void* p) {
    uint32_t a;
    asm("{ .reg .u64 t; cvta.to.shared.u64 t, %1; cvt.u32.u64 %0, t; }"
        : "=r"(a) : "l"(p));
    return a;
}
__device__ __forceinline__ void cp_async16(uint32_t saddr, const void* gaddr) {
    asm volatile("cp.async.cg.shared.global [%0], [%1], 16;"
                 :: "r"(saddr), "l"(gaddr));
}
#define CP_COMMIT() asm volatile("cp.async.commit_group;" ::: "memory")
#define CP_WAIT1()  asm volatile("cp.async.wait_group 1;" ::: "memory")
#define CP_WAIT0()  asm volatile("cp.async.wait_group 0;" ::: "memory")

__device__ __forceinline__ void ldsm4(uint32_t& r0, uint32_t& r1,
                                      uint32_t& r2, uint32_t& r3, uint32_t a) {
    asm volatile("ldmatrix.sync.aligned.m8n8.x4.shared.b16 {%0,%1,%2,%3}, [%4];"
                 : "=r"(r0), "=r"(r1), "=r"(r2), "=r"(r3) : "r"(a));
}
__device__ __forceinline__ void ldsm4t(uint32_t& r0, uint32_t& r1,
                                       uint32_t& r2, uint32_t& r3, uint32_t a) {
    asm volatile("ldmatrix.sync.aligned.m8n8.x4.trans.shared.b16 {%0,%1,%2,%3}, [%4];"
                 : "=r"(r0), "=r"(r1), "=r"(r2), "=r"(r3) : "r"(a));
}
__device__ __forceinline__ void mma_f16(float* d, const uint32_t* a,
                                        const uint32_t* b) {
    asm volatile("mma.sync.aligned.m16n8k16.row.col.f32.f16.f16.f32 "
                 "{%0,%1,%2,%3}, {%4,%5,%6,%7}, {%8,%9}, {%0,%1,%2,%3};"
                 : "+f"(d[0]), "+f"(d[1]), "+f"(d[2]), "+f"(d[3])
                 : "r"(a[0]), "r"(a[1]), "r"(a[2]), "r"(a[3]),
                   "r"(b[0]), "r"(b[1]));
}

// ---------------- cos/sin precompute --------------------------------------
__global__ void k_cossin(const float* __restrict__ f,
                         float* __restrict__ c, float* __restrict__ s) {
    int i = blockIdx.x * 256 + threadIdx.x;
    if (i < S_ * (R_/2)) { c[i] = cosf(f[i]); s[i] = sinf(f[i]); }
}

// ---------------- fp16 2-term split ----------------------------------------
// mode 0 (A operand): out row = [hi(K), lo(K)]
// mode 1 (B operand): out row = [hi(K), hi(K)]
__global__ void k_split(const float* __restrict__ in, __half* __restrict__ out,
                        int K, int in_ld, size_t in_goff, size_t out_gstride, int mode) {
    const float* ip = in + in_goff * blockIdx.z;
    __half* op = out + out_gstride * blockIdx.z;
    int k = blockIdx.x * 256 + threadIdx.x;
    int row = blockIdx.y;
    float v = ip[(size_t)row * in_ld + k];
    __half hi = __float2half(v);
    size_t ob = (size_t)row * 2 * K;
    op[ob + k] = hi;
    op[ob + K + k] = (mode == 0) ? __float2half(v - __half2float(hi)) : hi;
}

// ---------------- fused rmsnorm + A-split (row len 1024) -------------------
__global__ void k_rmsplit(const float* __restrict__ x, const float* __restrict__ w,
                          __half* __restrict__ out) {
    int row = blockIdx.x, t = threadIdx.x;
    const float* xp = x + (size_t)row * QL_;
    float ss = 0.f;
    float v4[4];
    *(float4*)v4 = *(const float4*)(xp + t*4);
#pragma unroll
    for (int i = 0; i < 4; i++) ss += v4[i]*v4[i];
#pragma unroll
    for (int o = 16; o; o >>= 1) ss += __shfl_xor_sync(0xffffffffu, ss, o);
    __shared__ float wr[8];
    __shared__ float rinv;
    if ((t & 31) == 0) wr[t >> 5] = ss;
    __syncthreads();
    if (t == 0) {
        float tot = 0.f;
        for (int i = 0; i < 8; i++) tot += wr[i];
        rinv = rsqrtf(tot / (float)QL_ + EPS_);
    }
    __syncthreads();
    float r = rinv;
    __half* op = out + (size_t)row * 2 * QL_;
#pragma unroll
    for (int i = 0; i < 4; i++) {
        int k = t*4 + i;
        float f = v4[i] * r * w[k];
        __half hi = __float2half(f);
        op[k] = hi;
        op[QL_ + k] = __float2half(f - __half2float(hi));
    }
}

// ---------------- HMMA fp16 GEMM: C[M,N] = A[M,K2] @ B[N,K2]^T -------------
// A=[hi,lo], B=[hi,hi] fp16 2-term. If Cs != nullptr: epilogue writes the
// fp16 [hi,lo] A-operand layout instead of fp32 C.
__global__ void __launch_bounds__(256)
k_hgemm(const __half* __restrict__ A, const __half* __restrict__ B,
        float* __restrict__ C, int K2, int ldc,
        size_t sA, size_t sB, size_t sC,
        __half* __restrict__ Cs, int splitK, int csoff) {
    extern __shared__ char smem_raw[];
    uint32_t sb_raw = smem_u32(smem_raw);
    uint32_t sb = (sb_raw + 127) & ~127u;

    A += sA * blockIdx.z; B += sB * blockIdx.z; C += sC * blockIdx.z;
    const int bn = blockIdx.x * 128, bm = blockIdx.y * 128;
    int t = threadIdx.x, lane = t & 31, wid = t >> 5;
    int wm = wid & 3, wn = wid >> 2;

    int r = t >> 1, hh = t & 1;
    const char* Ag = (const char*)(A + (size_t)(bm + r) * K2) + hh * 64;
    const char* Bg = (const char*)(B + (size_t)(bn + r) * K2) + hh * 64;
    uint32_t soff[4];
#pragma unroll
    for (int i = 0; i < 4; i++) {
        uint32_t off = (uint32_t)(r * 128 + hh * 64 + i * 16);
        soff[i] = off ^ ((off >> 3) & 0x70);
    }

#define LOADC(c, buf) do {                                                    \
        const char* ag = Ag + (size_t)(c) * 128;                              \
        const char* bg = Bg + (size_t)(c) * 128;                              \
        uint32_t ab = sb + (buf) * 32768;                                     \
        uint32_t bb = ab + 16384;                                             \
        cp_async16(ab + soff[0], ag);       cp_async16(ab + soff[1], ag + 16);\
        cp_async16(ab + soff[2], ag + 32);  cp_async16(ab + soff[3], ag + 48);\
        cp_async16(bb + soff[0], bg);       cp_async16(bb + soff[1], bg + 16);\
        cp_async16(bb + soff[2], bg + 32);  cp_async16(bb + soff[3], bg + 48);\
    } while (0)

    float d[2][8][4];
#pragma unroll
    for (int i = 0; i < 2; i++)
#pragma unroll
        for (int j = 0; j < 8; j++)
#pragma unroll
            for (int k = 0; k < 4; k++) d[i][j][k] = 0.f;

    const int nch = K2 >> 6;
    LOADC(0, 0);
    CP_COMMIT();

    uint32_t a_off[2];
#pragma unroll
    for (int i = 0; i < 2; i++) {
        uint32_t off = (uint32_t)((wm*32 + i*16 + (lane & 15)) * 128 + (lane >> 4) * 16);
        a_off[i] = off ^ ((off >> 3) & 0x70);
    }
    uint32_t b_off[4];
#pragma unroll
    for (int jp = 0; jp < 4; jp++) {
        uint32_t off = (uint32_t)((wn*64 + jp*16 + ((lane >> 4) << 3) + (lane & 7)) * 128
                                  + ((lane >> 3) & 1) * 16);
        b_off[jp] = off ^ ((off >> 3) & 0x70);
    }

    for (int c = 0; c < nch; ++c) {
        int buf = c & 1;
        if (c + 1 < nch) { LOADC(c + 1, buf ^ 1); CP_COMMIT(); CP_WAIT1(); }
        else             { CP_WAIT0(); }
        __syncthreads();

        uint32_t abase = sb + buf * 32768;
        uint32_t bbase = abase + 16384;
#pragma unroll
        for (int ks = 0; ks < 4; ++ks) {
            uint32_t kb = ks * 32;
            uint32_t a_f[2][4];
#pragma unroll
            for (int i = 0; i < 2; i++)
                ldsm4(a_f[i][0], a_f[i][1], a_f[i][2], a_f[i][3],
                      abase + (a_off[i] ^ kb));
            uint32_t b_f[8][2];
#pragma unroll
            for (int jp = 0; jp < 4; jp++) {
                uint32_t r0, r1, r2, r3;
                ldsm4(r0, r1, r2, r3, bbase + (b_off[jp] ^ kb));
                b_f[jp*2][0] = r0;   b_f[jp*2][1] = r1;
                b_f[jp*2+1][0] = r2; b_f[jp*2+1][1] = r3;
            }
#pragma unroll
            for (int i = 0; i < 2; i++)
#pragma unroll
                for (int j = 0; j < 8; j++)
                    mma_f16(d[i][j], a_f[i], b_f[j]);
        }
        __syncthreads();
    }

    if (Cs == nullptr) {
#pragma unroll
        for (int i = 0; i < 2; i++) {
            int row0 = bm + wm*32 + i*16 + (lane >> 2);
#pragma unroll
            for (int j = 0; j < 8; j++) {
                int col = bn + wn*64 + j*8 + (lane & 3)*2;
                *(float2*)&C[(size_t)row0 * ldc + col] = make_float2(d[i][j][0], d[i][j][1]);
                *(float2*)&C[(size_t)(row0 + 8) * ldc + col] = make_float2(d[i][j][2], d[i][j][3]);
            }
        }
    } else {
        const size_t ld2 = 2 * (size_t)splitK;
        int csbase = blockIdx.z * csoff;
#pragma unroll
        for (int i = 0; i < 2; i++) {
            int row0 = bm + wm*32 + i*16 + (lane >> 2);
#pragma unroll
            for (int j = 0; j < 8; j++) {
                int colg = csbase + bn + wn*64 + j*8 + (lane & 3)*2;
#pragma unroll
                for (int hf = 0; hf < 2; hf++) {
                    float v0 = d[i][j][hf*2], v1 = d[i][j][hf*2+1];
                    __half2 hp = __floats2half2_rn(v0, v1);
                    __half2 lp;
                    lp.x = __float2half(v0 - __half2float(hp.x));
                    lp.y = __float2half(v1 - __half2float(hp.y));
                    __half* p = Cs + (size_t)(row0 + hf*8) * ld2 + colg;
                    *(__half2*)p            = hp;
                    *(__half2*)(p + splitK) = lp;
                }
            }
        }
    }
#undef LOADC
}

// ---------------- q per-head norm + RoPE + fp16 hi/lo split ----------------
__global__ void k_qproc2(const float* __restrict__ q,
                         const float* __restrict__ cb, const float* __restrict__ sbn,
                         __half* __restrict__ qhi, __half* __restrict__ qlo) {
    int s = blockIdx.x >> 4;
    int h = blockIdx.x & 15;
    int t = threadIdx.x;   // 256
    const float* qp = q + ((size_t)s * H_ + h) * D_;
    float v = qp[t];
    float ss = v * v;
#pragma unroll
    for (int o = 16; o; o >>= 1) ss += __shfl_xor_sync(0xffffffffu, ss, o);
    __shared__ float wr[8];
    __shared__ float rinv;
    __shared__ float buf[D_];
    if ((t & 31) == 0) wr[t >> 5] = ss;
    __syncthreads();
    if (t == 0) {
        float tot = 0.f;
        for (int i = 0; i < 8; i++) tot += wr[i];
        rinv = rsqrtf(tot / 256.f + EPS_);
    }
    __syncthreads();
    buf[t] = v * rinv;
    __syncthreads();
    if (t < 32) {
        float c = cb[s*32 + t], sn = sbn[s*32 + t];
        float x1 = buf[NOPE_ + 2*t], x2 = buf[NOPE_ + 2*t + 1];
        buf[NOPE_ + 2*t]     = x1 * c - x2 * sn;
        buf[NOPE_ + 2*t + 1] = x1 * sn + x2 * c;
    }
    __syncthreads();
    float f = buf[t];
    __half hi = __float2half(f);
    size_t idx = ((size_t)s * H_ + h) * D_ + t;
    qhi[idx] = hi;
    qlo[idx] = __float2half(f - __half2float(hi));
}

// ---------------- kv rmsnorm + RoPE + fp16 hi/lo split ---------------------
__global__ void k_kvproc2(const float* __restrict__ kv, const float* __restrict__ w,
                          const float* __restrict__ cb, const float* __restrict__ sbn,
                          __half* __restrict__ kvhi, __half* __restrict__ kvlo) {
    int s = blockIdx.x, t = threadIdx.x;   // 256
    const float* p = kv + (size_t)s * D_;
    float v = p[t];
    float ss = v * v;
#pragma unroll
    for (int o = 16; o; o >>= 1) ss += __shfl_xor_sync(0xffffffffu, ss, o);
    __shared__ float wr[8];
    __shared__ float rinv;
    __shared__ float buf[D_];
    if ((t & 31) == 0) wr[t >> 5] = ss;
    __syncthreads();
    if (t == 0) {
        float tot = 0.f;
        for (int i = 0; i < 8; i++) tot += wr[i];
        rinv = rsqrtf(tot / 256.f + EPS_);
    }
    __syncthreads();
    buf[t] = v * rinv * w[t];
    __syncthreads();
    if (t < 32) {
        float c = cb[s*32 + t], sn = sbn[s*32 + t];
        float x1 = buf[NOPE_ + 2*t], x2 = buf[NOPE_ + 2*t + 1];
        buf[NOPE_ + 2*t]     = x1 * c - x2 * sn;
        buf[NOPE_ + 2*t + 1] = x1 * sn + x2 * c;
    }
    __syncthreads();
    float f = buf[t];
    __half hi = __float2half(f);
    size_t idx = (size_t)s * D_ + t;
    kvhi[idx] = hi;
    kvlo[idx] = __float2half(f - __half2float(hi));
}

// ================ HMMA fp16 flash attention v5 (causal, sink) ==============
// 4 MMA passes total: scores = (Qhi+Qlo)*Khi (2), PV = P*(Vhi+Vlo) (2).
#define AQHI 0u
#define AQLO 32768u
#define AKV0 65536u          // buf b at AKV0 + b*65536; hi +0, lo +32768
#define APS  196608u
#define APHI 212992u
#define ACS  221184u
#define AOS  221440u
#define ATTN5_SMEM (221696u + 512u)

__global__ void __launch_bounds__(256)
k_attn5(const __half* __restrict__ qhi, const __half* __restrict__ qlo,
        const __half* __restrict__ kvhi, const __half* __restrict__ kvlo,
        const float* __restrict__ sink, float* __restrict__ o) {
    extern __shared__ char smraw[];
    uint32_t sb_raw = smem_u32(smraw);
    uint32_t sb = (sb_raw + 511) & ~511u;
    char* sm = smraw + (sb - sb_raw);

    int bid = blockIdx.x;
    int qb = 31 - (bid >> 4);     // longest first
    int h  = bid & 15;
    int t = threadIdx.x, lane = t & 31, wid = t >> 5;
    int wm = wid & 3, wn = wid >> 2;

    uint32_t dsw[8];
    int      ksrc[8];
#pragma unroll
    for (int i = 0; i < 8; i++) {
        int idx = t + i * 256;
        int rr = idx >> 5, uu = idx & 31;
        uint32_t off = (uint32_t)(rr*512 + uu*16);
        dsw[i]  = off ^ ((uint32_t)(rr & 7) << 4);
        ksrc[i] = rr*256 + uu*8;
    }

#define LOADKV(kt, buf) do {                                                  \
        const __half* ph = kvhi + (size_t)(kt)*64*256;                        \
        const __half* pl = kvlo + (size_t)(kt)*64*256;                        \
        uint32_t base = sb + AKV0 + (uint32_t)(buf)*65536u;                   \
        _Pragma("unroll")                                                     \
        for (int i = 0; i < 8; i++) {                                         \
            cp_async16(base + dsw[i],          ph + ksrc[i]);                 \
            cp_async16(base + 32768u + dsw[i], pl + ksrc[i]);                 \
        }                                                                     \
    } while (0)

#pragma unroll
    for (int i = 0; i < 8; i++) {
        int idx = t + i * 256;
        int rr = idx >> 5, uu = idx & 31;
        size_t qsrc = ((size_t)(qb*64 + rr) * H_ + h) * D_ + uu*8;
        cp_async16(sb + AQHI + dsw[i], qhi + qsrc);
        cp_async16(sb + AQLO + dsw[i], qlo + qsrc);
    }
    LOADKV(0, 0);
    CP_COMMIT();

    uint32_t a_pre;
    { int row = wm*16 + (lane & 15);
      a_pre = (uint32_t)(row*512) ^ ((uint32_t)(lane >> 4) << 4)
            ^ ((uint32_t)(lane & 7) << 4); }
    uint32_t b_pre[2];
#pragma unroll
    for (int jp = 0; jp < 2; jp++) {
        int row = wn*32 + jp*16 + ((lane >> 4) << 3) + (lane & 7);
        b_pre[jp] = (uint32_t)(row*512) ^ (((uint32_t)(lane >> 3) & 1u) << 4)
                  ^ ((uint32_t)(lane & 7) << 4);
    }
    uint32_t pa_pre;
    { int row = wm*16 + (lane & 15);
      pa_pre = (uint32_t)(row*128) ^ ((uint32_t)(lane >> 4) << 4)
             ^ ((uint32_t)(lane & 7) << 4); }
    uint32_t pv_pre;
    { int mi = lane >> 3;
      pv_pre = (uint32_t)((((mi & 1)*8 + (lane & 7)) * 512) + wn*256)
             ^ ((uint32_t)(mi >> 1) << 4) ^ ((uint32_t)(lane & 7) << 4); }

    float cpv[16][4];
#pragma unroll
    for (int j = 0; j < 16; j++)
#pragma unroll
        for (int k = 0; k < 4; k++) cpv[j][k] = 0.f;

    float m_ = -1e30f, l_ = 0.f;
    int srow = t >> 2, sc = t & 3;
    int rm_lo = wm*16 + (lane >> 2);

    CP_WAIT0();
    __syncthreads();

    for (int kt = 0; kt <= qb; ++kt) {
        int buf = kt & 1;
        if (kt < qb) { LOADKV(kt + 1, buf ^ 1); CP_COMMIT(); }
        uint32_t KHI = AKV0 + (uint32_t)buf * 65536u;
        uint32_t KLO = KHI + 32768u;

        // ---- scores: (Qhi + Qlo) * Khi, shared B fragments ----
        float c[4][4];
#pragma unroll
        for (int j = 0; j < 4; j++)
#pragma unroll
            for (int k = 0; k < 4; k++) c[j][k] = 0.f;
#pragma unroll
        for (int ks = 0; ks < 16; ++ks) {
            uint32_t ahi[4], alo[4];
            ldsm4(ahi[0], ahi[1], ahi[2], ahi[3],
                  sb + AQHI + (a_pre ^ ((uint32_t)ks << 5)));
            ldsm4(alo[0], alo[1], alo[2], alo[3],
                  sb + AQLO + (a_pre ^ ((uint32_t)ks << 5)));
#pragma unroll
            for (int jp = 0; jp < 2; jp++) {
                uint32_t r0, r1, r2, r3;
                ldsm4(r0, r1, r2, r3,
                      sb + KHI + (b_pre[jp] ^ ((uint32_t)ks << 5)));
                uint32_t bA[2] = {r0, r1}, bB[2] = {r2, r3};
                mma_f16(c[jp*2],   ahi, bA);
                mma_f16(c[jp*2+1], ahi, bB);
                mma_f16(c[jp*2],   alo, bA);
                mma_f16(c[jp*2+1], alo, bB);
            }
        }

        // ---- score epilogue: scale + causal mask -> PS ----
#pragma unroll
        for (int n8 = 0; n8 < 4; n8++) {
            int col  = wn*32 + n8*8 + (lane & 3)*2;
            int gcol = kt*64 + col;
#pragma unroll
            for (int hf = 0; hf < 2; hf++) {
                int row  = wm*16 + (lane >> 2) + hf*8;
                int grow = qb*64 + row;
                float v0 = c[n8][hf*2]   * SCALE_;
                float v1 = c[n8][hf*2+1] * SCALE_;
                if (gcol     > grow) v0 = -1e30f;
                if (gcol + 1 > grow) v1 = -1e30f;
                uint32_t off = (uint32_t)(row*256 + col*4)
                             ^ ((uint32_t)(row & 7) << 5);
                *(float2*)(sm + APS + off) = make_float2(v0, v1);
            }
        }
        __syncthreads();

        // ---- online softmax: 4 threads per row, 16 cols each ----
        float sv[16];
#pragma unroll
        for (int jj = 0; jj < 4; jj++) {
            uint32_t off = (uint32_t)(srow*256 + sc*64 + jj*16)
                         ^ ((uint32_t)(srow & 7) << 5);
            *(float4*)&sv[jj*4] = *(const float4*)(sm + APS + off);
        }
        float tmax = sv[0];
#pragma unroll
        for (int j = 1; j < 16; j++) tmax = fmaxf(tmax, sv[j]);
        tmax = fmaxf(tmax, __shfl_xor_sync(0xffffffffu, tmax, 1));
        tmax = fmaxf(tmax, __shfl_xor_sync(0xffffffffu, tmax, 2));
        float nm = fmaxf(m_, tmax);
        float cs = __expf(m_ - nm);
        float ps = 0.f;
        uint32_t hw[8];
#pragma unroll
        for (int j = 0; j < 8; j++) {
            float p0 = __expf(sv[2*j]   - nm);
            float p1 = __expf(sv[2*j+1] - nm);
            ps += p0 + p1;
            __half2 hh = __floats2half2_rn(p0, p1);
            hw[j] = *(uint32_t*)&hh;
        }
        ps += __shfl_xor_sync(0xffffffffu, ps, 1);
        ps += __shfl_xor_sync(0xffffffffu, ps, 2);
        l_ = l_ * cs + ps;
        m_ = nm;
        uint32_t po0 = (uint32_t)(srow*128) ^ ((uint32_t)sc << 5)
                     ^ ((uint32_t)(srow & 7) << 4);
        uint32_t po1 = po0 ^ 16u;
        *(uint4*)(sm + APHI + po0) = make_uint4(hw[0], hw[1], hw[2], hw[3]);
        *(uint4*)(sm + APHI + po1) = make_uint4(hw[4], hw[5], hw[6], hw[7]);
        if (sc == 0) *(float*)(sm + ACS + srow*4) = cs;
        __syncthreads();

        // ---- rescale accumulators + PV: P * (Vhi + Vlo), shared A frags ----
        float cs_lo = *(const float*)(sm + ACS + rm_lo*4);
        float cs_hi = *(const float*)(sm + ACS + (rm_lo + 8)*4);
#pragma unroll
        for (int jn = 0; jn < 16; jn++) {
            cpv[jn][0] *= cs_lo; cpv[jn][1] *= cs_lo;
            cpv[jn][2] *= cs_hi; cpv[jn][3] *= cs_hi;
        }
#pragma unroll
        for (int ks = 0; ks < 4; ++ks) {
            uint32_t a4[4];
            ldsm4(a4[0], a4[1], a4[2], a4[3],
                  sb + APHI + (pa_pre ^ ((uint32_t)ks << 5)));
#pragma unroll
            for (int jn = 0; jn < 16; jn += 2) {
                uint32_t r0, r1, r2, r3;
                ldsm4t(r0, r1, r2, r3,
                       sb + KHI + (uint32_t)(ks*8192) + (pv_pre ^ ((uint32_t)jn << 4)));
                uint32_t bA[2] = {r0, r1}, bB[2] = {r2, r3};
                mma_f16(cpv[jn],   a4, bA);
                mma_f16(cpv[jn+1], a4, bB);
                ldsm4t(r0, r1, r2, r3,
                       sb + KLO + (uint32_t)(ks*8192) + (pv_pre ^ ((uint32_t)jn << 4)));
                uint32_t cA[2] = {r0, r1}, cB[2] = {r2, r3};
                mma_f16(cpv[jn],   a4, cA);
                mma_f16(cpv[jn+1], a4, cB);
            }
        }

        if (kt < qb) CP_WAIT0();
        __syncthreads();
    }

    // ---- fold sink, output scale ----
    if (sc == 0) {
        float sk = sink[h];
        float mf = fmaxf(m_, sk);
        float cf = __expf(m_ - mf);
        float den = l_ * cf + __expf(sk - mf);
        *(float*)(sm + AOS + srow*4) = cf / den;
    }
    __syncthreads();
    float os_lo = *(const float*)(sm + AOS + rm_lo*4);
    float os_hi = *(const float*)(sm + AOS + (rm_lo + 8)*4);
    int s_lo = qb*64 + rm_lo;
#pragma unroll
    for (int jn = 0; jn < 16; jn++) {
        int col = wn*128 + jn*8 + (lane & 3)*2;
        *(float2*)&o[(((size_t)s_lo) * H_ + h) * D_ + col] =
            make_float2(cpv[jn][0]*os_lo, cpv[jn][1]*os_lo);
        *(float2*)&o[(((size_t)(s_lo + 8)) * H_ + h) * D_ + col] =
            make_float2(cpv[jn][2]*os_hi, cpv[jn][3]*os_hi);
    }
#undef LOADKV
}

// ---------------- fused conj-RoPE + grouped fp16 hi/lo split of o ----------
__global__ void k_osplit(const float* __restrict__ o,
                         const float* __restrict__ cb, const float* __restrict__ sbn,
                         __half* __restrict__ os) {
    int t = threadIdx.x;
    int s = blockIdx.y;
    int g = blockIdx.z;
    int p = blockIdx.x * 256 + t;        // pair index 0..511
    int c0 = p * 2;                      // group col (even)
    int hpg = c0 >> 8;
    int d0  = c0 & 255;
    int hh  = g * (H_/G_) + hpg;
    const float* src = &o[((size_t)s * H_ + hh) * D_ + d0];
    float v0 = src[0], v1 = src[1];
    if (d0 >= NOPE_) {
        int i = (d0 - NOPE_) >> 1;
        float c = cb[s*32 + i], sn = sbn[s*32 + i];
        float n0 =  v0 * c + v1 * sn;    // conj rotation
        float n1 = -v0 * sn + v1 * c;
        v0 = n0; v1 = n1;
    }
    __half2 hip = __floats2half2_rn(v0, v1);
    __half2 lop;
    lop.x = __float2half(v0 - __half2float(hip.x));
    lop.y = __float2half(v1 - __half2float(hip.y));
    __half* ob = os + (size_t)g * (S_*2*1024) + (size_t)s * 2*1024;
    *(__half2*)(ob + c0)        = hip;   // hi
    *(__half2*)(ob + 1024 + c0) = lop;   // lo
}

// ---------------- launch ----------------------------------------------------
extern "C" void kernel_launch(void* const* d_in, const int* in_sizes, int n_in,
                              void* d_out, int out_size) {
    const float* x     = (const float*)d_in[0];
    const float* freqs = (const float*)d_in[1];
    const float* wq_a  = (const float*)d_in[2];
    const float* qnw   = (const float*)d_in[3];
    const float* wq_b  = (const float*)d_in[4];
    const float* wkv   = (const float*)d_in[5];
    const float* kvnw  = (const float*)d_in[6];
    const float* wo_a  = (const float*)d_in[7];
    const float* wo_b  = (const float*)d_in[8];
    const float* sink  = (const float*)d_in[9];
    float* out = (float*)d_out;

    float *qa, *q, *kv, *o, *cb, *sb;
    __half *xs, *wqas, *qas, *wqbs, *wkvs, *os, *woas, *ors, *wobs;
    __half *qhi, *qlo, *kvhi, *kvlo;
    cudaGetSymbolAddress((void**)&qa,  g_qa);
    cudaGetSymbolAddress((void**)&q,   g_q);
    cudaGetSymbolAddress((void**)&kv,  g_kv);
    cudaGetSymbolAddress((void**)&o,   g_o);
    cudaGetSymbolAddress((void**)&cb,  g_cos);
    cudaGetSymbolAddress((void**)&sb,  g_sin);
    cudaGetSymbolAddress((void**)&xs,   g_xs);
    cudaGetSymbolAddress((void**)&wqas, g_wqas);
    cudaGetSymbolAddress((void**)&qas,  g_qas);
    cudaGetSymbolAddress((void**)&wqbs, g_wqbs);
    cudaGetSymbolAddress((void**)&wkvs, g_wkvs);
    cudaGetSymbolAddress((void**)&os,   g_os);
    cudaGetSymbolAddress((void**)&woas, g_woas);
    cudaGetSymbolAddress((void**)&ors,  g_ors);
    cudaGetSymbolAddress((void**)&wobs, g_wobs);
    cudaGetSymbolAddress((void**)&qhi,  g_qhi);
    cudaGetSymbolAddress((void**)&qlo,  g_qlo);
    cudaGetSymbolAddress((void**)&kvhi, g_kvhi);
    cudaGetSymbolAddress((void**)&kvlo, g_kvlo);

    size_t hg_smem = 128 + 2 * 32768;
    cudaFuncSetAttribute(k_hgemm, cudaFuncAttributeMaxDynamicSharedMemorySize,
                         (int)hg_smem);
    cudaFuncSetAttribute(k_attn5, cudaFuncAttributeMaxDynamicSharedMemorySize,
                         (int)ATTN5_SMEM);

    k_cossin<<<(S_*32 + 255)/256, 256>>>(freqs, cb, sb);

    // ---- splits for stage-1 GEMMs (fp16 2-term, K doubled) ----
    k_split<<<dim3(HID_/256, S_),   256>>>(x,    xs,   HID_, HID_, 0, 0, 0);
    k_split<<<dim3(HID_/256, QL_),  256>>>(wq_a, wqas, HID_, HID_, 0, 0, 1);
    k_split<<<dim3(HID_/256, D_),   256>>>(wkv,  wkvs, HID_, HID_, 0, 0, 1);

    // qa = x @ wq_a^T   [2048,1024], K2=4096
    k_hgemm<<<dim3(QL_/128, S_/128), 256, hg_smem>>>(xs, wqas, qa,
                                                     2*HID_, QL_, 0, 0, 0,
                                                     nullptr, 0, 0);
    // fused rmsnorm + A-split: qa -> qas
    k_rmsplit<<<S_, 256>>>(qa, qnw, qas);
    k_split<<<dim3(QL_/256, H_*D_), 256>>>(wq_b, wqbs, QL_, QL_, 0, 0, 1);
    // q = qa @ wq_b^T   [2048,4096], K2=2048
    k_hgemm<<<dim3(H_*D_/128, S_/128), 256, hg_smem>>>(qas, wqbs, q,
                                                       2*QL_, H_*D_, 0, 0, 0,
                                                       nullptr, 0, 0);
    // kv = x @ wkv^T    [2048,256], K2=4096
    k_hgemm<<<dim3(D_/128, S_/128), 256, hg_smem>>>(xs, wkvs, kv,
                                                    2*HID_, D_, 0, 0, 0,
                                                    nullptr, 0, 0);
    // norm + rope + fp16 hi/lo pre-split for attention
    k_kvproc2<<<S_, 256>>>(kv, kvnw, cb, sb, kvhi, kvlo);
    k_qproc2<<<S_*H_, 256>>>(q, cb, sb, qhi, qlo);

    // attention: 32 q-tiles of 64 rows x 16 heads, fp16 4-pass
    k_attn5<<<dim3(32*16), 256, ATTN5_SMEM>>>(qhi, qlo, kvhi, kvlo, sink, o);

    // fused conj-rope + grouped split of o
    k_osplit<<<dim3(2, S_, G_), 256>>>(o, cb, sb, os);
    k_split<<<dim3(1024/256, G_*OR_), 256>>>(wo_a, woas, 1024, 1024, 0, 0, 1);
    // o_r[g] = o_g @ wo_a[g]^T, epilogue writes ors [hi,lo] directly
    k_hgemm<<<dim3(OR_/128, S_/128, G_), 256, hg_smem>>>(
        os, woas, (float*)out /*unused*/, 2*1024, 0,
        (size_t)S_*2*1024, (size_t)OR_*2*1024, 0,
        ors, G_*OR_, OR_);

    k_split<<<dim3((G_*OR_)/256, HID_), 256>>>(wo_b, wobs, G_*OR_, G_*OR_, 0, 0, 1);
    // out = o_r @ wo_b^T  [2048,2048], K2=4096
    k_hgemm<<<dim3(HID_/128, S_/128), 256, hg_smem>>>(ors, wobs, out,
                                                      2*(G_*OR_), HID_, 0, 0, 0,
                                                      nullptr, 0, 0);
}